// round 1
// baseline (speedup 1.0000x reference)
#include <cuda_runtime.h>
#include <math.h>
#include <stdint.h>

#define BATCH 8
#define DIMC  512
#define HW    4096
#define GH    64     // BATCH*HEADS
#define DH    64

// ---------------- scratch (device globals; allocation-free) ----------------
__device__ float g_ctxn[BATCH * DIMC * HW];          // normalized context
__device__ float g_qsn [BATCH * DIMC * HW];          // normalized query_source
__device__ float g_q   [BATCH * DIMC * HW];          // q proj (== folded (64,64,4096))
__device__ float g_kv  [BATCH * 2 * DIMC * HW];      // kv proj
__device__ float g_ao  [BATCH * DIMC * HW];          // attention output
__device__ float g_mean[BATCH * HW];
__device__ float g_rstd[BATCH * HW];
__device__ float g_qprobe[GH * DH];
__device__ float g_kh[GH * DH * 64];
__device__ float g_kw[GH * DH * 64];
__device__ int   g_idxh[GH * 8];
__device__ int   g_idxw[GH * 8];
__device__ float g_kf[GH * 64 * DH];
__device__ float g_vf[GH * 64 * DH];

// ---------------- channel layernorm: stats ----------------
__global__ __launch_bounds__(256) void stats_kernel(const float* __restrict__ in) {
    __shared__ float shs[8][32];
    __shared__ float shq[8][32];
    int tid = threadIdx.x;
    int px = tid & 31, cg = tid >> 5;
    int pos = blockIdx.x * 32 + px;           // 0..32767
    int b = pos >> 12, sp = pos & 4095;
    size_t base = (size_t)b * DIMC * HW + sp;
    float s = 0.f, q = 0.f;
    int c0 = cg * 64;
#pragma unroll 8
    for (int c = 0; c < 64; c++) {
        float x = in[base + (size_t)(c0 + c) * HW];
        s += x; q += x * x;
    }
    shs[cg][px] = s; shq[cg][px] = q;
    __syncthreads();
    if (cg == 0) {
        float ts = 0.f, tq = 0.f;
#pragma unroll
        for (int g = 0; g < 8; g++) { ts += shs[g][px]; tq += shq[g][px]; }
        float mean = ts * (1.0f / 512.0f);
        float var = tq * (1.0f / 512.0f) - mean * mean;
        g_mean[pos] = mean;
        g_rstd[pos] = rsqrtf(var + 1e-5f);
    }
}

// ---------------- channel layernorm: apply ----------------
__global__ __launch_bounds__(256) void norm_apply_kernel(const float* __restrict__ in,
                                                         const float* __restrict__ gw,
                                                         const float* __restrict__ bw,
                                                         float* __restrict__ out) {
    int i4 = blockIdx.x * 256 + threadIdx.x;   // float4 index, < 4194304
    size_t e = (size_t)i4 * 4;
    int sp = (int)(e & 4095);
    int c  = (int)((e >> 12) & 511);
    int b  = (int)(e >> 21);
    int pos = (b << 12) | sp;
    float4 x = ((const float4*)in)[i4];
    float4 m = ((const float4*)g_mean)[pos >> 2];
    float4 r = ((const float4*)g_rstd)[pos >> 2];
    float gc = gw[c], bc = bw[c];
    float4 y;
    y.x = (x.x - m.x) * r.x * gc + bc;
    y.y = (x.y - m.y) * r.y * gc + bc;
    y.z = (x.z - m.z) * r.z * gc + bc;
    y.w = (x.w - m.w) * r.w * gc + bc;
    ((float4*)out)[i4] = y;
}

// ---------------- fp32 tiled GEMM: Y[b,m,n] = sum_k W[m,k]*X[b,k,n] ----------------
// optional epilogue: Y = gamma[0]*acc + addend[b,m,n]
__global__ __launch_bounds__(256) void gemm_kernel(const float* __restrict__ W,
                                                   const float* __restrict__ X,
                                                   float* __restrict__ Y,
                                                   int M, int K, int N,
                                                   const float* __restrict__ gammap,
                                                   const float* __restrict__ addend) {
    __shared__ float As[16][128];
    __shared__ float Bs[16][128];
    int b  = blockIdx.z;
    int m0 = blockIdx.y * 128, n0 = blockIdx.x * 128;
    const float* Xb = X + (size_t)b * K * N;
    float* Yb = Y + (size_t)b * M * N;
    int tid = threadIdx.x;
    int tx = tid & 15, ty = tid >> 4;
    float acc[8][8] = {};
    int rowA = tid >> 2,  colA = (tid & 3) << 2;
    int rowB = tid >> 5,  colB = (tid & 31) << 2;

    for (int k0 = 0; k0 < K; k0 += 16) {
#pragma unroll
        for (int i = 0; i < 2; i++) {
            int r = rowA + i * 64;
            float4 a = *(const float4*)(W + (size_t)(m0 + r) * K + k0 + colA);
            As[colA + 0][r] = a.x; As[colA + 1][r] = a.y;
            As[colA + 2][r] = a.z; As[colA + 3][r] = a.w;
        }
#pragma unroll
        for (int i = 0; i < 2; i++) {
            int r = rowB + i * 8;
            *(float4*)(&Bs[r][colB]) =
                *(const float4*)(Xb + (size_t)(k0 + r) * N + n0 + colB);
        }
        __syncthreads();
#pragma unroll
        for (int kk = 0; kk < 16; kk++) {
            float4 a0 = *(const float4*)&As[kk][ty * 8];
            float4 a1 = *(const float4*)&As[kk][ty * 8 + 4];
            float4 b0 = *(const float4*)&Bs[kk][tx * 8];
            float4 b1 = *(const float4*)&Bs[kk][tx * 8 + 4];
            float ra[8] = {a0.x, a0.y, a0.z, a0.w, a1.x, a1.y, a1.z, a1.w};
            float rb[8] = {b0.x, b0.y, b0.z, b0.w, b1.x, b1.y, b1.z, b1.w};
#pragma unroll
            for (int i = 0; i < 8; i++)
#pragma unroll
                for (int j = 0; j < 8; j++)
                    acc[i][j] += ra[i] * rb[j];
        }
        __syncthreads();
    }

    float ga = gammap ? gammap[0] : 1.0f;
#pragma unroll
    for (int i = 0; i < 8; i++) {
        size_t off = (size_t)(m0 + ty * 8 + i) * N + n0 + tx * 8;
#pragma unroll
        for (int jv = 0; jv < 2; jv++) {
            float4 o;
            float* ai = &acc[i][jv * 4];
            if (addend) {
                float4 ad = *(const float4*)(addend + (size_t)b * M * N + off + jv * 4);
                o.x = ga * ai[0] + ad.x; o.y = ga * ai[1] + ad.y;
                o.z = ga * ai[2] + ad.z; o.w = ga * ai[3] + ad.w;
            } else {
                o.x = ai[0]; o.y = ai[1]; o.z = ai[2]; o.w = ai[3];
            }
            *(float4*)(Yb + off + jv * 4) = o;
        }
    }
}

// ---------------- l2 normalize over dh (64 chans) per (group, position) ----------------
__global__ __launch_bounds__(256) void l2norm_kernel(float* __restrict__ t, size_t bstride) {
    int idx = blockIdx.x * 256 + threadIdx.x;   // 262144 = GH*HW
    int g = idx >> 12, p = idx & 4095;
    size_t base = (size_t)(g >> 3) * bstride + (size_t)(g & 7) * (64 * HW) + p;
    float ss = 0.f;
#pragma unroll 8
    for (int d = 0; d < 64; d++) {
        float x = t[base + (size_t)d * HW];
        ss += x * x;
    }
    float inv = 1.0f / fmaxf(sqrtf(ss), 1e-12f);
#pragma unroll 8
    for (int d = 0; d < 64; d++) t[base + (size_t)d * HW] *= inv;
}

// ---------------- k abs-sum over width -> g_kh[bh][c][h] ----------------
__global__ __launch_bounds__(256) void kheight_kernel() {
    int idx = blockIdx.x * 256 + threadIdx.x;   // 262144
    int bh = idx >> 12, c = (idx >> 6) & 63, h = idx & 63;
    size_t base = (size_t)(bh >> 3) * (2 * DIMC * HW) + (size_t)(bh & 7) * (64 * HW)
                + (size_t)c * HW + (size_t)h * 64;
    const float4* p4 = (const float4*)(g_kv + base);
    float s = 0.f;
#pragma unroll
    for (int i = 0; i < 16; i++) {
        float4 v = p4[i];
        s += fabsf(v.x) + fabsf(v.y) + fabsf(v.z) + fabsf(v.w);
    }
    g_kh[idx] = s;
}

// ---------------- k abs-sum over height -> g_kw[bh][c][w] ----------------
__global__ __launch_bounds__(256) void kwidth_kernel() {
    int idx = blockIdx.x * 256 + threadIdx.x;   // 262144
    int bh = idx >> 12, c = (idx >> 6) & 63, w = idx & 63;
    size_t base = (size_t)(bh >> 3) * (2 * DIMC * HW) + (size_t)(bh & 7) * (64 * HW)
                + (size_t)c * HW + w;
    float s = 0.f;
#pragma unroll 8
    for (int h = 0; h < 64; h++) s += fabsf(g_kv[base + (size_t)h * 64]);
    g_kw[idx] = s;
}

// ---------------- q abs-sum over all spatial -> g_qprobe[bh][c] ----------------
__global__ __launch_bounds__(256) void qprobe_kernel() {
    int bid = blockIdx.x;          // 4096 = GH*DH
    size_t base = (size_t)bid * HW;
    const float4* p4 = (const float4*)(g_q + base);
    float s = 0.f;
    for (int i = threadIdx.x; i < 1024; i += 256) {
        float4 v = p4[i];
        s += fabsf(v.x) + fabsf(v.y) + fabsf(v.z) + fabsf(v.w);
    }
    __shared__ float sh[256];
    sh[threadIdx.x] = s;
    __syncthreads();
    for (int st = 128; st > 0; st >>= 1) {
        if (threadIdx.x < st) sh[threadIdx.x] += sh[threadIdx.x + st];
        __syncthreads();
    }
    if (threadIdx.x == 0) g_qprobe[bid] = sh[0];
}

// ---------------- scores + top-8 selection ----------------
__global__ __launch_bounds__(64) void score_topk_kernel() {
    int bh = blockIdx.x;
    int h = threadIdx.x;          // 64 threads
    __shared__ float sr[64], sc[64];
    float a = 0.f, bb = 0.f;
    for (int c = 0; c < 64; c++) {
        float qp = g_qprobe[bh * 64 + c];
        a  += qp * g_kh[bh * 4096 + c * 64 + h];
        bb += qp * g_kw[bh * 4096 + c * 64 + h];
    }
    sr[h] = a; sc[h] = bb;
    __syncthreads();
    if (h == 0) {
        for (int i = 0; i < 8; i++) {
            float best = -INFINITY; int bi = 0;
            for (int j = 0; j < 64; j++) if (sr[j] > best) { best = sr[j]; bi = j; }
            g_idxh[bh * 8 + i] = bi;
            sr[bi] = -INFINITY;
        }
    } else if (h == 1) {
        for (int i = 0; i < 8; i++) {
            float best = -INFINITY; int bi = 0;
            for (int j = 0; j < 64; j++) if (sc[j] > best) { best = sc[j]; bi = j; }
            g_idxw[bh * 8 + i] = bi;
            sc[bi] = -INFINITY;
        }
    }
}

// ---------------- gather pruned k/v -> g_kf/g_vf [bh][j][d] ----------------
__global__ __launch_bounds__(256) void gather_kernel() {
    int idx = blockIdx.x * 256 + threadIdx.x;   // 262144
    int bh = idx >> 12, j = (idx >> 6) & 63, d = idx & 63;
    int hh = g_idxh[bh * 8 + (j >> 3)];
    int ww = g_idxw[bh * 8 + (j & 7)];
    int p = hh * 64 + ww;
    size_t base = (size_t)(bh >> 3) * (2 * DIMC * HW) + (size_t)(bh & 7) * (64 * HW);
    g_kf[idx] = g_kv[base + (size_t)d * HW + p];
    g_vf[idx] = g_kv[base + (size_t)DIMC * HW + (size_t)d * HW + p];
}

// ---------------- attention over 64 pruned keys ----------------
__global__ __launch_bounds__(256, 1) void attn_kernel() {
    __shared__ float4 ks4[1024];
    __shared__ float4 vs4[1024];
    int bh = blockIdx.y;
    int p = blockIdx.x * 256 + threadIdx.x;
    const float4* kf4 = (const float4*)g_kf;
    const float4* vf4 = (const float4*)g_vf;
    for (int t = threadIdx.x; t < 1024; t += 256) {
        ks4[t] = kf4[bh * 1024 + t];
        vs4[t] = vf4[bh * 1024 + t];
    }
    __syncthreads();

    float qv[64];
    size_t qbase = (size_t)bh * 64 * HW + p;
#pragma unroll
    for (int d = 0; d < 64; d++) qv[d] = g_q[qbase + (size_t)d * HW];

    float s[64];
#pragma unroll
    for (int j = 0; j < 64; j++) {
        float acc = 0.f;
#pragma unroll
        for (int dt = 0; dt < 16; dt++) {
            float4 kk = ks4[j * 16 + dt];
            acc += qv[dt * 4 + 0] * kk.x + qv[dt * 4 + 1] * kk.y
                 + qv[dt * 4 + 2] * kk.z + qv[dt * 4 + 3] * kk.w;
        }
        s[j] = acc;
    }
    float m = -INFINITY;
#pragma unroll
    for (int j = 0; j < 64; j++) m = fmaxf(m, s[j]);
    float sum = 0.f;
#pragma unroll
    for (int j = 0; j < 64; j++) { s[j] = expf(s[j] - m); sum += s[j]; }
    float inv = 1.0f / sum;

    float4 o[16];
#pragma unroll
    for (int dt = 0; dt < 16; dt++) o[dt] = make_float4(0.f, 0.f, 0.f, 0.f);
#pragma unroll
    for (int j = 0; j < 64; j++) {
        float pj = s[j] * inv;
#pragma unroll
        for (int dt = 0; dt < 16; dt++) {
            float4 v = vs4[j * 16 + dt];
            o[dt].x += pj * v.x; o[dt].y += pj * v.y;
            o[dt].z += pj * v.z; o[dt].w += pj * v.w;
        }
    }
    size_t obase = (size_t)bh * 64 * HW + p;
#pragma unroll
    for (int dt = 0; dt < 16; dt++) {
        g_ao[obase + (size_t)(dt * 4 + 0) * HW] = o[dt].x;
        g_ao[obase + (size_t)(dt * 4 + 1) * HW] = o[dt].y;
        g_ao[obase + (size_t)(dt * 4 + 2) * HW] = o[dt].z;
        g_ao[obase + (size_t)(dt * 4 + 3) * HW] = o[dt].w;
    }
}

// ---------------- launch ----------------
extern "C" void kernel_launch(void* const* d_in, const int* in_sizes, int n_in,
                              void* d_out, int out_size) {
    (void)in_sizes; (void)n_in; (void)out_size;
    const float* context      = (const float*)d_in[0];
    const float* query_source = (const float*)d_in[1];
    const float* ctx_g = (const float*)d_in[2];
    const float* ctx_b = (const float*)d_in[3];
    const float* qs_g  = (const float*)d_in[4];
    const float* qs_b  = (const float*)d_in[5];
    const float* w_q   = (const float*)d_in[6];
    const float* w_kv  = (const float*)d_in[7];
    const float* w_out = (const float*)d_in[8];
    const float* gamma = (const float*)d_in[9];
    float* out = (float*)d_out;

    static float *p_ctxn = nullptr, *p_qsn = nullptr, *p_q = nullptr,
                 *p_kv = nullptr, *p_ao = nullptr;
    if (!p_ctxn) {
        cudaGetSymbolAddress((void**)&p_ctxn, g_ctxn);
        cudaGetSymbolAddress((void**)&p_qsn,  g_qsn);
        cudaGetSymbolAddress((void**)&p_q,    g_q);
        cudaGetSymbolAddress((void**)&p_kv,   g_kv);
        cudaGetSymbolAddress((void**)&p_ao,   g_ao);
    }

    // 1) channel layernorms
    stats_kernel<<<1024, 256>>>(context);
    norm_apply_kernel<<<16384, 256>>>(context, ctx_g, ctx_b, p_ctxn);
    stats_kernel<<<1024, 256>>>(query_source);
    norm_apply_kernel<<<16384, 256>>>(query_source, qs_g, qs_b, p_qsn);

    // 2) projections
    gemm_kernel<<<dim3(32, 8, 8), 256>>>(w_kv, p_ctxn, p_kv, 1024, 512, 4096, nullptr, nullptr);
    gemm_kernel<<<dim3(32, 4, 8), 256>>>(w_q,  p_qsn,  p_q,   512, 512, 4096, nullptr, nullptr);

    // 3) l2 norms (q; k half of kv)
    l2norm_kernel<<<1024, 256>>>(p_q,  (size_t)DIMC * HW);
    l2norm_kernel<<<1024, 256>>>(p_kv, (size_t)2 * DIMC * HW);

    // 4) pruning statistics + selection + gather
    kheight_kernel<<<1024, 256>>>();
    kwidth_kernel<<<1024, 256>>>();
    qprobe_kernel<<<4096, 256>>>();
    score_topk_kernel<<<64, 64>>>();
    gather_kernel<<<1024, 256>>>();

    // 5) attention over pruned keys
    attn_kernel<<<dim3(16, 64), 256>>>();

    // 6) out projection + residual: out = gamma*W_out@ao + qs_norm
    gemm_kernel<<<dim3(32, 4, 8), 256>>>(w_out, p_ao, out, 512, 512, 4096, gamma, p_qsn);
}

// round 2
// speedup vs baseline: 1.0017x; 1.0017x over previous
#include <cuda_runtime.h>
#include <math.h>
#include <stdint.h>

#define BATCH 8
#define DIMC  512
#define HW    4096
#define GH    64     // BATCH*HEADS
#define DH    64

// ---------------- scratch (device globals; allocation-free) ----------------
__device__ float g_ctxn[BATCH * DIMC * HW];          // normalized context
__device__ float g_qsn [BATCH * DIMC * HW];          // normalized query_source
__device__ float g_q   [BATCH * DIMC * HW];          // q proj (== folded (64,64,4096))
__device__ float g_kv  [BATCH * 2 * DIMC * HW];      // kv proj
__device__ float g_ao  [BATCH * DIMC * HW];          // attention output
__device__ float g_mean[BATCH * HW];
__device__ float g_rstd[BATCH * HW];
__device__ float g_qprobe[GH * DH];
__device__ float g_kh[GH * DH * 64];
__device__ float g_kw[GH * DH * 64];
__device__ int   g_idxh[GH * 8];
__device__ int   g_idxw[GH * 8];
__device__ float g_kf[GH * 64 * DH];
__device__ float g_vf[GH * 64 * DH];

// ---------------- channel layernorm: stats ----------------
__global__ __launch_bounds__(256) void stats_kernel(const float* __restrict__ in) {
    __shared__ float shs[8][32];
    __shared__ float shq[8][32];
    int tid = threadIdx.x;
    int px = tid & 31, cg = tid >> 5;
    int pos = blockIdx.x * 32 + px;           // 0..32767
    int b = pos >> 12, sp = pos & 4095;
    size_t base = (size_t)b * DIMC * HW + sp;
    float s = 0.f, q = 0.f;
    int c0 = cg * 64;
#pragma unroll 8
    for (int c = 0; c < 64; c++) {
        float x = in[base + (size_t)(c0 + c) * HW];
        s += x; q += x * x;
    }
    shs[cg][px] = s; shq[cg][px] = q;
    __syncthreads();
    if (cg == 0) {
        float ts = 0.f, tq = 0.f;
#pragma unroll
        for (int g = 0; g < 8; g++) { ts += shs[g][px]; tq += shq[g][px]; }
        float mean = ts * (1.0f / 512.0f);
        float var = tq * (1.0f / 512.0f) - mean * mean;
        g_mean[pos] = mean;
        g_rstd[pos] = rsqrtf(var + 1e-5f);
    }
}

// ---------------- channel layernorm: apply ----------------
__global__ __launch_bounds__(256) void norm_apply_kernel(const float* __restrict__ in,
                                                         const float* __restrict__ gw,
                                                         const float* __restrict__ bw,
                                                         float* __restrict__ out) {
    int i4 = blockIdx.x * 256 + threadIdx.x;   // float4 index, < 4194304
    size_t e = (size_t)i4 * 4;
    int sp = (int)(e & 4095);
    int c  = (int)((e >> 12) & 511);
    int b  = (int)(e >> 21);
    int pos = (b << 12) | sp;
    float4 x = ((const float4*)in)[i4];
    float4 m = ((const float4*)g_mean)[pos >> 2];
    float4 r = ((const float4*)g_rstd)[pos >> 2];
    float gc = gw[c], bc = bw[c];
    float4 y;
    y.x = (x.x - m.x) * r.x * gc + bc;
    y.y = (x.y - m.y) * r.y * gc + bc;
    y.z = (x.z - m.z) * r.z * gc + bc;
    y.w = (x.w - m.w) * r.w * gc + bc;
    ((float4*)out)[i4] = y;
}

// ---------------- fp32 tiled GEMM: Y[b,m,n] = sum_k W[m,k]*X[b,k,n] ----------------
// optional epilogue: Y = gamma[0]*acc + addend[b,m,n]
__global__ __launch_bounds__(256) void gemm_kernel(const float* __restrict__ W,
                                                   const float* __restrict__ X,
                                                   float* __restrict__ Y,
                                                   int M, int K, int N,
                                                   const float* __restrict__ gammap,
                                                   const float* __restrict__ addend) {
    __shared__ float As[16][128];
    __shared__ float Bs[16][128];
    int b  = blockIdx.z;
    int m0 = blockIdx.y * 128, n0 = blockIdx.x * 128;
    const float* Xb = X + (size_t)b * K * N;
    float* Yb = Y + (size_t)b * M * N;
    int tid = threadIdx.x;
    int tx = tid & 15, ty = tid >> 4;
    float acc[8][8] = {};
    int rowA = tid >> 2,  colA = (tid & 3) << 2;
    int rowB = tid >> 5,  colB = (tid & 31) << 2;

    for (int k0 = 0; k0 < K; k0 += 16) {
#pragma unroll
        for (int i = 0; i < 2; i++) {
            int r = rowA + i * 64;
            float4 a = *(const float4*)(W + (size_t)(m0 + r) * K + k0 + colA);
            As[colA + 0][r] = a.x; As[colA + 1][r] = a.y;
            As[colA + 2][r] = a.z; As[colA + 3][r] = a.w;
        }
#pragma unroll
        for (int i = 0; i < 2; i++) {
            int r = rowB + i * 8;
            *(float4*)(&Bs[r][colB]) =
                *(const float4*)(Xb + (size_t)(k0 + r) * N + n0 + colB);
        }
        __syncthreads();
#pragma unroll
        for (int kk = 0; kk < 16; kk++) {
            float4 a0 = *(const float4*)&As[kk][ty * 8];
            float4 a1 = *(const float4*)&As[kk][ty * 8 + 4];
            float4 b0 = *(const float4*)&Bs[kk][tx * 8];
            float4 b1 = *(const float4*)&Bs[kk][tx * 8 + 4];
            float ra[8] = {a0.x, a0.y, a0.z, a0.w, a1.x, a1.y, a1.z, a1.w};
            float rb[8] = {b0.x, b0.y, b0.z, b0.w, b1.x, b1.y, b1.z, b1.w};
#pragma unroll
            for (int i = 0; i < 8; i++)
#pragma unroll
                for (int j = 0; j < 8; j++)
                    acc[i][j] += ra[i] * rb[j];
        }
        __syncthreads();
    }

    float ga = gammap ? gammap[0] : 1.0f;
#pragma unroll
    for (int i = 0; i < 8; i++) {
        size_t off = (size_t)(m0 + ty * 8 + i) * N + n0 + tx * 8;
#pragma unroll
        for (int jv = 0; jv < 2; jv++) {
            float4 o;
            float* ai = &acc[i][jv * 4];
            if (addend) {
                float4 ad = *(const float4*)(addend + (size_t)b * M * N + off + jv * 4);
                o.x = ga * ai[0] + ad.x; o.y = ga * ai[1] + ad.y;
                o.z = ga * ai[2] + ad.z; o.w = ga * ai[3] + ad.w;
            } else {
                o.x = ai[0]; o.y = ai[1]; o.z = ai[2]; o.w = ai[3];
            }
            *(float4*)(Yb + off + jv * 4) = o;
        }
    }
}

// ---------------- l2 normalize over dh (64 chans) per (group, position) ----------------
__global__ __launch_bounds__(256) void l2norm_kernel(float* __restrict__ t, size_t bstride) {
    int idx = blockIdx.x * 256 + threadIdx.x;   // 262144 = GH*HW
    int g = idx >> 12, p = idx & 4095;
    size_t base = (size_t)(g >> 3) * bstride + (size_t)(g & 7) * (64 * HW) + p;
    float ss = 0.f;
#pragma unroll 8
    for (int d = 0; d < 64; d++) {
        float x = t[base + (size_t)d * HW];
        ss += x * x;
    }
    float inv = 1.0f / fmaxf(sqrtf(ss), 1e-12f);
#pragma unroll 8
    for (int d = 0; d < 64; d++) t[base + (size_t)d * HW] *= inv;
}

// ---------------- k abs-sum over width -> g_kh[bh][c][h] ----------------
__global__ __launch_bounds__(256) void kheight_kernel() {
    int idx = blockIdx.x * 256 + threadIdx.x;   // 262144
    int bh = idx >> 12, c = (idx >> 6) & 63, h = idx & 63;
    size_t base = (size_t)(bh >> 3) * (2 * DIMC * HW) + (size_t)(bh & 7) * (64 * HW)
                + (size_t)c * HW + (size_t)h * 64;
    const float4* p4 = (const float4*)(g_kv + base);
    float s = 0.f;
#pragma unroll
    for (int i = 0; i < 16; i++) {
        float4 v = p4[i];
        s += fabsf(v.x) + fabsf(v.y) + fabsf(v.z) + fabsf(v.w);
    }
    g_kh[idx] = s;
}

// ---------------- k abs-sum over height -> g_kw[bh][c][w] ----------------
__global__ __launch_bounds__(256) void kwidth_kernel() {
    int idx = blockIdx.x * 256 + threadIdx.x;   // 262144
    int bh = idx >> 12, c = (idx >> 6) & 63, w = idx & 63;
    size_t base = (size_t)(bh >> 3) * (2 * DIMC * HW) + (size_t)(bh & 7) * (64 * HW)
                + (size_t)c * HW + w;
    float s = 0.f;
#pragma unroll 8
    for (int h = 0; h < 64; h++) s += fabsf(g_kv[base + (size_t)h * 64]);
    g_kw[idx] = s;
}

// ---------------- q abs-sum over all spatial -> g_qprobe[bh][c] ----------------
__global__ __launch_bounds__(256) void qprobe_kernel() {
    int bid = blockIdx.x;          // 4096 = GH*DH
    size_t base = (size_t)bid * HW;
    const float4* p4 = (const float4*)(g_q + base);
    float s = 0.f;
    for (int i = threadIdx.x; i < 1024; i += 256) {
        float4 v = p4[i];
        s += fabsf(v.x) + fabsf(v.y) + fabsf(v.z) + fabsf(v.w);
    }
    __shared__ float sh[256];
    sh[threadIdx.x] = s;
    __syncthreads();
    for (int st = 128; st > 0; st >>= 1) {
        if (threadIdx.x < st) sh[threadIdx.x] += sh[threadIdx.x + st];
        __syncthreads();
    }
    if (threadIdx.x == 0) g_qprobe[bid] = sh[0];
}

// ---------------- scores + top-8 selection ----------------
__global__ __launch_bounds__(64) void score_topk_kernel() {
    int bh = blockIdx.x;
    int h = threadIdx.x;          // 64 threads
    __shared__ float sr[64], sc[64];
    float a = 0.f, bb = 0.f;
    for (int c = 0; c < 64; c++) {
        float qp = g_qprobe[bh * 64 + c];
        a  += qp * g_kh[bh * 4096 + c * 64 + h];
        bb += qp * g_kw[bh * 4096 + c * 64 + h];
    }
    sr[h] = a; sc[h] = bb;
    __syncthreads();
    if (h == 0) {
        for (int i = 0; i < 8; i++) {
            float best = -INFINITY; int bi = 0;
            for (int j = 0; j < 64; j++) if (sr[j] > best) { best = sr[j]; bi = j; }
            g_idxh[bh * 8 + i] = bi;
            sr[bi] = -INFINITY;
        }
    } else if (h == 1) {
        for (int i = 0; i < 8; i++) {
            float best = -INFINITY; int bi = 0;
            for (int j = 0; j < 64; j++) if (sc[j] > best) { best = sc[j]; bi = j; }
            g_idxw[bh * 8 + i] = bi;
            sc[bi] = -INFINITY;
        }
    }
}

// ---------------- gather pruned k/v -> g_kf/g_vf [bh][j][d] ----------------
__global__ __launch_bounds__(256) void gather_kernel() {
    int idx = blockIdx.x * 256 + threadIdx.x;   // 262144
    int bh = idx >> 12, j = (idx >> 6) & 63, d = idx & 63;
    int hh = g_idxh[bh * 8 + (j >> 3)];
    int ww = g_idxw[bh * 8 + (j & 7)];
    int p = hh * 64 + ww;
    size_t base = (size_t)(bh >> 3) * (2 * DIMC * HW) + (size_t)(bh & 7) * (64 * HW);
    g_kf[idx] = g_kv[base + (size_t)d * HW + p];
    g_vf[idx] = g_kv[base + (size_t)DIMC * HW + (size_t)d * HW + p];
}

// ---------------- attention over 64 pruned keys ----------------
__global__ __launch_bounds__(256, 1) void attn_kernel() {
    __shared__ float4 ks4[1024];
    __shared__ float4 vs4[1024];
    int bh = blockIdx.y;
    int p = blockIdx.x * 256 + threadIdx.x;
    const float4* kf4 = (const float4*)g_kf;
    const float4* vf4 = (const float4*)g_vf;
    for (int t = threadIdx.x; t < 1024; t += 256) {
        ks4[t] = kf4[bh * 1024 + t];
        vs4[t] = vf4[bh * 1024 + t];
    }
    __syncthreads();

    float qv[64];
    size_t qbase = (size_t)bh * 64 * HW + p;
#pragma unroll
    for (int d = 0; d < 64; d++) qv[d] = g_q[qbase + (size_t)d * HW];

    float s[64];
#pragma unroll
    for (int j = 0; j < 64; j++) {
        float acc = 0.f;
#pragma unroll
        for (int dt = 0; dt < 16; dt++) {
            float4 kk = ks4[j * 16 + dt];
            acc += qv[dt * 4 + 0] * kk.x + qv[dt * 4 + 1] * kk.y
                 + qv[dt * 4 + 2] * kk.z + qv[dt * 4 + 3] * kk.w;
        }
        s[j] = acc;
    }
    float m = -INFINITY;
#pragma unroll
    for (int j = 0; j < 64; j++) m = fmaxf(m, s[j]);
    float sum = 0.f;
#pragma unroll
    for (int j = 0; j < 64; j++) { s[j] = expf(s[j] - m); sum += s[j]; }
    float inv = 1.0f / sum;

    float4 o[16];
#pragma unroll
    for (int dt = 0; dt < 16; dt++) o[dt] = make_float4(0.f, 0.f, 0.f, 0.f);
#pragma unroll
    for (int j = 0; j < 64; j++) {
        float pj = s[j] * inv;
#pragma unroll
        for (int dt = 0; dt < 16; dt++) {
            float4 v = vs4[j * 16 + dt];
            o[dt].x += pj * v.x; o[dt].y += pj * v.y;
            o[dt].z += pj * v.z; o[dt].w += pj * v.w;
        }
    }
    size_t obase = (size_t)bh * 64 * HW + p;
#pragma unroll
    for (int dt = 0; dt < 16; dt++) {
        g_ao[obase + (size_t)(dt * 4 + 0) * HW] = o[dt].x;
        g_ao[obase + (size_t)(dt * 4 + 1) * HW] = o[dt].y;
        g_ao[obase + (size_t)(dt * 4 + 2) * HW] = o[dt].z;
        g_ao[obase + (size_t)(dt * 4 + 3) * HW] = o[dt].w;
    }
}

// ---------------- launch ----------------
extern "C" void kernel_launch(void* const* d_in, const int* in_sizes, int n_in,
                              void* d_out, int out_size) {
    (void)in_sizes; (void)n_in; (void)out_size;
    const float* context      = (const float*)d_in[0];
    const float* query_source = (const float*)d_in[1];
    const float* ctx_g = (const float*)d_in[2];
    const float* ctx_b = (const float*)d_in[3];
    const float* qs_g  = (const float*)d_in[4];
    const float* qs_b  = (const float*)d_in[5];
    const float* w_q   = (const float*)d_in[6];
    const float* w_kv  = (const float*)d_in[7];
    const float* w_out = (const float*)d_in[8];
    const float* gamma = (const float*)d_in[9];
    float* out = (float*)d_out;

    static float *p_ctxn = nullptr, *p_qsn = nullptr, *p_q = nullptr,
                 *p_kv = nullptr, *p_ao = nullptr;
    if (!p_ctxn) {
        cudaGetSymbolAddress((void**)&p_ctxn, g_ctxn);
        cudaGetSymbolAddress((void**)&p_qsn,  g_qsn);
        cudaGetSymbolAddress((void**)&p_q,    g_q);
        cudaGetSymbolAddress((void**)&p_kv,   g_kv);
        cudaGetSymbolAddress((void**)&p_ao,   g_ao);
    }

    // 1) channel layernorms
    stats_kernel<<<1024, 256>>>(context);
    norm_apply_kernel<<<16384, 256>>>(context, ctx_g, ctx_b, p_ctxn);
    stats_kernel<<<1024, 256>>>(query_source);
    norm_apply_kernel<<<16384, 256>>>(query_source, qs_g, qs_b, p_qsn);

    // 2) projections
    gemm_kernel<<<dim3(32, 8, 8), 256>>>(w_kv, p_ctxn, p_kv, 1024, 512, 4096, nullptr, nullptr);
    gemm_kernel<<<dim3(32, 4, 8), 256>>>(w_q,  p_qsn,  p_q,   512, 512, 4096, nullptr, nullptr);

    // 3) l2 norms (q; k half of kv)
    l2norm_kernel<<<1024, 256>>>(p_q,  (size_t)DIMC * HW);
    l2norm_kernel<<<1024, 256>>>(p_kv, (size_t)2 * DIMC * HW);

    // 4) pruning statistics + selection + gather
    kheight_kernel<<<1024, 256>>>();
    kwidth_kernel<<<1024, 256>>>();
    qprobe_kernel<<<4096, 256>>>();
    score_topk_kernel<<<64, 64>>>();
    gather_kernel<<<1024, 256>>>();

    // 5) attention over pruned keys
    attn_kernel<<<dim3(16, 64), 256>>>();

    // 6) out projection + residual: out = gamma*W_out@ao + qs_norm
    gemm_kernel<<<dim3(32, 4, 8), 256>>>(w_out, p_ao, out, 512, 512, 4096, gamma, p_qsn);
}

// round 4
// speedup vs baseline: 1.8913x; 1.8881x over previous
#include <cuda_runtime.h>
#include <cuda_bf16.h>
#include <math.h>
#include <stdint.h>

#define BATCH 8
#define DIMC  512
#define HW    4096
#define GH    64     // BATCH*HEADS
#define DH    64

// ---------------- scratch (device globals; allocation-free) ----------------
__device__ __align__(128) float g_qsn[BATCH * DIMC * HW];
__device__ __align__(128) float g_q  [BATCH * DIMC * HW];
__device__ __align__(128) float g_kv [BATCH * 2 * DIMC * HW];
__device__ __align__(128) __nv_bfloat16 g_ctxh[BATCH * DIMC * HW];
__device__ __align__(128) __nv_bfloat16 g_ctxl[BATCH * DIMC * HW];
__device__ __align__(128) __nv_bfloat16 g_qsh [BATCH * DIMC * HW];
__device__ __align__(128) __nv_bfloat16 g_qsl [BATCH * DIMC * HW];
__device__ __align__(128) __nv_bfloat16 g_aoh [BATCH * DIMC * HW];
__device__ __align__(128) __nv_bfloat16 g_aol [BATCH * DIMC * HW];
__device__ __align__(128) __nv_bfloat16 g_wqh [512 * 512],  g_wql [512 * 512];
__device__ __align__(128) __nv_bfloat16 g_wkvh[1024 * 512], g_wkvl[1024 * 512];
__device__ __align__(128) __nv_bfloat16 g_woh [512 * 512],  g_wol [512 * 512];
__device__ float g_mean[BATCH * HW];
__device__ float g_rstd[BATCH * HW];
__device__ float g_qprobe[GH * DH];
__device__ float g_kh[GH * DH * 64];
__device__ float g_kw[GH * DH * 64];
__device__ int   g_idxh[GH * 8];
__device__ int   g_idxw[GH * 8];
__device__ float g_kf[GH * 64 * DH];
__device__ float g_vf[GH * 64 * DH];

// ================= warp-MMA helpers (sm_80-compatible PTX) =================
__device__ __forceinline__ uint32_t smem_u32(const void* p) {
    uint32_t a;
    asm("{ .reg .u64 t; cvta.to.shared.u64 t, %1; cvt.u32.u64 %0, t; }" : "=r"(a) : "l"(p));
    return a;
}
__device__ __forceinline__ void cp16(uint32_t d, const void* s) {
    asm volatile("cp.async.cg.shared.global [%0], [%1], 16;" :: "r"(d), "l"(s));
}
__device__ __forceinline__ void ldsm4(uint32_t* r, uint32_t a) {
    asm volatile("ldmatrix.sync.aligned.m8n8.x4.shared.b16 {%0,%1,%2,%3}, [%4];"
                 : "=r"(r[0]), "=r"(r[1]), "=r"(r[2]), "=r"(r[3]) : "r"(a));
}
__device__ __forceinline__ void ldsm4t(uint32_t* r, uint32_t a) {
    asm volatile("ldmatrix.sync.aligned.m8n8.x4.trans.shared.b16 {%0,%1,%2,%3}, [%4];"
                 : "=r"(r[0]), "=r"(r[1]), "=r"(r[2]), "=r"(r[3]) : "r"(a));
}
__device__ __forceinline__ void mma16816(float* c, const uint32_t* a, const uint32_t* b) {
    asm volatile(
        "mma.sync.aligned.m16n8k16.row.col.f32.bf16.bf16.f32 "
        "{%0,%1,%2,%3}, {%4,%5,%6,%7}, {%8,%9}, {%0,%1,%2,%3};"
        : "+f"(c[0]), "+f"(c[1]), "+f"(c[2]), "+f"(c[3])
        : "r"(a[0]), "r"(a[1]), "r"(a[2]), "r"(a[3]), "r"(b[0]), "r"(b[1]));
}

// SMEM layout (bf16 element offsets). A rows padded to 72 (conflict-free ldmatrix),
// B rows padded to 136.
#define A_PAD 72
#define B_PAD 136
#define A_HL  (128 * A_PAD)        // 9216 elems per hi/lo plane
#define B_HL  (64 * B_PAD)         // 8704
#define B_OFF (2 * A_HL)           // 18432
#define BUF_ELEMS (B_OFF + 2 * B_HL)   // 35840
#define GEMM_SMEM (2 * BUF_ELEMS * 2)  // 143360 bytes

// ======== tensor-core GEMM: Y[b,m,n] = sum_k W[m,k]*X[b,k,n], bf16 hi/lo ×3 ========
// grid (N/128, M/128, BATCH), 256 threads.
__global__ void __launch_bounds__(256, 1)
mma_gemm_kernel(const __nv_bfloat16* __restrict__ Wh, const __nv_bfloat16* __restrict__ Wl,
                const __nv_bfloat16* __restrict__ Xh, const __nv_bfloat16* __restrict__ Xl,
                float* __restrict__ Y, int M,
                const float* __restrict__ gammap, const float* __restrict__ addend) {
    extern __shared__ __nv_bfloat16 sm[];
    uint32_t sbase = smem_u32(sm);
    int tid = threadIdx.x;
    int lane = tid & 31, wid = tid >> 5;
    int b = blockIdx.z;
    int m0 = blockIdx.y * 128, n0 = blockIdx.x * 128;
    const __nv_bfloat16* wsrc[2] = { Wh + (size_t)m0 * 512, Wl + (size_t)m0 * 512 };
    const __nv_bfloat16* xsrc[2] = { Xh + (size_t)b * DIMC * HW + n0,
                                     Xl + (size_t)b * DIMC * HW + n0 };

    // copy K-chunk c (64 k) into buffer c&1
    auto copy_chunk = [&](int c) {
        uint32_t sb = sbase + (uint32_t)(c & 1) * (BUF_ELEMS * 2);
#pragma unroll
        for (int i = 0; i < 8; i++) {           // A: 128m x 64k x {h,l}
            int t = tid + i * 256;
            int hl = t >> 10, q = t & 1023, m = q >> 3, j = q & 7;
            cp16(sb + (uint32_t)(hl * A_HL + m * A_PAD + j * 8) * 2,
                 wsrc[hl] + (size_t)m * 512 + c * 64 + j * 8);
        }
#pragma unroll
        for (int i = 0; i < 8; i++) {           // B: 64k x 128n x {h,l}
            int t = tid + i * 256;
            int hl = t >> 10, q = t & 1023, k = q >> 4, j = q & 15;
            cp16(sb + (uint32_t)(B_OFF + hl * B_HL + k * B_PAD + j * 8) * 2,
                 xsrc[hl] + (size_t)(c * 64 + k) * HW + j * 8);
        }
        asm volatile("cp.async.commit_group;" ::: "memory");
    };

    float acc[4][4][4] = {};
    int wm = (wid & 1) * 64;    // warp m-offset within 128
    int wn = (wid >> 1) * 32;   // warp n-offset within 128

    copy_chunk(0);
    for (int c = 0; c < 8; c++) {
        if (c < 7) {
            copy_chunk(c + 1);
            asm volatile("cp.async.wait_group 1;" ::: "memory");
        } else {
            asm volatile("cp.async.wait_group 0;" ::: "memory");
        }
        __syncthreads();
        uint32_t sb = sbase + (uint32_t)(c & 1) * (BUF_ELEMS * 2);
        // ldmatrix lane base addresses
        uint32_t a_h0 = sb + (uint32_t)((wm + (lane & 15)) * A_PAD + (lane >> 4) * 8) * 2;
        uint32_t a_l0 = a_h0 + A_HL * 2;
        uint32_t b_h0 = sb + (uint32_t)(B_OFF + (lane & 15) * B_PAD + wn + (lane >> 4) * 8) * 2;
        uint32_t b_l0 = b_h0 + B_HL * 2;
#pragma unroll
        for (int kk = 0; kk < 4; kk++) {
            uint32_t ah[4][4], al[4][4], bh[2][4], bl[2][4];
#pragma unroll
            for (int mb = 0; mb < 4; mb++) {
                uint32_t off = (uint32_t)(mb * 16 * A_PAD + kk * 16) * 2;
                ldsm4(ah[mb], a_h0 + off);
                ldsm4(al[mb], a_l0 + off);
            }
#pragma unroll
            for (int ng = 0; ng < 2; ng++) {
                uint32_t off = (uint32_t)(kk * 16 * B_PAD + ng * 16) * 2;
                ldsm4t(bh[ng], b_h0 + off);
                ldsm4t(bl[ng], b_l0 + off);
            }
#pragma unroll
            for (int mb = 0; mb < 4; mb++) {
#pragma unroll
                for (int nb = 0; nb < 4; nb++) {
                    const uint32_t* bhf = &bh[nb >> 1][(nb & 1) * 2];
                    const uint32_t* blf = &bl[nb >> 1][(nb & 1) * 2];
                    mma16816(acc[mb][nb], ah[mb], bhf);   // Ah*Bh
                    mma16816(acc[mb][nb], ah[mb], blf);   // Ah*Bl
                    mma16816(acc[mb][nb], al[mb], bhf);   // Al*Bh
                }
            }
        }
        __syncthreads();
    }

    // epilogue
    float ga = gammap ? gammap[0] : 1.0f;
    int g = lane >> 2, tig = lane & 3;
#pragma unroll
    for (int mb = 0; mb < 4; mb++) {
#pragma unroll
        for (int nb = 0; nb < 4; nb++) {
            int m = m0 + wm + mb * 16 + g;
            int n = n0 + wn + nb * 8 + tig * 2;
            size_t off0 = ((size_t)b * M + m) * HW + n;
            size_t off1 = off0 + (size_t)8 * HW;
            float* p = acc[mb][nb];
            if (addend) {
                size_t a0 = ((size_t)b * 512 + m) * HW + n;
                float2 d0 = *(const float2*)(addend + a0);
                float2 d1 = *(const float2*)(addend + a0 + (size_t)8 * HW);
                *(float2*)(Y + off0) = make_float2(ga * p[0] + d0.x, ga * p[1] + d0.y);
                *(float2*)(Y + off1) = make_float2(ga * p[2] + d1.x, ga * p[3] + d1.y);
            } else {
                *(float2*)(Y + off0) = make_float2(p[0], p[1]);
                *(float2*)(Y + off1) = make_float2(p[2], p[3]);
            }
        }
    }
}

// ---------------- channel layernorm: stats ----------------
__global__ __launch_bounds__(256) void stats_kernel(const float* __restrict__ in) {
    __shared__ float shs[8][32];
    __shared__ float shq[8][32];
    int tid = threadIdx.x;
    int px = tid & 31, cg = tid >> 5;
    int pos = blockIdx.x * 32 + px;
    int b = pos >> 12, sp = pos & 4095;
    size_t base = (size_t)b * DIMC * HW + sp;
    float s = 0.f, q = 0.f;
    int c0 = cg * 64;
#pragma unroll 8
    for (int c = 0; c < 64; c++) {
        float x = in[base + (size_t)(c0 + c) * HW];
        s += x; q += x * x;
    }
    shs[cg][px] = s; shq[cg][px] = q;
    __syncthreads();
    if (cg == 0) {
        float ts = 0.f, tq = 0.f;
#pragma unroll
        for (int g = 0; g < 8; g++) { ts += shs[g][px]; tq += shq[g][px]; }
        float mean = ts * (1.0f / 512.0f);
        float var = tq * (1.0f / 512.0f) - mean * mean;
        g_mean[pos] = mean;
        g_rstd[pos] = rsqrtf(var + 1e-5f);
    }
}

// ---------------- channel layernorm: apply + bf16 hi/lo split ----------------
__global__ __launch_bounds__(256) void norm_apply_kernel(const float* __restrict__ in,
                                                         const float* __restrict__ gw,
                                                         const float* __restrict__ bw,
                                                         __nv_bfloat16* __restrict__ oh,
                                                         __nv_bfloat16* __restrict__ ol,
                                                         float* __restrict__ of) {
    int i4 = blockIdx.x * 256 + threadIdx.x;
    size_t e = (size_t)i4 * 4;
    int sp = (int)(e & 4095);
    int c  = (int)((e >> 12) & 511);
    int b  = (int)(e >> 21);
    int pos = (b << 12) | sp;
    float4 x = ((const float4*)in)[i4];
    float4 m = ((const float4*)g_mean)[pos >> 2];
    float4 r = ((const float4*)g_rstd)[pos >> 2];
    float gc = gw[c], bc = bw[c];
    float4 y;
    y.x = (x.x - m.x) * r.x * gc + bc;
    y.y = (x.y - m.y) * r.y * gc + bc;
    y.z = (x.z - m.z) * r.z * gc + bc;
    y.w = (x.w - m.w) * r.w * gc + bc;
    float yy[4] = { y.x, y.y, y.z, y.w };
    ushort4 hv, lv;
    unsigned short* hp = &hv.x; unsigned short* lp = &lv.x;
#pragma unroll
    for (int u = 0; u < 4; u++) {
        __nv_bfloat16 h = __float2bfloat16(yy[u]);
        __nv_bfloat16 l = __float2bfloat16(yy[u] - __bfloat162float(h));
        hp[u] = __bfloat16_as_ushort(h);
        lp[u] = __bfloat16_as_ushort(l);
    }
    *(ushort4*)(oh + e) = hv;
    *(ushort4*)(ol + e) = lv;
    if (of) ((float4*)of)[i4] = y;
}

// ---------------- weight hi/lo split ----------------
__global__ __launch_bounds__(256) void wsplit_kernel(const float* __restrict__ w,
                                                     __nv_bfloat16* __restrict__ wh,
                                                     __nv_bfloat16* __restrict__ wl, int n) {
    int i = blockIdx.x * 256 + threadIdx.x;
    if (i < n) {
        float x = w[i];
        __nv_bfloat16 h = __float2bfloat16(x);
        wh[i] = h;
        wl[i] = __float2bfloat16(x - __bfloat162float(h));
    }
}

// ---------------- l2 normalize over dh ----------------
__global__ __launch_bounds__(256) void l2norm_kernel(float* __restrict__ t, size_t bstride) {
    int idx = blockIdx.x * 256 + threadIdx.x;
    int g = idx >> 12, p = idx & 4095;
    size_t base = (size_t)(g >> 3) * bstride + (size_t)(g & 7) * (64 * HW) + p;
    float ss = 0.f;
#pragma unroll 8
    for (int d = 0; d < 64; d++) {
        float x = t[base + (size_t)d * HW];
        ss += x * x;
    }
    float inv = 1.0f / fmaxf(sqrtf(ss), 1e-12f);
#pragma unroll 8
    for (int d = 0; d < 64; d++) t[base + (size_t)d * HW] *= inv;
}

// ---------------- k abs-sum over width ----------------
__global__ __launch_bounds__(256) void kheight_kernel() {
    int idx = blockIdx.x * 256 + threadIdx.x;
    int bh = idx >> 12, c = (idx >> 6) & 63, h = idx & 63;
    size_t base = (size_t)(bh >> 3) * (2 * DIMC * HW) + (size_t)(bh & 7) * (64 * HW)
                + (size_t)c * HW + (size_t)h * 64;
    const float4* p4 = (const float4*)(g_kv + base);
    float s = 0.f;
#pragma unroll
    for (int i = 0; i < 16; i++) {
        float4 v = p4[i];
        s += fabsf(v.x) + fabsf(v.y) + fabsf(v.z) + fabsf(v.w);
    }
    g_kh[idx] = s;
}

// ---------------- k abs-sum over height ----------------
__global__ __launch_bounds__(256) void kwidth_kernel() {
    int idx = blockIdx.x * 256 + threadIdx.x;
    int bh = idx >> 12, c = (idx >> 6) & 63, w = idx & 63;
    size_t base = (size_t)(bh >> 3) * (2 * DIMC * HW) + (size_t)(bh & 7) * (64 * HW)
                + (size_t)c * HW + w;
    float s = 0.f;
#pragma unroll 8
    for (int h = 0; h < 64; h++) s += fabsf(g_kv[base + (size_t)h * 64]);
    g_kw[idx] = s;
}

// ---------------- q abs-sum over spatial ----------------
__global__ __launch_bounds__(256) void qprobe_kernel() {
    int bid = blockIdx.x;
    size_t base = (size_t)bid * HW;
    const float4* p4 = (const float4*)(g_q + base);
    float s = 0.f;
    for (int i = threadIdx.x; i < 1024; i += 256) {
        float4 v = p4[i];
        s += fabsf(v.x) + fabsf(v.y) + fabsf(v.z) + fabsf(v.w);
    }
    __shared__ float sh[256];
    sh[threadIdx.x] = s;
    __syncthreads();
    for (int st = 128; st > 0; st >>= 1) {
        if (threadIdx.x < st) sh[threadIdx.x] += sh[threadIdx.x + st];
        __syncthreads();
    }
    if (threadIdx.x == 0) g_qprobe[bid] = sh[0];
}

// ---------------- scores + top-8 selection ----------------
__global__ __launch_bounds__(64) void score_topk_kernel() {
    int bh = blockIdx.x;
    int h = threadIdx.x;
    __shared__ float sr[64], sc[64];
    float a = 0.f, bb = 0.f;
    for (int c = 0; c < 64; c++) {
        float qp = g_qprobe[bh * 64 + c];
        a  += qp * g_kh[bh * 4096 + c * 64 + h];
        bb += qp * g_kw[bh * 4096 + c * 64 + h];
    }
    sr[h] = a; sc[h] = bb;
    __syncthreads();
    if (h == 0) {
        for (int i = 0; i < 8; i++) {
            float best = -INFINITY; int bi = 0;
            for (int j = 0; j < 64; j++) if (sr[j] > best) { best = sr[j]; bi = j; }
            g_idxh[bh * 8 + i] = bi;
            sr[bi] = -INFINITY;
        }
    } else if (h == 1) {
        for (int i = 0; i < 8; i++) {
            float best = -INFINITY; int bi = 0;
            for (int j = 0; j < 64; j++) if (sc[j] > best) { best = sc[j]; bi = j; }
            g_idxw[bh * 8 + i] = bi;
            sc[bi] = -INFINITY;
        }
    }
}

// ---------------- gather pruned k/v ----------------
__global__ __launch_bounds__(256) void gather_kernel() {
    int idx = blockIdx.x * 256 + threadIdx.x;
    int bh = idx >> 12, j = (idx >> 6) & 63, d = idx & 63;
    int hh = g_idxh[bh * 8 + (j >> 3)];
    int ww = g_idxw[bh * 8 + (j & 7)];
    int p = hh * 64 + ww;
    size_t base = (size_t)(bh >> 3) * (2 * DIMC * HW) + (size_t)(bh & 7) * (64 * HW);
    g_kf[idx] = g_kv[base + (size_t)d * HW + p];
    g_vf[idx] = g_kv[base + (size_t)DIMC * HW + (size_t)d * HW + p];
}

// ---------------- attention over 64 pruned keys (emit bf16 hi/lo) ----------------
__global__ __launch_bounds__(256, 1) void attn_kernel() {
    __shared__ float4 ks4[1024];
    __shared__ float4 vs4[1024];
    int bh = blockIdx.y;
    int p = blockIdx.x * 256 + threadIdx.x;
    const float4* kf4 = (const float4*)g_kf;
    const float4* vf4 = (const float4*)g_vf;
    for (int t = threadIdx.x; t < 1024; t += 256) {
        ks4[t] = kf4[bh * 1024 + t];
        vs4[t] = vf4[bh * 1024 + t];
    }
    __syncthreads();

    float qv[64];
    size_t qbase = (size_t)bh * 64 * HW + p;
#pragma unroll
    for (int d = 0; d < 64; d++) qv[d] = g_q[qbase + (size_t)d * HW];

    float s[64];
#pragma unroll
    for (int j = 0; j < 64; j++) {
        float acc = 0.f;
#pragma unroll
        for (int dt = 0; dt < 16; dt++) {
            float4 kk = ks4[j * 16 + dt];
            acc += qv[dt * 4 + 0] * kk.x + qv[dt * 4 + 1] * kk.y
                 + qv[dt * 4 + 2] * kk.z + qv[dt * 4 + 3] * kk.w;
        }
        s[j] = acc;
    }
    float m = -INFINITY;
#pragma unroll
    for (int j = 0; j < 64; j++) m = fmaxf(m, s[j]);
    float sum = 0.f;
#pragma unroll
    for (int j = 0; j < 64; j++) { s[j] = expf(s[j] - m); sum += s[j]; }
    float inv = 1.0f / sum;

    float4 o[16];
#pragma unroll
    for (int dt = 0; dt < 16; dt++) o[dt] = make_float4(0.f, 0.f, 0.f, 0.f);
#pragma unroll
    for (int j = 0; j < 64; j++) {
        float pj = s[j] * inv;
#pragma unroll
        for (int dt = 0; dt < 16; dt++) {
            float4 v = vs4[j * 16 + dt];
            o[dt].x += pj * v.x; o[dt].y += pj * v.y;
            o[dt].z += pj * v.z; o[dt].w += pj * v.w;
        }
    }
    size_t obase = (size_t)bh * 64 * HW + p;
#pragma unroll
    for (int dt = 0; dt < 16; dt++) {
        float vals[4] = { o[dt].x, o[dt].y, o[dt].z, o[dt].w };
#pragma unroll
        for (int u = 0; u < 4; u++) {
            size_t idx = obase + (size_t)(dt * 4 + u) * HW;
            __nv_bfloat16 h = __float2bfloat16(vals[u]);
            g_aoh[idx] = h;
            g_aol[idx] = __float2bfloat16(vals[u] - __bfloat162float(h));
        }
    }
}

// ---------------- launch ----------------
extern "C" void kernel_launch(void* const* d_in, const int* in_sizes, int n_in,
                              void* d_out, int out_size) {
    (void)in_sizes; (void)n_in; (void)out_size;
    const float* context      = (const float*)d_in[0];
    const float* query_source = (const float*)d_in[1];
    const float* ctx_g = (const float*)d_in[2];
    const float* ctx_b = (const float*)d_in[3];
    const float* qs_g  = (const float*)d_in[4];
    const float* qs_b  = (const float*)d_in[5];
    const float* w_q   = (const float*)d_in[6];
    const float* w_kv  = (const float*)d_in[7];
    const float* w_out = (const float*)d_in[8];
    const float* gamma = (const float*)d_in[9];
    float* out = (float*)d_out;

    static bool inited = false;
    static float *p_qsn, *p_q, *p_kv;
    static __nv_bfloat16 *p_ctxh, *p_ctxl, *p_qsh, *p_qsl, *p_aoh, *p_aol;
    static __nv_bfloat16 *p_wqh, *p_wql, *p_wkvh, *p_wkvl, *p_woh, *p_wol;
    if (!inited) {
        cudaGetSymbolAddress((void**)&p_qsn,  g_qsn);
        cudaGetSymbolAddress((void**)&p_q,    g_q);
        cudaGetSymbolAddress((void**)&p_kv,   g_kv);
        cudaGetSymbolAddress((void**)&p_ctxh, g_ctxh);
        cudaGetSymbolAddress((void**)&p_ctxl, g_ctxl);
        cudaGetSymbolAddress((void**)&p_qsh,  g_qsh);
        cudaGetSymbolAddress((void**)&p_qsl,  g_qsl);
        cudaGetSymbolAddress((void**)&p_aoh,  g_aoh);
        cudaGetSymbolAddress((void**)&p_aol,  g_aol);
        cudaGetSymbolAddress((void**)&p_wqh,  g_wqh);
        cudaGetSymbolAddress((void**)&p_wql,  g_wql);
        cudaGetSymbolAddress((void**)&p_wkvh, g_wkvh);
        cudaGetSymbolAddress((void**)&p_wkvl, g_wkvl);
        cudaGetSymbolAddress((void**)&p_woh,  g_woh);
        cudaGetSymbolAddress((void**)&p_wol,  g_wol);
        cudaFuncSetAttribute(mma_gemm_kernel,
                             cudaFuncAttributeMaxDynamicSharedMemorySize, GEMM_SMEM);
        inited = true;
    }

    // 1) channel layernorms -> bf16 hi/lo (+ fp32 qsn for residual)
    stats_kernel<<<1024, 256>>>(context);
    norm_apply_kernel<<<16384, 256>>>(context, ctx_g, ctx_b, p_ctxh, p_ctxl, nullptr);
    stats_kernel<<<1024, 256>>>(query_source);
    norm_apply_kernel<<<16384, 256>>>(query_source, qs_g, qs_b, p_qsh, p_qsl, p_qsn);

    // weight splits
    wsplit_kernel<<<1024, 256>>>(w_q,   p_wqh,  p_wql,  512 * 512);
    wsplit_kernel<<<2048, 256>>>(w_kv,  p_wkvh, p_wkvl, 1024 * 512);
    wsplit_kernel<<<1024, 256>>>(w_out, p_woh,  p_wol,  512 * 512);

    // 2) projections (HMMA tensor core, bf16x3)
    mma_gemm_kernel<<<dim3(32, 8, 8), 256, GEMM_SMEM>>>(p_wkvh, p_wkvl, p_ctxh, p_ctxl,
                                                        p_kv, 1024, nullptr, nullptr);
    mma_gemm_kernel<<<dim3(32, 4, 8), 256, GEMM_SMEM>>>(p_wqh, p_wql, p_qsh, p_qsl,
                                                        p_q, 512, nullptr, nullptr);

    // 3) l2 norms
    l2norm_kernel<<<1024, 256>>>(p_q,  (size_t)DIMC * HW);
    l2norm_kernel<<<1024, 256>>>(p_kv, (size_t)2 * DIMC * HW);

    // 4) pruning statistics + selection + gather
    kheight_kernel<<<1024, 256>>>();
    kwidth_kernel<<<1024, 256>>>();
    qprobe_kernel<<<4096, 256>>>();
    score_topk_kernel<<<64, 64>>>();
    gather_kernel<<<1024, 256>>>();

    // 5) attention (emits bf16 hi/lo for out-proj)
    attn_kernel<<<dim3(16, 64), 256>>>();

    // 6) out projection + residual: out = gamma*W_out@ao + qs_norm
    mma_gemm_kernel<<<dim3(32, 4, 8), 256, GEMM_SMEM>>>(p_woh, p_wol, p_aoh, p_aol,
                                                        out, 512, gamma, p_qsn);
}

// round 5
// speedup vs baseline: 2.2487x; 1.1890x over previous
#include <cuda_runtime.h>
#include <cuda_fp16.h>
#include <math.h>
#include <stdint.h>

#define BATCH 8
#define DIMC  512
#define HW    4096
#define GH    64     // BATCH*HEADS
#define DH    64

// ---------------- scratch (device globals; allocation-free) ----------------
__device__ __align__(128) float  g_qsn[BATCH * DIMC * HW];     // normalized qs fp32 (residual)
__device__ __align__(128) float  g_q  [BATCH * DIMC * HW];     // q proj fp32
__device__ __align__(128) float  g_kv [BATCH * 2 * DIMC * HW]; // kv proj fp32
__device__ __align__(128) __half g_ctxh[BATCH * DIMC * HW];    // normalized ctx fp16
__device__ __align__(128) __half g_qsh [BATCH * DIMC * HW];    // normalized qs fp16
__device__ __align__(128) __half g_aoh [BATCH * DIMC * HW];    // attention out fp16
__device__ __align__(128) __half g_wqh [512 * 512],  g_wql [512 * 512];
__device__ __align__(128) __half g_wkvh[1024 * 512], g_wkvl[1024 * 512];
__device__ __align__(128) __half g_woh [512 * 512],  g_wol [512 * 512];
__device__ float g_qinv[GH * HW];
__device__ float g_kinv[GH * HW];
__device__ float g_qprobe[GH * DH];
__device__ float g_kh[GH * DH * 64];
__device__ float g_kw[GH * DH * 64];
__device__ int   g_idxh[GH * 8];
__device__ int   g_idxw[GH * 8];
__device__ float g_kf[GH * 64 * DH];
__device__ float g_vf[GH * 64 * DH];

// ================= warp-MMA helpers =================
__device__ __forceinline__ uint32_t smem_u32(const void* p) {
    uint32_t a;
    asm("{ .reg .u64 t; cvta.to.shared.u64 t, %1; cvt.u32.u64 %0, t; }" : "=r"(a) : "l"(p));
    return a;
}
__device__ __forceinline__ void cp16(uint32_t d, const void* s) {
    asm volatile("cp.async.cg.shared.global [%0], [%1], 16;" :: "r"(d), "l"(s));
}
__device__ __forceinline__ void ldsm4(uint32_t* r, uint32_t a) {
    asm volatile("ldmatrix.sync.aligned.m8n8.x4.shared.b16 {%0,%1,%2,%3}, [%4];"
                 : "=r"(r[0]), "=r"(r[1]), "=r"(r[2]), "=r"(r[3]) : "r"(a));
}
__device__ __forceinline__ void ldsm4t(uint32_t* r, uint32_t a) {
    asm volatile("ldmatrix.sync.aligned.m8n8.x4.trans.shared.b16 {%0,%1,%2,%3}, [%4];"
                 : "=r"(r[0]), "=r"(r[1]), "=r"(r[2]), "=r"(r[3]) : "r"(a));
}
__device__ __forceinline__ void mma16816(float* c, const uint32_t* a, const uint32_t* b) {
    asm volatile(
        "mma.sync.aligned.m16n8k16.row.col.f32.f16.f16.f32 "
        "{%0,%1,%2,%3}, {%4,%5,%6,%7}, {%8,%9}, {%0,%1,%2,%3};"
        : "+f"(c[0]), "+f"(c[1]), "+f"(c[2]), "+f"(c[3])
        : "r"(a[0]), "r"(a[1]), "r"(a[2]), "r"(a[3]), "r"(b[0]), "r"(b[1]));
}

// SMEM: A padded to 72 elems/row, B to 136 elems/row (conflict-free ldmatrix)
#define A_PAD 72
#define B_PAD 136
#define A_PL  (128 * A_PAD)          // 9216 elems per A plane
#define B_PL  (64 * B_PAD)           // 8704
#define B_OFF (2 * A_PL)             // 18432
#define ST_ELEMS (B_OFF + B_PL)      // 27136 elems = 54272 B per stage
#define GEMM_SMEM (3 * ST_ELEMS * 2) // 162816 B, 3 stages

// ======== GEMM: Y[b,m,n] = (1/64)*sum_k (Wh+Wl)[m,k]*Xh[b,k,n], fp16 2-pass ========
// grid (N/128, M/128, BATCH), 256 threads. W planes pre-scaled by 64.
__global__ void __launch_bounds__(256, 1)
mma_gemm_kernel(const __half* __restrict__ Wh, const __half* __restrict__ Wl,
                const __half* __restrict__ Xh, float* __restrict__ Y, int M,
                const float* __restrict__ gammap, const float* __restrict__ addend) {
    extern __shared__ __half sm[];
    uint32_t sbase = smem_u32(sm);
    int tid = threadIdx.x;
    int lane = tid & 31, wid = tid >> 5;
    int b = blockIdx.z;
    int m0 = blockIdx.y * 128, n0 = blockIdx.x * 128;
    const __half* wsrc[2] = { Wh + (size_t)m0 * 512, Wl + (size_t)m0 * 512 };
    const __half* xsrc = Xh + (size_t)b * DIMC * HW + n0;

    auto copy_chunk = [&](int c) {
        uint32_t sb = sbase + (uint32_t)(c % 3) * (ST_ELEMS * 2);
#pragma unroll
        for (int i = 0; i < 8; i++) {           // A: 128m x 64k x {h,l}
            int t = tid + i * 256;
            int hl = t >> 10, q = t & 1023, m = q >> 3, j = q & 7;
            cp16(sb + (uint32_t)(hl * A_PL + m * A_PAD + j * 8) * 2,
                 wsrc[hl] + (size_t)m * 512 + c * 64 + j * 8);
        }
#pragma unroll
        for (int i = 0; i < 4; i++) {           // B: 64k x 128n, hi only
            int t = tid + i * 256;
            int k = t >> 4, j = t & 15;
            cp16(sb + (uint32_t)(B_OFF + k * B_PAD + j * 8) * 2,
                 xsrc + (size_t)(c * 64 + k) * HW + j * 8);
        }
        asm volatile("cp.async.commit_group;" ::: "memory");
    };

    float acc[4][4][4] = {};
    int wm = (wid & 1) * 64;
    int wn = (wid >> 1) * 32;

    copy_chunk(0);
    copy_chunk(1);
    for (int c = 0; c < 8; c++) {
        if (c < 6) {
            copy_chunk(c + 2);
            asm volatile("cp.async.wait_group 2;" ::: "memory");
        } else if (c < 7) {
            asm volatile("cp.async.wait_group 1;" ::: "memory");
        } else {
            asm volatile("cp.async.wait_group 0;" ::: "memory");
        }
        __syncthreads();
        uint32_t sb = sbase + (uint32_t)(c % 3) * (ST_ELEMS * 2);
        uint32_t a_h0 = sb + (uint32_t)((wm + (lane & 15)) * A_PAD + (lane >> 4) * 8) * 2;
        uint32_t a_l0 = a_h0 + A_PL * 2;
        uint32_t b_h0 = sb + (uint32_t)(B_OFF + (lane & 15) * B_PAD + wn + (lane >> 4) * 8) * 2;
#pragma unroll
        for (int kk = 0; kk < 4; kk++) {
            uint32_t ah[4][4], al[4][4], bh[2][4];
#pragma unroll
            for (int mb = 0; mb < 4; mb++) {
                uint32_t off = (uint32_t)(mb * 16 * A_PAD + kk * 16) * 2;
                ldsm4(ah[mb], a_h0 + off);
                ldsm4(al[mb], a_l0 + off);
            }
#pragma unroll
            for (int ng = 0; ng < 2; ng++) {
                uint32_t off = (uint32_t)(kk * 16 * B_PAD + ng * 16) * 2;
                ldsm4t(bh[ng], b_h0 + off);
            }
#pragma unroll
            for (int mb = 0; mb < 4; mb++) {
#pragma unroll
                for (int nb = 0; nb < 4; nb++) {
                    const uint32_t* bf = &bh[nb >> 1][(nb & 1) * 2];
                    mma16816(acc[mb][nb], ah[mb], bf);   // Wh*Xh
                    mma16816(acc[mb][nb], al[mb], bf);   // Wl*Xh
                }
            }
        }
        __syncthreads();
    }

    // epilogue (acc is 64x the true value)
    const float isc = 1.0f / 64.0f;
    float ga = gammap ? gammap[0] * isc : isc;
    int g = lane >> 2, tig = lane & 3;
#pragma unroll
    for (int mb = 0; mb < 4; mb++) {
#pragma unroll
        for (int nb = 0; nb < 4; nb++) {
            int m = m0 + wm + mb * 16 + g;
            int n = n0 + wn + nb * 8 + tig * 2;
            size_t off0 = ((size_t)b * M + m) * HW + n;
            size_t off1 = off0 + (size_t)8 * HW;
            float* p = acc[mb][nb];
            if (addend) {
                size_t a0 = ((size_t)b * 512 + m) * HW + n;
                float2 d0 = *(const float2*)(addend + a0);
                float2 d1 = *(const float2*)(addend + a0 + (size_t)8 * HW);
                *(float2*)(Y + off0) = make_float2(ga * p[0] + d0.x, ga * p[1] + d0.y);
                *(float2*)(Y + off1) = make_float2(ga * p[2] + d1.x, ga * p[3] + d1.y);
            } else {
                *(float2*)(Y + off0) = make_float2(ga * p[0], ga * p[1]);
                *(float2*)(Y + off1) = make_float2(ga * p[2], ga * p[3]);
            }
        }
    }
}

// ---------------- fused channel layernorm (stats + apply) ----------------
// grid 1024, block 256: 32 positions per block, 8 channel-groups of 64.
__global__ __launch_bounds__(256) void fused_norm_kernel(const float* __restrict__ in,
                                                         const float* __restrict__ gw,
                                                         const float* __restrict__ bw,
                                                         __half* __restrict__ oh,
                                                         float* __restrict__ of) {
    __shared__ float shs[8][32], shq[8][32];
    __shared__ float smean[32], srstd[32];
    int tid = threadIdx.x;
    int px = tid & 31, cg = tid >> 5;
    int pos = blockIdx.x * 32 + px;
    int b = pos >> 12, sp = pos & 4095;
    size_t base = (size_t)b * DIMC * HW + sp;
    int c0 = cg * 64;
    float v[64];
    float s = 0.f, q = 0.f;
#pragma unroll 8
    for (int c = 0; c < 64; c++) {
        float x = in[base + (size_t)(c0 + c) * HW];
        v[c] = x; s += x; q += x * x;
    }
    shs[cg][px] = s; shq[cg][px] = q;
    __syncthreads();
    if (cg == 0) {
        float ts = 0.f, tq = 0.f;
#pragma unroll
        for (int g = 0; g < 8; g++) { ts += shs[g][px]; tq += shq[g][px]; }
        float mean = ts * (1.0f / 512.0f);
        float var = tq * (1.0f / 512.0f) - mean * mean;
        smean[px] = mean;
        srstd[px] = rsqrtf(var + 1e-5f);
    }
    __syncthreads();
    float m = smean[px], r = srstd[px];
#pragma unroll 8
    for (int c = 0; c < 64; c++) {
        float y = (v[c] - m) * r * gw[c0 + c] + bw[c0 + c];
        size_t idx = base + (size_t)(c0 + c) * HW;
        oh[idx] = __float2half_rn(y);
        if (of) of[idx] = y;
    }
}

// ---------------- weight hi/lo split (fp16, scaled by 64) ----------------
__global__ __launch_bounds__(256) void wsplit_kernel(const float* __restrict__ w,
                                                     __half* __restrict__ wh,
                                                     __half* __restrict__ wl, int n) {
    int i = blockIdx.x * 256 + threadIdx.x;
    if (i < n) {
        float x = 64.0f * w[i];
        __half h = __float2half_rn(x);
        wh[i] = h;
        wl[i] = __float2half_rn(x - __half2float(h));
    }
}

// ---------------- per-position inverse L2 norm over 64 channels ----------------
__global__ __launch_bounds__(256) void inv_norm_kernel(const float* __restrict__ t,
                                                       float* __restrict__ inv,
                                                       size_t bstride) {
    int idx = blockIdx.x * 256 + threadIdx.x;   // GH*HW
    int g = idx >> 12, p = idx & 4095;
    size_t base = (size_t)(g >> 3) * bstride + (size_t)(g & 7) * (64 * HW) + p;
    float ss = 0.f;
#pragma unroll 8
    for (int d = 0; d < 64; d++) {
        float x = t[base + (size_t)d * HW];
        ss += x * x;
    }
    inv[idx] = 1.0f / fmaxf(sqrtf(ss), 1e-12f);
}

// ---------------- fused k abs-sums (height + width) with kinv ----------------
// grid 4096 = (bh, c), 128 threads, stages the 64x64 plane in smem.
__global__ __launch_bounds__(128) void khw_kernel() {
    __shared__ float pl[4096];
    int bh = blockIdx.x >> 6, c = blockIdx.x & 63;
    size_t base = (size_t)(bh >> 3) * (2 * DIMC * HW) + (size_t)(bh & 7) * (64 * HW)
                + (size_t)c * HW;
    const float* ki = g_kinv + bh * HW;
    int tid = threadIdx.x;
    for (int i = tid; i < 4096; i += 128)
        pl[i] = fabsf(g_kv[base + i]) * ki[i];
    __syncthreads();
    if (tid < 64) {
        int h = tid;
        float s = 0.f;
#pragma unroll 8
        for (int w = 0; w < 64; w++) s += pl[h * 64 + ((w + h) & 63)];
        g_kh[bh * 4096 + c * 64 + h] = s;
    } else {
        int w = tid - 64;
        float s = 0.f;
#pragma unroll 8
        for (int h = 0; h < 64; h++) s += pl[h * 64 + w];
        g_kw[bh * 4096 + c * 64 + w] = s;
    }
}

// ---------------- q abs-sum over spatial (with qinv) ----------------
__global__ __launch_bounds__(256) void qprobe_kernel() {
    int bid = blockIdx.x;          // bh*64 + c
    int g = bid >> 6;
    size_t base = (size_t)bid * HW;
    const float4* p4 = (const float4*)(g_q + base);
    const float4* iv4 = (const float4*)(g_qinv + (size_t)g * HW);
    float s = 0.f;
    for (int i = threadIdx.x; i < 1024; i += 256) {
        float4 v = p4[i];
        float4 iv = iv4[i];
        s += fabsf(v.x) * iv.x + fabsf(v.y) * iv.y + fabsf(v.z) * iv.z + fabsf(v.w) * iv.w;
    }
    __shared__ float sh[256];
    sh[threadIdx.x] = s;
    __syncthreads();
    for (int st = 128; st > 0; st >>= 1) {
        if (threadIdx.x < st) sh[threadIdx.x] += sh[threadIdx.x + st];
        __syncthreads();
    }
    if (threadIdx.x == 0) g_qprobe[bid] = sh[0];
}

// ---------------- scores + top-8 selection ----------------
__global__ __launch_bounds__(64) void score_topk_kernel() {
    int bh = blockIdx.x;
    int h = threadIdx.x;
    __shared__ float sr[64], sc[64];
    float a = 0.f, bb = 0.f;
    for (int c = 0; c < 64; c++) {
        float qp = g_qprobe[bh * 64 + c];
        a  += qp * g_kh[bh * 4096 + c * 64 + h];
        bb += qp * g_kw[bh * 4096 + c * 64 + h];
    }
    sr[h] = a; sc[h] = bb;
    __syncthreads();
    if (h == 0) {
        for (int i = 0; i < 8; i++) {
            float best = -INFINITY; int bi = 0;
            for (int j = 0; j < 64; j++) if (sr[j] > best) { best = sr[j]; bi = j; }
            g_idxh[bh * 8 + i] = bi;
            sr[bi] = -INFINITY;
        }
    } else if (h == 1) {
        for (int i = 0; i < 8; i++) {
            float best = -INFINITY; int bi = 0;
            for (int j = 0; j < 64; j++) if (sc[j] > best) { best = sc[j]; bi = j; }
            g_idxw[bh * 8 + i] = bi;
            sc[bi] = -INFINITY;
        }
    }
}

// ---------------- gather pruned k/v (k normalized) ----------------
__global__ __launch_bounds__(256) void gather_kernel() {
    int idx = blockIdx.x * 256 + threadIdx.x;
    int bh = idx >> 12, j = (idx >> 6) & 63, d = idx & 63;
    int hh = g_idxh[bh * 8 + (j >> 3)];
    int ww = g_idxw[bh * 8 + (j & 7)];
    int p = hh * 64 + ww;
    size_t base = (size_t)(bh >> 3) * (2 * DIMC * HW) + (size_t)(bh & 7) * (64 * HW);
    g_kf[idx] = g_kv[base + (size_t)d * HW + p] * g_kinv[bh * HW + p];
    g_vf[idx] = g_kv[base + (size_t)DIMC * HW + (size_t)d * HW + p];
}

// ---------------- attention over 64 pruned keys ----------------
__global__ __launch_bounds__(256, 1) void attn_kernel() {
    __shared__ float4 ks4[1024];
    __shared__ float4 vs4[1024];
    int bh = blockIdx.y;
    int p = blockIdx.x * 256 + threadIdx.x;
    const float4* kf4 = (const float4*)g_kf;
    const float4* vf4 = (const float4*)g_vf;
    for (int t = threadIdx.x; t < 1024; t += 256) {
        ks4[t] = kf4[bh * 1024 + t];
        vs4[t] = vf4[bh * 1024 + t];
    }
    __syncthreads();

    float qiv = g_qinv[bh * HW + p];
    float qv[64];
    size_t qbase = (size_t)bh * 64 * HW + p;
#pragma unroll
    for (int d = 0; d < 64; d++) qv[d] = g_q[qbase + (size_t)d * HW] * qiv;

    float s[64];
#pragma unroll
    for (int j = 0; j < 64; j++) {
        float acc = 0.f;
#pragma unroll
        for (int dt = 0; dt < 16; dt++) {
            float4 kk = ks4[j * 16 + dt];
            acc += qv[dt * 4 + 0] * kk.x + qv[dt * 4 + 1] * kk.y
                 + qv[dt * 4 + 2] * kk.z + qv[dt * 4 + 3] * kk.w;
        }
        s[j] = acc;
    }
    float m = -INFINITY;
#pragma unroll
    for (int j = 0; j < 64; j++) m = fmaxf(m, s[j]);
    float sum = 0.f;
#pragma unroll
    for (int j = 0; j < 64; j++) { s[j] = expf(s[j] - m); sum += s[j]; }
    float inv = 1.0f / sum;

    float4 o[16];
#pragma unroll
    for (int dt = 0; dt < 16; dt++) o[dt] = make_float4(0.f, 0.f, 0.f, 0.f);
#pragma unroll
    for (int j = 0; j < 64; j++) {
        float pj = s[j] * inv;
#pragma unroll
        for (int dt = 0; dt < 16; dt++) {
            float4 v = vs4[j * 16 + dt];
            o[dt].x += pj * v.x; o[dt].y += pj * v.y;
            o[dt].z += pj * v.z; o[dt].w += pj * v.w;
        }
    }
    size_t obase = (size_t)bh * 64 * HW + p;
#pragma unroll
    for (int dt = 0; dt < 16; dt++) {
        g_aoh[obase + (size_t)(dt * 4 + 0) * HW] = __float2half_rn(o[dt].x);
        g_aoh[obase + (size_t)(dt * 4 + 1) * HW] = __float2half_rn(o[dt].y);
        g_aoh[obase + (size_t)(dt * 4 + 2) * HW] = __float2half_rn(o[dt].z);
        g_aoh[obase + (size_t)(dt * 4 + 3) * HW] = __float2half_rn(o[dt].w);
    }
}

// ---------------- launch ----------------
extern "C" void kernel_launch(void* const* d_in, const int* in_sizes, int n_in,
                              void* d_out, int out_size) {
    (void)in_sizes; (void)n_in; (void)out_size;
    const float* context      = (const float*)d_in[0];
    const float* query_source = (const float*)d_in[1];
    const float* ctx_g = (const float*)d_in[2];
    const float* ctx_b = (const float*)d_in[3];
    const float* qs_g  = (const float*)d_in[4];
    const float* qs_b  = (const float*)d_in[5];
    const float* w_q   = (const float*)d_in[6];
    const float* w_kv  = (const float*)d_in[7];
    const float* w_out = (const float*)d_in[8];
    const float* gamma = (const float*)d_in[9];
    float* out = (float*)d_out;

    static bool inited = false;
    static float *p_qsn, *p_q, *p_kv, *p_qinv, *p_kinv;
    static __half *p_ctxh, *p_qsh, *p_aoh;
    static __half *p_wqh, *p_wql, *p_wkvh, *p_wkvl, *p_woh, *p_wol;
    if (!inited) {
        cudaGetSymbolAddress((void**)&p_qsn,  g_qsn);
        cudaGetSymbolAddress((void**)&p_q,    g_q);
        cudaGetSymbolAddress((void**)&p_kv,   g_kv);
        cudaGetSymbolAddress((void**)&p_qinv, g_qinv);
        cudaGetSymbolAddress((void**)&p_kinv, g_kinv);
        cudaGetSymbolAddress((void**)&p_ctxh, g_ctxh);
        cudaGetSymbolAddress((void**)&p_qsh,  g_qsh);
        cudaGetSymbolAddress((void**)&p_aoh,  g_aoh);
        cudaGetSymbolAddress((void**)&p_wqh,  g_wqh);
        cudaGetSymbolAddress((void**)&p_wql,  g_wql);
        cudaGetSymbolAddress((void**)&p_wkvh, g_wkvh);
        cudaGetSymbolAddress((void**)&p_wkvl, g_wkvl);
        cudaGetSymbolAddress((void**)&p_woh,  g_woh);
        cudaGetSymbolAddress((void**)&p_wol,  g_wol);
        cudaFuncSetAttribute(mma_gemm_kernel,
                             cudaFuncAttributeMaxDynamicSharedMemorySize, GEMM_SMEM);
        inited = true;
    }

    // 1) fused channel layernorms -> fp16 (+ fp32 qsn for residual)
    fused_norm_kernel<<<1024, 256>>>(context, ctx_g, ctx_b, p_ctxh, nullptr);
    fused_norm_kernel<<<1024, 256>>>(query_source, qs_g, qs_b, p_qsh, p_qsn);

    // weight splits (fp16 hi/lo, scaled x64)
    wsplit_kernel<<<1024, 256>>>(w_q,   p_wqh,  p_wql,  512 * 512);
    wsplit_kernel<<<2048, 256>>>(w_kv,  p_wkvh, p_wkvl, 1024 * 512);
    wsplit_kernel<<<1024, 256>>>(w_out, p_woh,  p_wol,  512 * 512);

    // 2) projections (fp16 2-pass HMMA)
    mma_gemm_kernel<<<dim3(32, 8, 8), 256, GEMM_SMEM>>>(p_wkvh, p_wkvl, p_ctxh,
                                                        p_kv, 1024, nullptr, nullptr);
    mma_gemm_kernel<<<dim3(32, 4, 8), 256, GEMM_SMEM>>>(p_wqh, p_wql, p_qsh,
                                                        p_q, 512, nullptr, nullptr);

    // 3) inverse L2 norms (not materialized into tensors)
    inv_norm_kernel<<<1024, 256>>>(p_q,  p_qinv, (size_t)DIMC * HW);
    inv_norm_kernel<<<1024, 256>>>(p_kv, p_kinv, (size_t)2 * DIMC * HW);

    // 4) pruning statistics + selection + gather
    khw_kernel<<<4096, 128>>>();
    qprobe_kernel<<<4096, 256>>>();
    score_topk_kernel<<<64, 64>>>();
    gather_kernel<<<1024, 256>>>();

    // 5) attention (emits fp16 for out-proj)
    attn_kernel<<<dim3(16, 64), 256>>>();

    // 6) out projection + residual: out = gamma*W_out@ao + qs_norm
    mma_gemm_kernel<<<dim3(32, 4, 8), 256, GEMM_SMEM>>>(p_woh, p_wol, p_aoh,
                                                        out, 512, gamma, p_qsn);
}

// round 6
// speedup vs baseline: 4.5758x; 2.0349x over previous
#include <cuda_runtime.h>
#include <cuda_fp16.h>
#include <math.h>
#include <stdint.h>

#define BATCH 8
#define DIMC  512
#define HW    4096
#define GH    64     // BATCH*HEADS
#define DH    64

// ---------------- scratch (device globals; allocation-free) ----------------
__device__ __align__(128) float  g_qsn[BATCH * DIMC * HW];     // normalized qs fp32 (residual)
__device__ __align__(128) float  g_q  [BATCH * DIMC * HW];     // q proj fp32
__device__ __align__(128) float  g_kv [BATCH * 2 * DIMC * HW]; // kv proj fp32
__device__ __align__(128) __half g_ctxh[BATCH * DIMC * HW];    // normalized ctx fp16
__device__ __align__(128) __half g_qsh [BATCH * DIMC * HW];    // normalized qs fp16
__device__ __align__(128) __half g_aoh [BATCH * DIMC * HW];    // attention out fp16
__device__ __align__(128) __half g_wq [512 * 512];
__device__ __align__(128) __half g_wkv[1024 * 512];
__device__ __align__(128) __half g_wo [512 * 512];
__device__ float g_qinv[GH * HW];
__device__ float g_kinv[GH * HW];
__device__ float g_qprobe[GH * DH];
__device__ float g_kh[GH * DH * 64];
__device__ float g_kw[GH * DH * 64];
__device__ int   g_idxh[GH * 8];
__device__ int   g_idxw[GH * 8];
__device__ __half g_kT[GH * 64 * 64];   // [bh][d][j]  (normalized k, transposed)
__device__ __half g_vf[GH * 64 * 64];   // [bh][j][d]

// ================= warp-MMA helpers =================
__device__ __forceinline__ uint32_t smem_u32(const void* p) {
    uint32_t a;
    asm("{ .reg .u64 t; cvta.to.shared.u64 t, %1; cvt.u32.u64 %0, t; }" : "=r"(a) : "l"(p));
    return a;
}
__device__ __forceinline__ void cp16(uint32_t d, const void* s) {
    asm volatile("cp.async.cg.shared.global [%0], [%1], 16;" :: "r"(d), "l"(s));
}
__device__ __forceinline__ void ldsm4(uint32_t* r, uint32_t a) {
    asm volatile("ldmatrix.sync.aligned.m8n8.x4.shared.b16 {%0,%1,%2,%3}, [%4];"
                 : "=r"(r[0]), "=r"(r[1]), "=r"(r[2]), "=r"(r[3]) : "r"(a));
}
__device__ __forceinline__ void ldsm4t(uint32_t* r, uint32_t a) {
    asm volatile("ldmatrix.sync.aligned.m8n8.x4.trans.shared.b16 {%0,%1,%2,%3}, [%4];"
                 : "=r"(r[0]), "=r"(r[1]), "=r"(r[2]), "=r"(r[3]) : "r"(a));
}
__device__ __forceinline__ void mma16816(float* c, const uint32_t* a, const uint32_t* b) {
    asm volatile(
        "mma.sync.aligned.m16n8k16.row.col.f32.f16.f16.f32 "
        "{%0,%1,%2,%3}, {%4,%5,%6,%7}, {%8,%9}, {%0,%1,%2,%3};"
        : "+f"(c[0]), "+f"(c[1]), "+f"(c[2]), "+f"(c[3])
        : "r"(a[0]), "r"(a[1]), "r"(a[2]), "r"(a[3]), "r"(b[0]), "r"(b[1]));
}

// SMEM: A padded to 72 elems/row, B to 136 (conflict-free ldmatrix)
#define A_PAD 72
#define B_PAD 136
#define A_PL  (128 * A_PAD)              // 9216 elems
#define ST_ELEMS (A_PL + 64 * B_PAD)     // 17920 elems = 35840 B/stage
#define GEMM_SMEM (3 * ST_ELEMS * 2)     // 107520 B, 3 stages

// ======== GEMM: Y[b,m,n] = sum_k W[m,k]*X[b,k,n], fp16 single-pass, fp32 acc ========
// grid (N/128, M/128, BATCH), 256 threads, 2 CTAs/SM.
__global__ void __launch_bounds__(256, 2)
mma_gemm_kernel(const __half* __restrict__ Wh, const __half* __restrict__ Xh,
                float* __restrict__ Y, int M,
                const float* __restrict__ gammap, const float* __restrict__ addend) {
    extern __shared__ __half sm[];
    uint32_t sbase = smem_u32(sm);
    int tid = threadIdx.x;
    int lane = tid & 31, wid = tid >> 5;
    int b = blockIdx.z;
    int m0 = blockIdx.y * 128, n0 = blockIdx.x * 128;
    const __half* wsrc = Wh + (size_t)m0 * 512;
    const __half* xsrc = Xh + (size_t)b * DIMC * HW + n0;

    auto copy_chunk = [&](int c) {
        uint32_t sb = sbase + (uint32_t)(c % 3) * (ST_ELEMS * 2);
#pragma unroll
        for (int i = 0; i < 4; i++) {           // A: 128m x 64k
            int t = tid + i * 256;
            int m = t >> 3, j = t & 7;
            cp16(sb + (uint32_t)(m * A_PAD + j * 8) * 2,
                 wsrc + (size_t)m * 512 + c * 64 + j * 8);
        }
#pragma unroll
        for (int i = 0; i < 4; i++) {           // B: 64k x 128n
            int t = tid + i * 256;
            int k = t >> 4, j = t & 15;
            cp16(sb + (uint32_t)(A_PL + k * B_PAD + j * 8) * 2,
                 xsrc + (size_t)(c * 64 + k) * HW + j * 8);
        }
        asm volatile("cp.async.commit_group;" ::: "memory");
    };

    float acc[4][4][4] = {};
    int wm = (wid & 1) * 64;
    int wn = (wid >> 1) * 32;

    copy_chunk(0);
    copy_chunk(1);
    for (int c = 0; c < 8; c++) {
        if (c < 6) {
            copy_chunk(c + 2);
            asm volatile("cp.async.wait_group 2;" ::: "memory");
        } else if (c < 7) {
            asm volatile("cp.async.wait_group 1;" ::: "memory");
        } else {
            asm volatile("cp.async.wait_group 0;" ::: "memory");
        }
        __syncthreads();
        uint32_t sb = sbase + (uint32_t)(c % 3) * (ST_ELEMS * 2);
        uint32_t a_0 = sb + (uint32_t)((wm + (lane & 15)) * A_PAD + (lane >> 4) * 8) * 2;
        uint32_t b_0 = sb + (uint32_t)(A_PL + (lane & 15) * B_PAD + wn + (lane >> 4) * 8) * 2;
#pragma unroll
        for (int kk = 0; kk < 4; kk++) {
            uint32_t ah[4][4], bh[2][4];
#pragma unroll
            for (int mb = 0; mb < 4; mb++)
                ldsm4(ah[mb], a_0 + (uint32_t)(mb * 16 * A_PAD + kk * 16) * 2);
#pragma unroll
            for (int ng = 0; ng < 2; ng++)
                ldsm4t(bh[ng], b_0 + (uint32_t)(kk * 16 * B_PAD + ng * 16) * 2);
#pragma unroll
            for (int mb = 0; mb < 4; mb++)
#pragma unroll
                for (int nb = 0; nb < 4; nb++)
                    mma16816(acc[mb][nb], ah[mb], &bh[nb >> 1][(nb & 1) * 2]);
        }
        __syncthreads();
    }

    float ga = gammap ? gammap[0] : 1.0f;
    int g = lane >> 2, tig = lane & 3;
#pragma unroll
    for (int mb = 0; mb < 4; mb++) {
#pragma unroll
        for (int nb = 0; nb < 4; nb++) {
            int m = m0 + wm + mb * 16 + g;
            int n = n0 + wn + nb * 8 + tig * 2;
            size_t off0 = ((size_t)b * M + m) * HW + n;
            size_t off1 = off0 + (size_t)8 * HW;
            float* p = acc[mb][nb];
            if (addend) {
                size_t a0 = ((size_t)b * 512 + m) * HW + n;
                float2 d0 = *(const float2*)(addend + a0);
                float2 d1 = *(const float2*)(addend + a0 + (size_t)8 * HW);
                *(float2*)(Y + off0) = make_float2(ga * p[0] + d0.x, ga * p[1] + d0.y);
                *(float2*)(Y + off1) = make_float2(ga * p[2] + d1.x, ga * p[3] + d1.y);
            } else {
                *(float2*)(Y + off0) = make_float2(p[0], p[1]);
                *(float2*)(Y + off1) = make_float2(p[2], p[3]);
            }
        }
    }
}

// ---------------- fused channel layernorm (stats + apply) ----------------
__global__ __launch_bounds__(256) void fused_norm_kernel(const float* __restrict__ in,
                                                         const float* __restrict__ gw,
                                                         const float* __restrict__ bw,
                                                         __half* __restrict__ oh,
                                                         float* __restrict__ of) {
    __shared__ float shs[8][32], shq[8][32];
    __shared__ float smean[32], srstd[32];
    int tid = threadIdx.x;
    int px = tid & 31, cg = tid >> 5;
    int pos = blockIdx.x * 32 + px;
    int b = pos >> 12, sp = pos & 4095;
    size_t base = (size_t)b * DIMC * HW + sp;
    int c0 = cg * 64;
    float v[64];
    float s = 0.f, q = 0.f;
#pragma unroll 8
    for (int c = 0; c < 64; c++) {
        float x = in[base + (size_t)(c0 + c) * HW];
        v[c] = x; s += x; q += x * x;
    }
    shs[cg][px] = s; shq[cg][px] = q;
    __syncthreads();
    if (cg == 0) {
        float ts = 0.f, tq = 0.f;
#pragma unroll
        for (int g = 0; g < 8; g++) { ts += shs[g][px]; tq += shq[g][px]; }
        float mean = ts * (1.0f / 512.0f);
        float var = tq * (1.0f / 512.0f) - mean * mean;
        smean[px] = mean;
        srstd[px] = rsqrtf(var + 1e-5f);
    }
    __syncthreads();
    float m = smean[px], r = srstd[px];
#pragma unroll 8
    for (int c = 0; c < 64; c++) {
        float y = (v[c] - m) * r * gw[c0 + c] + bw[c0 + c];
        size_t idx = base + (size_t)(c0 + c) * HW;
        oh[idx] = __float2half_rn(y);
        if (of) of[idx] = y;
    }
}

// ---------------- weight fp32 -> fp16 ----------------
__global__ __launch_bounds__(256) void wconv_kernel(const float* __restrict__ w,
                                                    __half* __restrict__ wh, int n) {
    int i = blockIdx.x * 256 + threadIdx.x;
    if (i < n) wh[i] = __float2half_rn(w[i]);
}

// ---------------- per-position inverse L2 norm over 64 channels ----------------
__global__ __launch_bounds__(256) void inv_norm_kernel(const float* __restrict__ t,
                                                       float* __restrict__ inv,
                                                       size_t bstride) {
    int idx = blockIdx.x * 256 + threadIdx.x;   // GH*HW
    int g = idx >> 12, p = idx & 4095;
    size_t base = (size_t)(g >> 3) * bstride + (size_t)(g & 7) * (64 * HW) + p;
    float ss = 0.f;
#pragma unroll 8
    for (int d = 0; d < 64; d++) {
        float x = t[base + (size_t)d * HW];
        ss += x * x;
    }
    inv[idx] = 1.0f / fmaxf(sqrtf(ss), 1e-12f);
}

// ---------------- fused k abs-sums (height + width), normalized k ----------------
__global__ __launch_bounds__(128) void khw_kernel() {
    __shared__ float pl[4096];
    int bh = blockIdx.x >> 6, c = blockIdx.x & 63;
    size_t base = (size_t)(bh >> 3) * (2 * DIMC * HW) + (size_t)(bh & 7) * (64 * HW)
                + (size_t)c * HW;
    const float* ki = g_kinv + bh * HW;
    int tid = threadIdx.x;
    for (int i = tid; i < 4096; i += 128)
        pl[i] = fabsf(g_kv[base + i]) * ki[i];
    __syncthreads();
    if (tid < 64) {
        int h = tid;
        float s = 0.f;
#pragma unroll 8
        for (int w = 0; w < 64; w++) s += pl[h * 64 + ((w + h) & 63)];
        g_kh[bh * 4096 + c * 64 + h] = s;
    } else {
        int w = tid - 64;
        float s = 0.f;
#pragma unroll 8
        for (int h = 0; h < 64; h++) s += pl[h * 64 + w];
        g_kw[bh * 4096 + c * 64 + w] = s;
    }
}

// ---------------- q abs-sum over spatial (normalized q) ----------------
__global__ __launch_bounds__(256) void qprobe_kernel() {
    int bid = blockIdx.x;          // bh*64 + c
    int g = bid >> 6;
    size_t base = (size_t)bid * HW;
    const float4* p4 = (const float4*)(g_q + base);
    const float4* iv4 = (const float4*)(g_qinv + (size_t)g * HW);
    float s = 0.f;
    for (int i = threadIdx.x; i < 1024; i += 256) {
        float4 v = p4[i];
        float4 iv = iv4[i];
        s += fabsf(v.x) * iv.x + fabsf(v.y) * iv.y + fabsf(v.z) * iv.z + fabsf(v.w) * iv.w;
    }
    __shared__ float sh[256];
    sh[threadIdx.x] = s;
    __syncthreads();
    for (int st = 128; st > 0; st >>= 1) {
        if (threadIdx.x < st) sh[threadIdx.x] += sh[threadIdx.x + st];
        __syncthreads();
    }
    if (threadIdx.x == 0) g_qprobe[bid] = sh[0];
}

// ---------------- scores + top-8 selection ----------------
__global__ __launch_bounds__(64) void score_topk_kernel() {
    int bh = blockIdx.x;
    int h = threadIdx.x;
    __shared__ float sr[64], sc[64];
    float a = 0.f, bb = 0.f;
    for (int c = 0; c < 64; c++) {
        float qp = g_qprobe[bh * 64 + c];
        a  += qp * g_kh[bh * 4096 + c * 64 + h];
        bb += qp * g_kw[bh * 4096 + c * 64 + h];
    }
    sr[h] = a; sc[h] = bb;
    __syncthreads();
    if (h == 0) {
        for (int i = 0; i < 8; i++) {
            float best = -INFINITY; int bi = 0;
            for (int j = 0; j < 64; j++) if (sr[j] > best) { best = sr[j]; bi = j; }
            g_idxh[bh * 8 + i] = bi;
            sr[bi] = -INFINITY;
        }
    } else if (h == 1) {
        for (int i = 0; i < 8; i++) {
            float best = -INFINITY; int bi = 0;
            for (int j = 0; j < 64; j++) if (sc[j] > best) { best = sc[j]; bi = j; }
            g_idxw[bh * 8 + i] = bi;
            sc[bi] = -INFINITY;
        }
    }
}

// ---------------- gather pruned k/v -> fp16 tiles for MMA attention ----------------
// g_kT[bh][d][j] = k_norm ; g_vf[bh][j][d] = v
__global__ __launch_bounds__(256) void gather_kernel() {
    int idx = blockIdx.x * 256 + threadIdx.x;   // 262144
    int bh = idx >> 12, r = (idx >> 6) & 63, cc = idx & 63;
    size_t base = (size_t)(bh >> 3) * (2 * DIMC * HW) + (size_t)(bh & 7) * (64 * HW);
    {   // kT: row d=r, col j=cc
        int hh = g_idxh[bh * 8 + (cc >> 3)];
        int ww = g_idxw[bh * 8 + (cc & 7)];
        int p = hh * 64 + ww;
        g_kT[idx] = __float2half_rn(g_kv[base + (size_t)r * HW + p] * g_kinv[bh * HW + p]);
    }
    {   // vf: row j=r, col d=cc
        int hh = g_idxh[bh * 8 + (r >> 3)];
        int ww = g_idxw[bh * 8 + (r & 7)];
        int p = hh * 64 + ww;
        g_vf[idx] = __float2half_rn(g_kv[base + (size_t)DIMC * HW + (size_t)cc * HW + p]);
    }
}

// ---------------- MMA attention: per (bh, 128-query tile) ----------------
// S = Qn*K^T (fp16 in, fp32 acc), softmax in regs, O = P*V, store [d][p] fp16.
__global__ __launch_bounds__(128) void attn_kernel() {
    __shared__ __half sQ[128 * A_PAD];   // [p][d]; reused for O staging [q][d]
    __shared__ __half sK[64 * A_PAD];    // [d][j]
    __shared__ __half sV[64 * A_PAD];    // [j][d]
    int tid = threadIdx.x, lane = tid & 31, w = tid >> 5;
    int p0 = blockIdx.x * 128, bh = blockIdx.y;
    uint32_t sQa = smem_u32(sQ), sKa = smem_u32(sK), sVa = smem_u32(sV);

    const __half* kt = g_kT + bh * 4096;
    const __half* vf = g_vf + bh * 4096;
#pragma unroll
    for (int i = 0; i < 4; i++) {
        int t = tid + i * 128;
        int r = t >> 3, j = t & 7;
        cp16(sKa + (uint32_t)(r * A_PAD + j * 8) * 2, kt + r * 64 + j * 8);
        cp16(sVa + (uint32_t)(r * A_PAD + j * 8) * 2, vf + r * 64 + j * 8);
    }
    asm volatile("cp.async.commit_group;" ::: "memory");

    // Q: fp32 * qinv -> fp16 smem [p][d]
    const float* qp = g_q + (size_t)bh * 64 * HW + p0;
    const float* qi = g_qinv + bh * HW + p0;
#pragma unroll
    for (int i = 0; i < 32; i++) {
        int t = tid + i * 128;          // 4096 half2 units
        int d2 = t >> 7, p = t & 127;
        float iv = qi[p];
        __half2 h = __floats2half2_rn(qp[(size_t)(2 * d2) * HW + p] * iv,
                                      qp[(size_t)(2 * d2 + 1) * HW + p] * iv);
        *(__half2*)(sQ + p * A_PAD + 2 * d2) = h;
    }
    asm volatile("cp.async.wait_group 0;" ::: "memory");
    __syncthreads();

    // S = Q*K^T : each warp 32 q rows (2 m16 tiles), n = 64 j (8 n8 tiles)
    float sacc[2][8][4] = {};
#pragma unroll
    for (int kk = 0; kk < 4; kk++) {
        uint32_t a[2][4], bk[4][4];
#pragma unroll
        for (int mb = 0; mb < 2; mb++)
            ldsm4(a[mb], sQa + (uint32_t)((w * 32 + mb * 16 + (lane & 15)) * A_PAD
                                          + kk * 16 + (lane >> 4) * 8) * 2);
#pragma unroll
        for (int nt2 = 0; nt2 < 4; nt2++)
            ldsm4t(bk[nt2], sKa + (uint32_t)((kk * 16 + (lane & 15)) * A_PAD
                                             + nt2 * 16 + (lane >> 4) * 8) * 2);
#pragma unroll
        for (int mb = 0; mb < 2; mb++)
#pragma unroll
            for (int nt = 0; nt < 8; nt++)
                mma16816(sacc[mb][nt], a[mb], &bk[nt >> 1][(nt & 1) * 2]);
    }

    // softmax over each row (64 scores); rows g and g+8 per thread per mb
    float is0[2], is1[2];
#pragma unroll
    for (int mb = 0; mb < 2; mb++) {
        float mx0 = -INFINITY, mx1 = -INFINITY;
#pragma unroll
        for (int nt = 0; nt < 8; nt++) {
            mx0 = fmaxf(mx0, fmaxf(sacc[mb][nt][0], sacc[mb][nt][1]));
            mx1 = fmaxf(mx1, fmaxf(sacc[mb][nt][2], sacc[mb][nt][3]));
        }
        mx0 = fmaxf(mx0, __shfl_xor_sync(0xffffffff, mx0, 1));
        mx0 = fmaxf(mx0, __shfl_xor_sync(0xffffffff, mx0, 2));
        mx1 = fmaxf(mx1, __shfl_xor_sync(0xffffffff, mx1, 1));
        mx1 = fmaxf(mx1, __shfl_xor_sync(0xffffffff, mx1, 2));
        float s0 = 0.f, s1 = 0.f;
#pragma unroll
        for (int nt = 0; nt < 8; nt++) {
            sacc[mb][nt][0] = expf(sacc[mb][nt][0] - mx0);
            sacc[mb][nt][1] = expf(sacc[mb][nt][1] - mx0);
            sacc[mb][nt][2] = expf(sacc[mb][nt][2] - mx1);
            sacc[mb][nt][3] = expf(sacc[mb][nt][3] - mx1);
            s0 += sacc[mb][nt][0] + sacc[mb][nt][1];
            s1 += sacc[mb][nt][2] + sacc[mb][nt][3];
        }
        s0 += __shfl_xor_sync(0xffffffff, s0, 1);
        s0 += __shfl_xor_sync(0xffffffff, s0, 2);
        s1 += __shfl_xor_sync(0xffffffff, s1, 1);
        s1 += __shfl_xor_sync(0xffffffff, s1, 2);
        is0[mb] = 1.0f / s0;
        is1[mb] = 1.0f / s1;
    }

    // P (fp16 a-frags) directly from acc frags: k16 tile u <- n8 tiles 2u, 2u+1
    uint32_t pa[2][4][4];
#pragma unroll
    for (int mb = 0; mb < 2; mb++)
#pragma unroll
        for (int u = 0; u < 4; u++) {
            __half2 h0 = __floats2half2_rn(sacc[mb][2*u][0],   sacc[mb][2*u][1]);
            __half2 h1 = __floats2half2_rn(sacc[mb][2*u][2],   sacc[mb][2*u][3]);
            __half2 h2 = __floats2half2_rn(sacc[mb][2*u+1][0], sacc[mb][2*u+1][1]);
            __half2 h3 = __floats2half2_rn(sacc[mb][2*u+1][2], sacc[mb][2*u+1][3]);
            pa[mb][u][0] = *(uint32_t*)&h0;
            pa[mb][u][1] = *(uint32_t*)&h1;
            pa[mb][u][2] = *(uint32_t*)&h2;
            pa[mb][u][3] = *(uint32_t*)&h3;
        }

    // O = P*V : k = 64 j (4 k16), n = 64 d (8 n8)
    float oacc[2][8][4] = {};
#pragma unroll
    for (int u = 0; u < 4; u++) {
        uint32_t bv[4][4];
#pragma unroll
        for (int nt2 = 0; nt2 < 4; nt2++)
            ldsm4t(bv[nt2], sVa + (uint32_t)((u * 16 + (lane & 15)) * A_PAD
                                             + nt2 * 16 + (lane >> 4) * 8) * 2);
#pragma unroll
        for (int mb = 0; mb < 2; mb++)
#pragma unroll
            for (int nt = 0; nt < 8; nt++)
                mma16816(oacc[mb][nt], pa[mb][u], &bv[nt >> 1][(nt & 1) * 2]);
    }

    __syncthreads();   // done reading sQ; reuse as O staging [q][d]
#pragma unroll
    for (int mb = 0; mb < 2; mb++) {
        int q = w * 32 + mb * 16 + (lane >> 2);
#pragma unroll
        for (int nt = 0; nt < 8; nt++) {
            int d = nt * 8 + (lane & 3) * 2;
            __half2 h0 = __floats2half2_rn(oacc[mb][nt][0] * is0[mb],
                                           oacc[mb][nt][1] * is0[mb]);
            __half2 h1 = __floats2half2_rn(oacc[mb][nt][2] * is1[mb],
                                           oacc[mb][nt][3] * is1[mb]);
            *(__half2*)(sQ + q * A_PAD + d) = h0;
            *(__half2*)(sQ + (q + 8) * A_PAD + d) = h1;
        }
    }
    __syncthreads();

    // write O transposed: aoh[(b*512 + (bh&7)*64 + d) * HW + p]
    size_t ob = ((size_t)(bh >> 3) * 512 + (size_t)(bh & 7) * 64) * HW + p0;
    for (int i = tid; i < 4096; i += 128) {
        int d = i >> 6, jj = i & 63;
        __half2 h = __halves2half2(sQ[(jj * 2) * A_PAD + d],
                                   sQ[(jj * 2 + 1) * A_PAD + d]);
        *(__half2*)(g_aoh + ob + (size_t)d * HW + jj * 2) = h;
    }
}

// ---------------- launch ----------------
extern "C" void kernel_launch(void* const* d_in, const int* in_sizes, int n_in,
                              void* d_out, int out_size) {
    (void)in_sizes; (void)n_in; (void)out_size;
    const float* context      = (const float*)d_in[0];
    const float* query_source = (const float*)d_in[1];
    const float* ctx_g = (const float*)d_in[2];
    const float* ctx_b = (const float*)d_in[3];
    const float* qs_g  = (const float*)d_in[4];
    const float* qs_b  = (const float*)d_in[5];
    const float* w_q   = (const float*)d_in[6];
    const float* w_kv  = (const float*)d_in[7];
    const float* w_out = (const float*)d_in[8];
    const float* gamma = (const float*)d_in[9];
    float* out = (float*)d_out;

    static bool inited = false;
    static float *p_qsn, *p_q, *p_kv, *p_qinv, *p_kinv;
    static __half *p_ctxh, *p_qsh, *p_aoh, *p_wq, *p_wkv, *p_wo;
    if (!inited) {
        cudaGetSymbolAddress((void**)&p_qsn,  g_qsn);
        cudaGetSymbolAddress((void**)&p_q,    g_q);
        cudaGetSymbolAddress((void**)&p_kv,   g_kv);
        cudaGetSymbolAddress((void**)&p_qinv, g_qinv);
        cudaGetSymbolAddress((void**)&p_kinv, g_kinv);
        cudaGetSymbolAddress((void**)&p_ctxh, g_ctxh);
        cudaGetSymbolAddress((void**)&p_qsh,  g_qsh);
        cudaGetSymbolAddress((void**)&p_aoh,  g_aoh);
        cudaGetSymbolAddress((void**)&p_wq,   g_wq);
        cudaGetSymbolAddress((void**)&p_wkv,  g_wkv);
        cudaGetSymbolAddress((void**)&p_wo,   g_wo);
        cudaFuncSetAttribute(mma_gemm_kernel,
                             cudaFuncAttributeMaxDynamicSharedMemorySize, GEMM_SMEM);
        inited = true;
    }

    // 1) fused channel layernorms -> fp16 (+ fp32 qsn for residual)
    fused_norm_kernel<<<1024, 256>>>(context, ctx_g, ctx_b, p_ctxh, nullptr);
    fused_norm_kernel<<<1024, 256>>>(query_source, qs_g, qs_b, p_qsh, p_qsn);

    // weight fp16 conversion
    wconv_kernel<<<1024, 256>>>(w_q,   p_wq,  512 * 512);
    wconv_kernel<<<2048, 256>>>(w_kv,  p_wkv, 1024 * 512);
    wconv_kernel<<<1024, 256>>>(w_out, p_wo,  512 * 512);

    // 2) projections (fp16 single-pass HMMA)
    mma_gemm_kernel<<<dim3(32, 8, 8), 256, GEMM_SMEM>>>(p_wkv, p_ctxh, p_kv, 1024,
                                                        nullptr, nullptr);
    mma_gemm_kernel<<<dim3(32, 4, 8), 256, GEMM_SMEM>>>(p_wq, p_qsh, p_q, 512,
                                                        nullptr, nullptr);

    // 3) inverse L2 norms
    inv_norm_kernel<<<1024, 256>>>(p_q,  p_qinv, (size_t)DIMC * HW);
    inv_norm_kernel<<<1024, 256>>>(p_kv, p_kinv, (size_t)2 * DIMC * HW);

    // 4) pruning statistics + selection + gather
    khw_kernel<<<4096, 128>>>();
    qprobe_kernel<<<4096, 256>>>();
    score_topk_kernel<<<64, 64>>>();
    gather_kernel<<<1024, 256>>>();

    // 5) MMA attention (emits fp16 [d][p] for out-proj)
    attn_kernel<<<dim3(32, 64), 128>>>();

    // 6) out projection + residual: out = gamma*W_out@ao + qs_norm
    mma_gemm_kernel<<<dim3(32, 4, 8), 256, GEMM_SMEM>>>(p_wo, p_aoh, out, 512,
                                                        gamma, p_qsn);
}

// round 7
// speedup vs baseline: 4.7211x; 1.0317x over previous
#include <cuda_runtime.h>
#include <cuda_fp16.h>
#include <math.h>
#include <stdint.h>

#define BATCH 8
#define DIMC  512
#define HW    4096
#define GH    64     // BATCH*HEADS
#define DH    64

// ---------------- scratch (device globals; allocation-free) ----------------
__device__ __align__(128) float  g_qsn[BATCH * DIMC * HW];     // normalized qs fp32 (residual)
__device__ __align__(128) __half g_qh [BATCH * DIMC * HW];     // q proj fp16
__device__ __align__(128) __half g_kvh[BATCH * 2 * DIMC * HW]; // kv proj fp16
__device__ __align__(128) __half g_ctxh[BATCH * DIMC * HW];    // normalized ctx fp16
__device__ __align__(128) __half g_qsh [BATCH * DIMC * HW];    // normalized qs fp16
__device__ __align__(128) __half g_aoh [BATCH * DIMC * HW];    // attention out fp16
__device__ __align__(128) __half g_wq [512 * 512];
__device__ __align__(128) __half g_wkv[1024 * 512];
__device__ __align__(128) __half g_wo [512 * 512];
__device__ float g_qinv[GH * HW];
__device__ float g_kinv[GH * HW];
__device__ float g_qprobe[GH * DH];
__device__ float g_kh[GH * DH * 64];
__device__ float g_kw[GH * DH * 64];
__device__ int   g_idxh[GH * 8];
__device__ int   g_idxw[GH * 8];
__device__ __half g_kT[GH * 64 * 64];   // [bh][d][j]  (normalized k, transposed)
__device__ __half g_vf[GH * 64 * 64];   // [bh][j][d]

// ================= warp-MMA helpers =================
__device__ __forceinline__ uint32_t smem_u32(const void* p) {
    uint32_t a;
    asm("{ .reg .u64 t; cvta.to.shared.u64 t, %1; cvt.u32.u64 %0, t; }" : "=r"(a) : "l"(p));
    return a;
}
__device__ __forceinline__ void cp16(uint32_t d, const void* s) {
    asm volatile("cp.async.cg.shared.global [%0], [%1], 16;" :: "r"(d), "l"(s));
}
__device__ __forceinline__ void ldsm4(uint32_t* r, uint32_t a) {
    asm volatile("ldmatrix.sync.aligned.m8n8.x4.shared.b16 {%0,%1,%2,%3}, [%4];"
                 : "=r"(r[0]), "=r"(r[1]), "=r"(r[2]), "=r"(r[3]) : "r"(a));
}
__device__ __forceinline__ void ldsm4t(uint32_t* r, uint32_t a) {
    asm volatile("ldmatrix.sync.aligned.m8n8.x4.trans.shared.b16 {%0,%1,%2,%3}, [%4];"
                 : "=r"(r[0]), "=r"(r[1]), "=r"(r[2]), "=r"(r[3]) : "r"(a));
}
__device__ __forceinline__ void mma16816(float* c, const uint32_t* a, const uint32_t* b) {
    asm volatile(
        "mma.sync.aligned.m16n8k16.row.col.f32.f16.f16.f32 "
        "{%0,%1,%2,%3}, {%4,%5,%6,%7}, {%8,%9}, {%0,%1,%2,%3};"
        : "+f"(c[0]), "+f"(c[1]), "+f"(c[2]), "+f"(c[3])
        : "r"(a[0]), "r"(a[1]), "r"(a[2]), "r"(a[3]), "r"(b[0]), "r"(b[1]));
}

// SMEM: A padded to 72 elems/row, B to 136 (conflict-free ldmatrix)
#define A_PAD 72
#define B_PAD 136
#define A_PL  (128 * A_PAD)              // 9216 elems
#define ST_ELEMS (A_PL + 64 * B_PAD)     // 17920 elems = 35840 B/stage
#define GEMM_SMEM (3 * ST_ELEMS * 2)     // 107520 B, 3 stages

// ======== GEMM: Y[b,m,n] = sum_k W[m,k]*X[b,k,n], fp16 in, fp32 acc ========
// Output: fp16 (Yh) when Yh != nullptr, else fp32 with gamma*acc + addend.
// grid (N/128, M/128, BATCH), 256 threads, 2 CTAs/SM.
__global__ void __launch_bounds__(256, 2)
mma_gemm_kernel(const __half* __restrict__ Wh, const __half* __restrict__ Xh,
                float* __restrict__ Y, __half* __restrict__ Yh, int M,
                const float* __restrict__ gammap, const float* __restrict__ addend) {
    extern __shared__ __half sm[];
    uint32_t sbase = smem_u32(sm);
    int tid = threadIdx.x;
    int lane = tid & 31, wid = tid >> 5;
    int b = blockIdx.z;
    int m0 = blockIdx.y * 128, n0 = blockIdx.x * 128;
    const __half* wsrc = Wh + (size_t)m0 * 512;
    const __half* xsrc = Xh + (size_t)b * DIMC * HW + n0;

    auto copy_chunk = [&](int c) {
        uint32_t sb = sbase + (uint32_t)(c % 3) * (ST_ELEMS * 2);
#pragma unroll
        for (int i = 0; i < 4; i++) {           // A: 128m x 64k
            int t = tid + i * 256;
            int m = t >> 3, j = t & 7;
            cp16(sb + (uint32_t)(m * A_PAD + j * 8) * 2,
                 wsrc + (size_t)m * 512 + c * 64 + j * 8);
        }
#pragma unroll
        for (int i = 0; i < 4; i++) {           // B: 64k x 128n
            int t = tid + i * 256;
            int k = t >> 4, j = t & 15;
            cp16(sb + (uint32_t)(A_PL + k * B_PAD + j * 8) * 2,
                 xsrc + (size_t)(c * 64 + k) * HW + j * 8);
        }
        asm volatile("cp.async.commit_group;" ::: "memory");
    };

    float acc[4][4][4] = {};
    int wm = (wid & 1) * 64;
    int wn = (wid >> 1) * 32;

    copy_chunk(0);
    copy_chunk(1);
    for (int c = 0; c < 8; c++) {
        if (c < 6) {
            copy_chunk(c + 2);
            asm volatile("cp.async.wait_group 2;" ::: "memory");
        } else if (c < 7) {
            asm volatile("cp.async.wait_group 1;" ::: "memory");
        } else {
            asm volatile("cp.async.wait_group 0;" ::: "memory");
        }
        __syncthreads();
        uint32_t sb = sbase + (uint32_t)(c % 3) * (ST_ELEMS * 2);
        uint32_t a_0 = sb + (uint32_t)((wm + (lane & 15)) * A_PAD + (lane >> 4) * 8) * 2;
        uint32_t b_0 = sb + (uint32_t)(A_PL + (lane & 15) * B_PAD + wn + (lane >> 4) * 8) * 2;
#pragma unroll
        for (int kk = 0; kk < 4; kk++) {
            uint32_t ah[4][4], bh[2][4];
#pragma unroll
            for (int mb = 0; mb < 4; mb++)
                ldsm4(ah[mb], a_0 + (uint32_t)(mb * 16 * A_PAD + kk * 16) * 2);
#pragma unroll
            for (int ng = 0; ng < 2; ng++)
                ldsm4t(bh[ng], b_0 + (uint32_t)(kk * 16 * B_PAD + ng * 16) * 2);
#pragma unroll
            for (int mb = 0; mb < 4; mb++)
#pragma unroll
                for (int nb = 0; nb < 4; nb++)
                    mma16816(acc[mb][nb], ah[mb], &bh[nb >> 1][(nb & 1) * 2]);
        }
        __syncthreads();
    }

    float ga = gammap ? gammap[0] : 1.0f;
    int g = lane >> 2, tig = lane & 3;
#pragma unroll
    for (int mb = 0; mb < 4; mb++) {
#pragma unroll
        for (int nb = 0; nb < 4; nb++) {
            int m = m0 + wm + mb * 16 + g;
            int n = n0 + wn + nb * 8 + tig * 2;
            size_t off0 = ((size_t)b * M + m) * HW + n;
            size_t off1 = off0 + (size_t)8 * HW;
            float* p = acc[mb][nb];
            if (Yh) {
                *(__half2*)(Yh + off0) = __floats2half2_rn(p[0], p[1]);
                *(__half2*)(Yh + off1) = __floats2half2_rn(p[2], p[3]);
            } else if (addend) {
                size_t a0 = ((size_t)b * 512 + m) * HW + n;
                float2 d0 = *(const float2*)(addend + a0);
                float2 d1 = *(const float2*)(addend + a0 + (size_t)8 * HW);
                *(float2*)(Y + off0) = make_float2(ga * p[0] + d0.x, ga * p[1] + d0.y);
                *(float2*)(Y + off1) = make_float2(ga * p[2] + d1.x, ga * p[3] + d1.y);
            } else {
                *(float2*)(Y + off0) = make_float2(p[0], p[1]);
                *(float2*)(Y + off1) = make_float2(p[2], p[3]);
            }
        }
    }
}

// ---------------- fused channel layernorm (stats + apply) ----------------
__global__ __launch_bounds__(256) void fused_norm_kernel(const float* __restrict__ in,
                                                         const float* __restrict__ gw,
                                                         const float* __restrict__ bw,
                                                         __half* __restrict__ oh,
                                                         float* __restrict__ of) {
    __shared__ float shs[8][32], shq[8][32];
    __shared__ float smean[32], srstd[32];
    int tid = threadIdx.x;
    int px = tid & 31, cg = tid >> 5;
    int pos = blockIdx.x * 32 + px;
    int b = pos >> 12, sp = pos & 4095;
    size_t base = (size_t)b * DIMC * HW + sp;
    int c0 = cg * 64;
    float v[64];
    float s = 0.f, q = 0.f;
#pragma unroll 8
    for (int c = 0; c < 64; c++) {
        float x = in[base + (size_t)(c0 + c) * HW];
        v[c] = x; s += x; q += x * x;
    }
    shs[cg][px] = s; shq[cg][px] = q;
    __syncthreads();
    if (cg == 0) {
        float ts = 0.f, tq = 0.f;
#pragma unroll
        for (int g = 0; g < 8; g++) { ts += shs[g][px]; tq += shq[g][px]; }
        float mean = ts * (1.0f / 512.0f);
        float var = tq * (1.0f / 512.0f) - mean * mean;
        smean[px] = mean;
        srstd[px] = rsqrtf(var + 1e-5f);
    }
    __syncthreads();
    float m = smean[px], r = srstd[px];
#pragma unroll 8
    for (int c = 0; c < 64; c++) {
        float y = (v[c] - m) * r * gw[c0 + c] + bw[c0 + c];
        size_t idx = base + (size_t)(c0 + c) * HW;
        oh[idx] = __float2half_rn(y);
        if (of) of[idx] = y;
    }
}

// ---------------- weight fp32 -> fp16 ----------------
__global__ __launch_bounds__(256) void wconv_kernel(const float* __restrict__ w,
                                                    __half* __restrict__ wh, int n) {
    int i = blockIdx.x * 256 + threadIdx.x;
    int i4 = i * 4;
    if (i4 < n) {
        float4 x = *(const float4*)(w + i4);
        __half2 h0 = __floats2half2_rn(x.x, x.y);
        __half2 h1 = __floats2half2_rn(x.z, x.w);
        *(__half2*)(wh + i4) = h0;
        *(__half2*)(wh + i4 + 2) = h1;
    }
}

// ---------------- per-position inverse L2 norm over 64 channels (fp16 in) ----------------
__global__ __launch_bounds__(256) void inv_norm_kernel(const __half* __restrict__ t,
                                                       float* __restrict__ inv,
                                                       size_t bstride) {
    int idx = blockIdx.x * 256 + threadIdx.x;   // GH*HW
    int g = idx >> 12, p = idx & 4095;
    size_t base = (size_t)(g >> 3) * bstride + (size_t)(g & 7) * (64 * HW) + p;
    float ss = 0.f;
#pragma unroll 8
    for (int d = 0; d < 64; d++) {
        float x = __half2float(t[base + (size_t)d * HW]);
        ss += x * x;
    }
    inv[idx] = 1.0f / fmaxf(sqrtf(ss), 1e-12f);
}

// ---------------- fused k abs-sums (height + width), normalized k (fp16 in) ----------------
__global__ __launch_bounds__(128) void khw_kernel() {
    __shared__ float pl[4096];
    int bh = blockIdx.x >> 6, c = blockIdx.x & 63;
    size_t base = (size_t)(bh >> 3) * (2 * DIMC * HW) + (size_t)(bh & 7) * (64 * HW)
                + (size_t)c * HW;
    const float* ki = g_kinv + bh * HW;
    int tid = threadIdx.x;
    for (int i = tid; i < 2048; i += 128) {
        __half2 h = *(const __half2*)(g_kvh + base + 2 * i);
        float2 kv2 = __half22float2(h);
        float2 ki2 = *(const float2*)(ki + 2 * i);
        pl[2 * i]     = fabsf(kv2.x) * ki2.x;
        pl[2 * i + 1] = fabsf(kv2.y) * ki2.y;
    }
    __syncthreads();
    if (tid < 64) {
        int h = tid;
        float s = 0.f;
#pragma unroll 8
        for (int w = 0; w < 64; w++) s += pl[h * 64 + ((w + h) & 63)];
        g_kh[bh * 4096 + c * 64 + h] = s;
    } else {
        int w = tid - 64;
        float s = 0.f;
#pragma unroll 8
        for (int h = 0; h < 64; h++) s += pl[h * 64 + w];
        g_kw[bh * 4096 + c * 64 + w] = s;
    }
}

// ---------------- q abs-sum over spatial (normalized q, fp16 in) ----------------
__global__ __launch_bounds__(256) void qprobe_kernel() {
    int bid = blockIdx.x;          // bh*64 + c
    int g = bid >> 6;
    const __half2* p2 = (const __half2*)(g_qh + (size_t)bid * HW);
    const float2* iv2 = (const float2*)(g_qinv + (size_t)g * HW);
    float s = 0.f;
    for (int i = threadIdx.x; i < 2048; i += 256) {
        float2 v = __half22float2(p2[i]);
        float2 iv = iv2[i];
        s += fabsf(v.x) * iv.x + fabsf(v.y) * iv.y;
    }
    __shared__ float sh[256];
    sh[threadIdx.x] = s;
    __syncthreads();
    for (int st = 128; st > 0; st >>= 1) {
        if (threadIdx.x < st) sh[threadIdx.x] += sh[threadIdx.x + st];
        __syncthreads();
    }
    if (threadIdx.x == 0) g_qprobe[bid] = sh[0];
}

// ---------------- scores + top-8 selection ----------------
__global__ __launch_bounds__(64) void score_topk_kernel() {
    int bh = blockIdx.x;
    int h = threadIdx.x;
    __shared__ float sr[64], sc[64];
    float a = 0.f, bb = 0.f;
    for (int c = 0; c < 64; c++) {
        float qp = g_qprobe[bh * 64 + c];
        a  += qp * g_kh[bh * 4096 + c * 64 + h];
        bb += qp * g_kw[bh * 4096 + c * 64 + h];
    }
    sr[h] = a; sc[h] = bb;
    __syncthreads();
    if (h == 0) {
        for (int i = 0; i < 8; i++) {
            float best = -INFINITY; int bi = 0;
            for (int j = 0; j < 64; j++) if (sr[j] > best) { best = sr[j]; bi = j; }
            g_idxh[bh * 8 + i] = bi;
            sr[bi] = -INFINITY;
        }
    } else if (h == 1) {
        for (int i = 0; i < 8; i++) {
            float best = -INFINITY; int bi = 0;
            for (int j = 0; j < 64; j++) if (sc[j] > best) { best = sc[j]; bi = j; }
            g_idxw[bh * 8 + i] = bi;
            sc[bi] = -INFINITY;
        }
    }
}

// ---------------- gather pruned k/v -> fp16 tiles for MMA attention ----------------
__global__ __launch_bounds__(256) void gather_kernel() {
    int idx = blockIdx.x * 256 + threadIdx.x;   // 262144
    int bh = idx >> 12, r = (idx >> 6) & 63, cc = idx & 63;
    size_t base = (size_t)(bh >> 3) * (2 * DIMC * HW) + (size_t)(bh & 7) * (64 * HW);
    {   // kT: row d=r, col j=cc (normalized)
        int hh = g_idxh[bh * 8 + (cc >> 3)];
        int ww = g_idxw[bh * 8 + (cc & 7)];
        int p = hh * 64 + ww;
        float k = __half2float(g_kvh[base + (size_t)r * HW + p]) * g_kinv[bh * HW + p];
        g_kT[idx] = __float2half_rn(k);
    }
    {   // vf: row j=r, col d=cc (plain copy)
        int hh = g_idxh[bh * 8 + (r >> 3)];
        int ww = g_idxw[bh * 8 + (r & 7)];
        int p = hh * 64 + ww;
        g_vf[idx] = g_kvh[base + (size_t)DIMC * HW + (size_t)cc * HW + p];
    }
}

// ---------------- MMA attention: per (bh, 128-query tile) ----------------
__global__ __launch_bounds__(128) void attn_kernel() {
    __shared__ __half sQ[128 * A_PAD];   // [p][d]; reused for O staging [q][d]
    __shared__ __half sK[64 * A_PAD];    // [d][j]
    __shared__ __half sV[64 * A_PAD];    // [j][d]
    int tid = threadIdx.x, lane = tid & 31, w = tid >> 5;
    int p0 = blockIdx.x * 128, bh = blockIdx.y;
    uint32_t sQa = smem_u32(sQ), sKa = smem_u32(sK), sVa = smem_u32(sV);

    const __half* kt = g_kT + bh * 4096;
    const __half* vf = g_vf + bh * 4096;
#pragma unroll
    for (int i = 0; i < 4; i++) {
        int t = tid + i * 128;
        int r = t >> 3, j = t & 7;
        cp16(sKa + (uint32_t)(r * A_PAD + j * 8) * 2, kt + r * 64 + j * 8);
        cp16(sVa + (uint32_t)(r * A_PAD + j * 8) * 2, vf + r * 64 + j * 8);
    }
    asm volatile("cp.async.commit_group;" ::: "memory");

    // Q: fp16 * qinv -> fp16 smem [p][d]
    const __half* qp = g_qh + (size_t)bh * 64 * HW + p0;
    const float* qi = g_qinv + bh * HW + p0;
#pragma unroll
    for (int i = 0; i < 32; i++) {
        int t = tid + i * 128;          // 4096 half2 units
        int d2 = t >> 7, p = t & 127;
        float iv = qi[p];
        __half2 h = __floats2half2_rn(__half2float(qp[(size_t)(2 * d2) * HW + p]) * iv,
                                      __half2float(qp[(size_t)(2 * d2 + 1) * HW + p]) * iv);
        *(__half2*)(sQ + p * A_PAD + 2 * d2) = h;
    }
    asm volatile("cp.async.wait_group 0;" ::: "memory");
    __syncthreads();

    // S = Q*K^T
    float sacc[2][8][4] = {};
#pragma unroll
    for (int kk = 0; kk < 4; kk++) {
        uint32_t a[2][4], bk[4][4];
#pragma unroll
        for (int mb = 0; mb < 2; mb++)
            ldsm4(a[mb], sQa + (uint32_t)((w * 32 + mb * 16 + (lane & 15)) * A_PAD
                                          + kk * 16 + (lane >> 4) * 8) * 2);
#pragma unroll
        for (int nt2 = 0; nt2 < 4; nt2++)
            ldsm4t(bk[nt2], sKa + (uint32_t)((kk * 16 + (lane & 15)) * A_PAD
                                             + nt2 * 16 + (lane >> 4) * 8) * 2);
#pragma unroll
        for (int mb = 0; mb < 2; mb++)
#pragma unroll
            for (int nt = 0; nt < 8; nt++)
                mma16816(sacc[mb][nt], a[mb], &bk[nt >> 1][(nt & 1) * 2]);
    }

    // softmax per row
    float is0[2], is1[2];
#pragma unroll
    for (int mb = 0; mb < 2; mb++) {
        float mx0 = -INFINITY, mx1 = -INFINITY;
#pragma unroll
        for (int nt = 0; nt < 8; nt++) {
            mx0 = fmaxf(mx0, fmaxf(sacc[mb][nt][0], sacc[mb][nt][1]));
            mx1 = fmaxf(mx1, fmaxf(sacc[mb][nt][2], sacc[mb][nt][3]));
        }
        mx0 = fmaxf(mx0, __shfl_xor_sync(0xffffffff, mx0, 1));
        mx0 = fmaxf(mx0, __shfl_xor_sync(0xffffffff, mx0, 2));
        mx1 = fmaxf(mx1, __shfl_xor_sync(0xffffffff, mx1, 1));
        mx1 = fmaxf(mx1, __shfl_xor_sync(0xffffffff, mx1, 2));
        float s0 = 0.f, s1 = 0.f;
#pragma unroll
        for (int nt = 0; nt < 8; nt++) {
            sacc[mb][nt][0] = expf(sacc[mb][nt][0] - mx0);
            sacc[mb][nt][1] = expf(sacc[mb][nt][1] - mx0);
            sacc[mb][nt][2] = expf(sacc[mb][nt][2] - mx1);
            sacc[mb][nt][3] = expf(sacc[mb][nt][3] - mx1);
            s0 += sacc[mb][nt][0] + sacc[mb][nt][1];
            s1 += sacc[mb][nt][2] + sacc[mb][nt][3];
        }
        s0 += __shfl_xor_sync(0xffffffff, s0, 1);
        s0 += __shfl_xor_sync(0xffffffff, s0, 2);
        s1 += __shfl_xor_sync(0xffffffff, s1, 1);
        s1 += __shfl_xor_sync(0xffffffff, s1, 2);
        is0[mb] = 1.0f / s0;
        is1[mb] = 1.0f / s1;
    }

    // P a-frags from acc frags
    uint32_t pa[2][4][4];
#pragma unroll
    for (int mb = 0; mb < 2; mb++)
#pragma unroll
        for (int u = 0; u < 4; u++) {
            __half2 h0 = __floats2half2_rn(sacc[mb][2*u][0],   sacc[mb][2*u][1]);
            __half2 h1 = __floats2half2_rn(sacc[mb][2*u][2],   sacc[mb][2*u][3]);
            __half2 h2 = __floats2half2_rn(sacc[mb][2*u+1][0], sacc[mb][2*u+1][1]);
            __half2 h3 = __floats2half2_rn(sacc[mb][2*u+1][2], sacc[mb][2*u+1][3]);
            pa[mb][u][0] = *(uint32_t*)&h0;
            pa[mb][u][1] = *(uint32_t*)&h1;
            pa[mb][u][2] = *(uint32_t*)&h2;
            pa[mb][u][3] = *(uint32_t*)&h3;
        }

    // O = P*V
    float oacc[2][8][4] = {};
#pragma unroll
    for (int u = 0; u < 4; u++) {
        uint32_t bv[4][4];
#pragma unroll
        for (int nt2 = 0; nt2 < 4; nt2++)
            ldsm4t(bv[nt2], sVa + (uint32_t)((u * 16 + (lane & 15)) * A_PAD
                                             + nt2 * 16 + (lane >> 4) * 8) * 2);
#pragma unroll
        for (int mb = 0; mb < 2; mb++)
#pragma unroll
            for (int nt = 0; nt < 8; nt++)
                mma16816(oacc[mb][nt], pa[mb][u], &bv[nt >> 1][(nt & 1) * 2]);
    }

    __syncthreads();
#pragma unroll
    for (int mb = 0; mb < 2; mb++) {
        int q = w * 32 + mb * 16 + (lane >> 2);
#pragma unroll
        for (int nt = 0; nt < 8; nt++) {
            int d = nt * 8 + (lane & 3) * 2;
            __half2 h0 = __floats2half2_rn(oacc[mb][nt][0] * is0[mb],
                                           oacc[mb][nt][1] * is0[mb]);
            __half2 h1 = __floats2half2_rn(oacc[mb][nt][2] * is1[mb],
                                           oacc[mb][nt][3] * is1[mb]);
            *(__half2*)(sQ + q * A_PAD + d) = h0;
            *(__half2*)(sQ + (q + 8) * A_PAD + d) = h1;
        }
    }
    __syncthreads();

    size_t ob = ((size_t)(bh >> 3) * 512 + (size_t)(bh & 7) * 64) * HW + p0;
    for (int i = tid; i < 4096; i += 128) {
        int d = i >> 6, jj = i & 63;
        __half2 h = __halves2half2(sQ[(jj * 2) * A_PAD + d],
                                   sQ[(jj * 2 + 1) * A_PAD + d]);
        *(__half2*)(g_aoh + ob + (size_t)d * HW + jj * 2) = h;
    }
}

// ---------------- launch ----------------
extern "C" void kernel_launch(void* const* d_in, const int* in_sizes, int n_in,
                              void* d_out, int out_size) {
    (void)in_sizes; (void)n_in; (void)out_size;
    const float* context      = (const float*)d_in[0];
    const float* query_source = (const float*)d_in[1];
    const float* ctx_g = (const float*)d_in[2];
    const float* ctx_b = (const float*)d_in[3];
    const float* qs_g  = (const float*)d_in[4];
    const float* qs_b  = (const float*)d_in[5];
    const float* w_q   = (const float*)d_in[6];
    const float* w_kv  = (const float*)d_in[7];
    const float* w_out = (const float*)d_in[8];
    const float* gamma = (const float*)d_in[9];
    float* out = (float*)d_out;

    static bool inited = false;
    static float *p_qsn, *p_qinv, *p_kinv;
    static __half *p_qh, *p_kvh, *p_ctxh, *p_qsh, *p_aoh, *p_wq, *p_wkv, *p_wo;
    if (!inited) {
        cudaGetSymbolAddress((void**)&p_qsn,  g_qsn);
        cudaGetSymbolAddress((void**)&p_qh,   g_qh);
        cudaGetSymbolAddress((void**)&p_kvh,  g_kvh);
        cudaGetSymbolAddress((void**)&p_qinv, g_qinv);
        cudaGetSymbolAddress((void**)&p_kinv, g_kinv);
        cudaGetSymbolAddress((void**)&p_ctxh, g_ctxh);
        cudaGetSymbolAddress((void**)&p_qsh,  g_qsh);
        cudaGetSymbolAddress((void**)&p_aoh,  g_aoh);
        cudaGetSymbolAddress((void**)&p_wq,   g_wq);
        cudaGetSymbolAddress((void**)&p_wkv,  g_wkv);
        cudaGetSymbolAddress((void**)&p_wo,   g_wo);
        cudaFuncSetAttribute(mma_gemm_kernel,
                             cudaFuncAttributeMaxDynamicSharedMemorySize, GEMM_SMEM);
        inited = true;
    }

    // 1) fused channel layernorms -> fp16 (+ fp32 qsn for residual)
    fused_norm_kernel<<<1024, 256>>>(context, ctx_g, ctx_b, p_ctxh, nullptr);
    fused_norm_kernel<<<1024, 256>>>(query_source, qs_g, qs_b, p_qsh, p_qsn);

    // weight fp16 conversion
    wconv_kernel<<<256, 256>>>(w_q,   p_wq,  512 * 512);
    wconv_kernel<<<512, 256>>>(w_kv,  p_wkv, 1024 * 512);
    wconv_kernel<<<256, 256>>>(w_out, p_wo,  512 * 512);

    // 2) projections (fp16 HMMA, fp16 out)
    mma_gemm_kernel<<<dim3(32, 8, 8), 256, GEMM_SMEM>>>(p_wkv, p_ctxh, nullptr, p_kvh,
                                                        1024, nullptr, nullptr);
    mma_gemm_kernel<<<dim3(32, 4, 8), 256, GEMM_SMEM>>>(p_wq, p_qsh, nullptr, p_qh,
                                                        512, nullptr, nullptr);

    // 3) inverse L2 norms
    inv_norm_kernel<<<1024, 256>>>(p_qh,  p_qinv, (size_t)DIMC * HW);
    inv_norm_kernel<<<1024, 256>>>(p_kvh, p_kinv, (size_t)2 * DIMC * HW);

    // 4) pruning statistics + selection + gather
    khw_kernel<<<4096, 128>>>();
    qprobe_kernel<<<4096, 256>>>();
    score_topk_kernel<<<64, 64>>>();
    gather_kernel<<<1024, 256>>>();

    // 5) MMA attention (emits fp16 [d][p] for out-proj)
    attn_kernel<<<dim3(32, 64), 128>>>();

    // 6) out projection + residual: out = gamma*W_out@ao + qs_norm (fp32)
    mma_gemm_kernel<<<dim3(32, 4, 8), 256, GEMM_SMEM>>>(p_wo, p_aoh, out, nullptr,
                                                        512, gamma, p_qsn);
}

// round 8
// speedup vs baseline: 4.8137x; 1.0196x over previous
#include <cuda_runtime.h>
#include <cuda_fp16.h>
#include <math.h>
#include <stdint.h>

#define BATCH 8
#define DIMC  512
#define HW    4096
#define GH    64     // BATCH*HEADS
#define DH    64

// ---------------- scratch (device globals; allocation-free) ----------------
__device__ __align__(128) float  g_qsn[BATCH * DIMC * HW];     // normalized qs fp32 (residual)
__device__ __align__(128) __half g_qh [BATCH * DIMC * HW];     // q proj fp16
__device__ __align__(128) __half g_kvh[BATCH * 2 * DIMC * HW]; // kv proj fp16
__device__ __align__(128) __half g_ctxh[BATCH * DIMC * HW];    // normalized ctx fp16
__device__ __align__(128) __half g_qsh [BATCH * DIMC * HW];    // normalized qs fp16
__device__ __align__(128) __half g_aoh [BATCH * DIMC * HW];    // attention out fp16
__device__ __align__(128) __half g_wq [512 * 512];
__device__ __align__(128) __half g_wkv[1024 * 512];
__device__ __align__(128) __half g_wo [512 * 512];
__device__ float g_qinv[GH * HW];
__device__ float g_kinv[GH * HW];
__device__ float g_qprobe[GH * DH];
__device__ float g_kh[GH * DH * 64];
__device__ float g_kw[GH * DH * 64];
__device__ int   g_idxh[GH * 8];
__device__ int   g_idxw[GH * 8];
__device__ __half g_kT[GH * 64 * 64];   // [bh][d][j]  (normalized k, transposed)
__device__ __half g_vf[GH * 64 * 64];   // [bh][j][d]

// ================= warp-MMA helpers =================
__device__ __forceinline__ uint32_t smem_u32(const void* p) {
    uint32_t a;
    asm("{ .reg .u64 t; cvta.to.shared.u64 t, %1; cvt.u32.u64 %0, t; }" : "=r"(a) : "l"(p));
    return a;
}
__device__ __forceinline__ void cp16(uint32_t d, const void* s) {
    asm volatile("cp.async.cg.shared.global [%0], [%1], 16;" :: "r"(d), "l"(s));
}
__device__ __forceinline__ void ldsm4(uint32_t* r, uint32_t a) {
    asm volatile("ldmatrix.sync.aligned.m8n8.x4.shared.b16 {%0,%1,%2,%3}, [%4];"
                 : "=r"(r[0]), "=r"(r[1]), "=r"(r[2]), "=r"(r[3]) : "r"(a));
}
__device__ __forceinline__ void ldsm4t(uint32_t* r, uint32_t a) {
    asm volatile("ldmatrix.sync.aligned.m8n8.x4.trans.shared.b16 {%0,%1,%2,%3}, [%4];"
                 : "=r"(r[0]), "=r"(r[1]), "=r"(r[2]), "=r"(r[3]) : "r"(a));
}
__device__ __forceinline__ void mma16816(float* c, const uint32_t* a, const uint32_t* b) {
    asm volatile(
        "mma.sync.aligned.m16n8k16.row.col.f32.f16.f16.f32 "
        "{%0,%1,%2,%3}, {%4,%5,%6,%7}, {%8,%9}, {%0,%1,%2,%3};"
        : "+f"(c[0]), "+f"(c[1]), "+f"(c[2]), "+f"(c[3])
        : "r"(a[0]), "r"(a[1]), "r"(a[2]), "r"(a[3]), "r"(b[0]), "r"(b[1]));
}

// SMEM: A padded to 72 elems/row, B to 136 (conflict-free ldmatrix)
#define A_PAD 72
#define B_PAD 136
#define A_PL  (128 * A_PAD)              // 9216 elems
#define ST_ELEMS (A_PL + 64 * B_PAD)     // 17920 elems = 35840 B/stage
#define GEMM_SMEM (3 * ST_ELEMS * 2)     // 107520 B, 3 stages

// ======== GEMM: Y[b,m,n] = sum_k W[m,k]*X[b,k,n], fp16 in, fp32 acc ========
// 128x128 CTA tile, 4 warps of 64x64, 3-stage cp.async, 2 CTAs/SM.
__global__ void __launch_bounds__(128, 2)
mma_gemm_kernel(const __half* __restrict__ Wh, const __half* __restrict__ Xh,
                float* __restrict__ Y, __half* __restrict__ Yh, int M,
                const float* __restrict__ gammap, const float* __restrict__ addend) {
    extern __shared__ __half sm[];
    uint32_t sbase = smem_u32(sm);
    int tid = threadIdx.x;
    int lane = tid & 31, wid = tid >> 5;
    int b = blockIdx.z;
    int m0 = blockIdx.y * 128, n0 = blockIdx.x * 128;
    const __half* wsrc = Wh + (size_t)m0 * 512;
    const __half* xsrc = Xh + (size_t)b * DIMC * HW + n0;

    auto copy_chunk = [&](int c) {
        uint32_t sb = sbase + (uint32_t)(c % 3) * (ST_ELEMS * 2);
#pragma unroll
        for (int i = 0; i < 8; i++) {           // A: 128m x 64k
            int t = tid + i * 128;
            int m = t >> 3, j = t & 7;
            cp16(sb + (uint32_t)(m * A_PAD + j * 8) * 2,
                 wsrc + (size_t)m * 512 + c * 64 + j * 8);
        }
#pragma unroll
        for (int i = 0; i < 8; i++) {           // B: 64k x 128n
            int t = tid + i * 128;
            int k = t >> 4, j = t & 15;
            cp16(sb + (uint32_t)(A_PL + k * B_PAD + j * 8) * 2,
                 xsrc + (size_t)(c * 64 + k) * HW + j * 8);
        }
        asm volatile("cp.async.commit_group;" ::: "memory");
    };

    float acc[4][8][4] = {};
    int wm = (wid & 1) * 64;     // warp m-offset
    int wn = (wid >> 1) * 64;    // warp n-offset

    copy_chunk(0);
    copy_chunk(1);
    for (int c = 0; c < 8; c++) {
        if (c < 7) {
            asm volatile("cp.async.wait_group 1;" ::: "memory");
        } else {
            asm volatile("cp.async.wait_group 0;" ::: "memory");
        }
        __syncthreads();        // data for chunk c visible; all warps done reading stage (c-1)%3
        if (c < 6) copy_chunk(c + 2);   // overwrites stage (c-1)%3 — safe after the sync

        uint32_t sb = sbase + (uint32_t)(c % 3) * (ST_ELEMS * 2);
        uint32_t a_0 = sb + (uint32_t)((wm + (lane & 15)) * A_PAD + (lane >> 4) * 8) * 2;
        uint32_t b_0 = sb + (uint32_t)(A_PL + (lane & 15) * B_PAD + wn + (lane >> 4) * 8) * 2;
#pragma unroll
        for (int kk = 0; kk < 4; kk++) {
            uint32_t ah[4][4], bh[4][4];
#pragma unroll
            for (int mb = 0; mb < 4; mb++)
                ldsm4(ah[mb], a_0 + (uint32_t)(mb * 16 * A_PAD + kk * 16) * 2);
#pragma unroll
            for (int nt2 = 0; nt2 < 4; nt2++)
                ldsm4t(bh[nt2], b_0 + (uint32_t)(kk * 16 * B_PAD + nt2 * 16) * 2);
#pragma unroll
            for (int mb = 0; mb < 4; mb++)
#pragma unroll
                for (int nb = 0; nb < 8; nb++)
                    mma16816(acc[mb][nb], ah[mb], &bh[nb >> 1][(nb & 1) * 2]);
        }
    }

    float ga = gammap ? gammap[0] : 1.0f;
    int g = lane >> 2, tig = lane & 3;
#pragma unroll
    for (int mb = 0; mb < 4; mb++) {
#pragma unroll
        for (int nb = 0; nb < 8; nb++) {
            int m = m0 + wm + mb * 16 + g;
            int n = n0 + wn + nb * 8 + tig * 2;
            size_t off0 = ((size_t)b * M + m) * HW + n;
            size_t off1 = off0 + (size_t)8 * HW;
            float* p = acc[mb][nb];
            if (Yh) {
                *(__half2*)(Yh + off0) = __floats2half2_rn(p[0], p[1]);
                *(__half2*)(Yh + off1) = __floats2half2_rn(p[2], p[3]);
            } else if (addend) {
                size_t a0 = ((size_t)b * 512 + m) * HW + n;
                float2 d0 = *(const float2*)(addend + a0);
                float2 d1 = *(const float2*)(addend + a0 + (size_t)8 * HW);
                *(float2*)(Y + off0) = make_float2(ga * p[0] + d0.x, ga * p[1] + d0.y);
                *(float2*)(Y + off1) = make_float2(ga * p[2] + d1.x, ga * p[3] + d1.y);
            } else {
                *(float2*)(Y + off0) = make_float2(p[0], p[1]);
                *(float2*)(Y + off1) = make_float2(p[2], p[3]);
            }
        }
    }
}

// ---------------- fused channel layernorm (both tensors, one launch) ----------------
__global__ __launch_bounds__(256) void fused_norm_kernel(const float* __restrict__ in0,
                                                         const float* __restrict__ gw0,
                                                         const float* __restrict__ bw0,
                                                         __half* __restrict__ oh0,
                                                         const float* __restrict__ in1,
                                                         const float* __restrict__ gw1,
                                                         const float* __restrict__ bw1,
                                                         __half* __restrict__ oh1,
                                                         float* __restrict__ of1) {
    __shared__ float shs[8][32], shq[8][32];
    __shared__ float smean[32], srstd[32];
    int half2nd = blockIdx.x >> 10;
    const float* in = half2nd ? in1 : in0;
    const float* gw = half2nd ? gw1 : gw0;
    const float* bw = half2nd ? bw1 : bw0;
    __half* oh = half2nd ? oh1 : oh0;
    float* of = half2nd ? of1 : nullptr;
    int tid = threadIdx.x;
    int px = tid & 31, cg = tid >> 5;
    int pos = (blockIdx.x & 1023) * 32 + px;
    int b = pos >> 12, sp = pos & 4095;
    size_t base = (size_t)b * DIMC * HW + sp;
    int c0 = cg * 64;
    float v[64];
    float s = 0.f, q = 0.f;
#pragma unroll 8
    for (int c = 0; c < 64; c++) {
        float x = in[base + (size_t)(c0 + c) * HW];
        v[c] = x; s += x; q += x * x;
    }
    shs[cg][px] = s; shq[cg][px] = q;
    __syncthreads();
    if (cg == 0) {
        float ts = 0.f, tq = 0.f;
#pragma unroll
        for (int g = 0; g < 8; g++) { ts += shs[g][px]; tq += shq[g][px]; }
        float mean = ts * (1.0f / 512.0f);
        float var = tq * (1.0f / 512.0f) - mean * mean;
        smean[px] = mean;
        srstd[px] = rsqrtf(var + 1e-5f);
    }
    __syncthreads();
    float m = smean[px], r = srstd[px];
#pragma unroll 8
    for (int c = 0; c < 64; c++) {
        float y = (v[c] - m) * r * gw[c0 + c] + bw[c0 + c];
        size_t idx = base + (size_t)(c0 + c) * HW;
        oh[idx] = __float2half_rn(y);
        if (of) of[idx] = y;
    }
}

// ---------------- all weights fp32 -> fp16, one launch ----------------
__global__ __launch_bounds__(256) void wconv_kernel(const float* __restrict__ wq,
                                                    const float* __restrict__ wkv,
                                                    const float* __restrict__ wo) {
    int i4 = (blockIdx.x * 256 + threadIdx.x) * 4;     // over 1,048,576 elems
    const float* src;
    __half* dst;
    int off;
    if (i4 < 262144)       { src = wq;  dst = g_wq;  off = i4; }
    else if (i4 < 786432)  { src = wkv; dst = g_wkv; off = i4 - 262144; }
    else                   { src = wo;  dst = g_wo;  off = i4 - 786432; }
    float4 x = *(const float4*)(src + off);
    *(__half2*)(dst + off)     = __floats2half2_rn(x.x, x.y);
    *(__half2*)(dst + off + 2) = __floats2half2_rn(x.z, x.w);
}

// ---------------- inverse L2 norms for q and k, one launch ----------------
__global__ __launch_bounds__(256) void inv_norm_kernel() {
    int gidx = blockIdx.x * 256 + threadIdx.x;    // 2*GH*HW
    int qk = gidx >> 18;                          // 0: q, 1: k
    int idx = gidx & 262143;
    int g = idx >> 12, p = idx & 4095;
    const __half* t;
    size_t base;
    if (qk == 0) {
        base = (size_t)(g >> 3) * (DIMC * HW) + (size_t)(g & 7) * (64 * HW) + p;
        t = g_qh;
    } else {
        base = (size_t)(g >> 3) * (2 * DIMC * HW) + (size_t)(g & 7) * (64 * HW) + p;
        t = g_kvh;
    }
    float ss = 0.f;
#pragma unroll 8
    for (int d = 0; d < 64; d++) {
        float x = __half2float(t[base + (size_t)d * HW]);
        ss += x * x;
    }
    float r = 1.0f / fmaxf(sqrtf(ss), 1e-12f);
    if (qk == 0) g_qinv[idx] = r; else g_kinv[idx] = r;
}

// ---------------- fused k abs-sums (height + width), normalized k ----------------
__global__ __launch_bounds__(128) void khw_kernel() {
    __shared__ float pl[4096];
    int bh = blockIdx.x >> 6, c = blockIdx.x & 63;
    size_t base = (size_t)(bh >> 3) * (2 * DIMC * HW) + (size_t)(bh & 7) * (64 * HW)
                + (size_t)c * HW;
    const float* ki = g_kinv + bh * HW;
    int tid = threadIdx.x;
    for (int i = tid; i < 2048; i += 128) {
        __half2 h = *(const __half2*)(g_kvh + base + 2 * i);
        float2 kv2 = __half22float2(h);
        float2 ki2 = *(const float2*)(ki + 2 * i);
        pl[2 * i]     = fabsf(kv2.x) * ki2.x;
        pl[2 * i + 1] = fabsf(kv2.y) * ki2.y;
    }
    __syncthreads();
    if (tid < 64) {
        int h = tid;
        float s = 0.f;
#pragma unroll 8
        for (int w = 0; w < 64; w++) s += pl[h * 64 + ((w + h) & 63)];
        g_kh[bh * 4096 + c * 64 + h] = s;
    } else {
        int w = tid - 64;
        float s = 0.f;
#pragma unroll 8
        for (int h = 0; h < 64; h++) s += pl[h * 64 + w];
        g_kw[bh * 4096 + c * 64 + w] = s;
    }
}

// ---------------- q abs-sum over spatial (normalized q) ----------------
__global__ __launch_bounds__(256) void qprobe_kernel() {
    int bid = blockIdx.x;          // bh*64 + c
    int g = bid >> 6;
    const __half2* p2 = (const __half2*)(g_qh + (size_t)bid * HW);
    const float2* iv2 = (const float2*)(g_qinv + (size_t)g * HW);
    float s = 0.f;
    for (int i = threadIdx.x; i < 2048; i += 256) {
        float2 v = __half22float2(p2[i]);
        float2 iv = iv2[i];
        s += fabsf(v.x) * iv.x + fabsf(v.y) * iv.y;
    }
    __shared__ float sh[256];
    sh[threadIdx.x] = s;
    __syncthreads();
    for (int st = 128; st > 0; st >>= 1) {
        if (threadIdx.x < st) sh[threadIdx.x] += sh[threadIdx.x + st];
        __syncthreads();
    }
    if (threadIdx.x == 0) g_qprobe[bid] = sh[0];
}

// ---------------- scores + top-8 selection ----------------
__global__ __launch_bounds__(64) void score_topk_kernel() {
    int bh = blockIdx.x;
    int h = threadIdx.x;
    __shared__ float sr[64], sc[64];
    float a = 0.f, bb = 0.f;
    for (int c = 0; c < 64; c++) {
        float qp = g_qprobe[bh * 64 + c];
        a  += qp * g_kh[bh * 4096 + c * 64 + h];
        bb += qp * g_kw[bh * 4096 + c * 64 + h];
    }
    sr[h] = a; sc[h] = bb;
    __syncthreads();
    if (h == 0) {
        for (int i = 0; i < 8; i++) {
            float best = -INFINITY; int bi = 0;
            for (int j = 0; j < 64; j++) if (sr[j] > best) { best = sr[j]; bi = j; }
            g_idxh[bh * 8 + i] = bi;
            sr[bi] = -INFINITY;
        }
    } else if (h == 1) {
        for (int i = 0; i < 8; i++) {
            float best = -INFINITY; int bi = 0;
            for (int j = 0; j < 64; j++) if (sc[j] > best) { best = sc[j]; bi = j; }
            g_idxw[bh * 8 + i] = bi;
            sc[bi] = -INFINITY;
        }
    }
}

// ---------------- gather pruned k/v -> fp16 tiles for MMA attention ----------------
__global__ __launch_bounds__(256) void gather_kernel() {
    int idx = blockIdx.x * 256 + threadIdx.x;   // 262144
    int bh = idx >> 12, r = (idx >> 6) & 63, cc = idx & 63;
    size_t base = (size_t)(bh >> 3) * (2 * DIMC * HW) + (size_t)(bh & 7) * (64 * HW);
    {   // kT: row d=r, col j=cc (normalized)
        int hh = g_idxh[bh * 8 + (cc >> 3)];
        int ww = g_idxw[bh * 8 + (cc & 7)];
        int p = hh * 64 + ww;
        float k = __half2float(g_kvh[base + (size_t)r * HW + p]) * g_kinv[bh * HW + p];
        g_kT[idx] = __float2half_rn(k);
    }
    {   // vf: row j=r, col d=cc (plain copy)
        int hh = g_idxh[bh * 8 + (r >> 3)];
        int ww = g_idxw[bh * 8 + (r & 7)];
        int p = hh * 64 + ww;
        g_vf[idx] = g_kvh[base + (size_t)DIMC * HW + (size_t)cc * HW + p];
    }
}

// ---------------- MMA attention: per (bh, 128-query tile) ----------------
__global__ __launch_bounds__(128) void attn_kernel() {
    __shared__ __half sQ[128 * A_PAD];   // [p][d]; reused for O staging [q][d]
    __shared__ __half sK[64 * A_PAD];    // [d][j]
    __shared__ __half sV[64 * A_PAD];    // [j][d]
    int tid = threadIdx.x, lane = tid & 31, w = tid >> 5;
    int p0 = blockIdx.x * 128, bh = blockIdx.y;
    uint32_t sQa = smem_u32(sQ), sKa = smem_u32(sK), sVa = smem_u32(sV);

    const __half* kt = g_kT + bh * 4096;
    const __half* vf = g_vf + bh * 4096;
#pragma unroll
    for (int i = 0; i < 4; i++) {
        int t = tid + i * 128;
        int r = t >> 3, j = t & 7;
        cp16(sKa + (uint32_t)(r * A_PAD + j * 8) * 2, kt + r * 64 + j * 8);
        cp16(sVa + (uint32_t)(r * A_PAD + j * 8) * 2, vf + r * 64 + j * 8);
    }
    asm volatile("cp.async.commit_group;" ::: "memory");

    // Q: fp16 * qinv -> fp16 smem [p][d]
    const __half* qp = g_qh + (size_t)bh * 64 * HW + p0;
    const float* qi = g_qinv + bh * HW + p0;
#pragma unroll
    for (int i = 0; i < 32; i++) {
        int t = tid + i * 128;          // 4096 half2 units
        int d2 = t >> 7, p = t & 127;
        float iv = qi[p];
        __half2 h = __floats2half2_rn(__half2float(qp[(size_t)(2 * d2) * HW + p]) * iv,
                                      __half2float(qp[(size_t)(2 * d2 + 1) * HW + p]) * iv);
        *(__half2*)(sQ + p * A_PAD + 2 * d2) = h;
    }
    asm volatile("cp.async.wait_group 0;" ::: "memory");
    __syncthreads();

    // S = Q*K^T
    float sacc[2][8][4] = {};
#pragma unroll
    for (int kk = 0; kk < 4; kk++) {
        uint32_t a[2][4], bk[4][4];
#pragma unroll
        for (int mb = 0; mb < 2; mb++)
            ldsm4(a[mb], sQa + (uint32_t)((w * 32 + mb * 16 + (lane & 15)) * A_PAD
                                          + kk * 16 + (lane >> 4) * 8) * 2);
#pragma unroll
        for (int nt2 = 0; nt2 < 4; nt2++)
            ldsm4t(bk[nt2], sKa + (uint32_t)((kk * 16 + (lane & 15)) * A_PAD
                                             + nt2 * 16 + (lane >> 4) * 8) * 2);
#pragma unroll
        for (int mb = 0; mb < 2; mb++)
#pragma unroll
            for (int nt = 0; nt < 8; nt++)
                mma16816(sacc[mb][nt], a[mb], &bk[nt >> 1][(nt & 1) * 2]);
    }

    // softmax per row
    float is0[2], is1[2];
#pragma unroll
    for (int mb = 0; mb < 2; mb++) {
        float mx0 = -INFINITY, mx1 = -INFINITY;
#pragma unroll
        for (int nt = 0; nt < 8; nt++) {
            mx0 = fmaxf(mx0, fmaxf(sacc[mb][nt][0], sacc[mb][nt][1]));
            mx1 = fmaxf(mx1, fmaxf(sacc[mb][nt][2], sacc[mb][nt][3]));
        }
        mx0 = fmaxf(mx0, __shfl_xor_sync(0xffffffff, mx0, 1));
        mx0 = fmaxf(mx0, __shfl_xor_sync(0xffffffff, mx0, 2));
        mx1 = fmaxf(mx1, __shfl_xor_sync(0xffffffff, mx1, 1));
        mx1 = fmaxf(mx1, __shfl_xor_sync(0xffffffff, mx1, 2));
        float s0 = 0.f, s1 = 0.f;
#pragma unroll
        for (int nt = 0; nt < 8; nt++) {
            sacc[mb][nt][0] = expf(sacc[mb][nt][0] - mx0);
            sacc[mb][nt][1] = expf(sacc[mb][nt][1] - mx0);
            sacc[mb][nt][2] = expf(sacc[mb][nt][2] - mx1);
            sacc[mb][nt][3] = expf(sacc[mb][nt][3] - mx1);
            s0 += sacc[mb][nt][0] + sacc[mb][nt][1];
            s1 += sacc[mb][nt][2] + sacc[mb][nt][3];
        }
        s0 += __shfl_xor_sync(0xffffffff, s0, 1);
        s0 += __shfl_xor_sync(0xffffffff, s0, 2);
        s1 += __shfl_xor_sync(0xffffffff, s1, 1);
        s1 += __shfl_xor_sync(0xffffffff, s1, 2);
        is0[mb] = 1.0f / s0;
        is1[mb] = 1.0f / s1;
    }

    // P a-frags from acc frags
    uint32_t pa[2][4][4];
#pragma unroll
    for (int mb = 0; mb < 2; mb++)
#pragma unroll
        for (int u = 0; u < 4; u++) {
            __half2 h0 = __floats2half2_rn(sacc[mb][2*u][0],   sacc[mb][2*u][1]);
            __half2 h1 = __floats2half2_rn(sacc[mb][2*u][2],   sacc[mb][2*u][3]);
            __half2 h2 = __floats2half2_rn(sacc[mb][2*u+1][0], sacc[mb][2*u+1][1]);
            __half2 h3 = __floats2half2_rn(sacc[mb][2*u+1][2], sacc[mb][2*u+1][3]);
            pa[mb][u][0] = *(uint32_t*)&h0;
            pa[mb][u][1] = *(uint32_t*)&h1;
            pa[mb][u][2] = *(uint32_t*)&h2;
            pa[mb][u][3] = *(uint32_t*)&h3;
        }

    // O = P*V
    float oacc[2][8][4] = {};
#pragma unroll
    for (int u = 0; u < 4; u++) {
        uint32_t bv[4][4];
#pragma unroll
        for (int nt2 = 0; nt2 < 4; nt2++)
            ldsm4t(bv[nt2], sVa + (uint32_t)((u * 16 + (lane & 15)) * A_PAD
                                             + nt2 * 16 + (lane >> 4) * 8) * 2);
#pragma unroll
        for (int mb = 0; mb < 2; mb++)
#pragma unroll
            for (int nt = 0; nt < 8; nt++)
                mma16816(oacc[mb][nt], pa[mb][u], &bv[nt >> 1][(nt & 1) * 2]);
    }

    __syncthreads();
#pragma unroll
    for (int mb = 0; mb < 2; mb++) {
        int q = w * 32 + mb * 16 + (lane >> 2);
#pragma unroll
        for (int nt = 0; nt < 8; nt++) {
            int d = nt * 8 + (lane & 3) * 2;
            __half2 h0 = __floats2half2_rn(oacc[mb][nt][0] * is0[mb],
                                           oacc[mb][nt][1] * is0[mb]);
            __half2 h1 = __floats2half2_rn(oacc[mb][nt][2] * is1[mb],
                                           oacc[mb][nt][3] * is1[mb]);
            *(__half2*)(sQ + q * A_PAD + d) = h0;
            *(__half2*)(sQ + (q + 8) * A_PAD + d) = h1;
        }
    }
    __syncthreads();

    size_t ob = ((size_t)(bh >> 3) * 512 + (size_t)(bh & 7) * 64) * HW + p0;
    for (int i = tid; i < 4096; i += 128) {
        int d = i >> 6, jj = i & 63;
        __half2 h = __halves2half2(sQ[(jj * 2) * A_PAD + d],
                                   sQ[(jj * 2 + 1) * A_PAD + d]);
        *(__half2*)(g_aoh + ob + (size_t)d * HW + jj * 2) = h;
    }
}

// ---------------- launch ----------------
extern "C" void kernel_launch(void* const* d_in, const int* in_sizes, int n_in,
                              void* d_out, int out_size) {
    (void)in_sizes; (void)n_in; (void)out_size;
    const float* context      = (const float*)d_in[0];
    const float* query_source = (const float*)d_in[1];
    const float* ctx_g = (const float*)d_in[2];
    const float* ctx_b = (const float*)d_in[3];
    const float* qs_g  = (const float*)d_in[4];
    const float* qs_b  = (const float*)d_in[5];
    const float* w_q   = (const float*)d_in[6];
    const float* w_kv  = (const float*)d_in[7];
    const float* w_out = (const float*)d_in[8];
    const float* gamma = (const float*)d_in[9];
    float* out = (float*)d_out;

    static bool inited = false;
    static float *p_qsn;
    static __half *p_qh, *p_kvh, *p_ctxh, *p_qsh, *p_aoh, *p_wq, *p_wkv, *p_wo;
    if (!inited) {
        cudaGetSymbolAddress((void**)&p_qsn,  g_qsn);
        cudaGetSymbolAddress((void**)&p_qh,   g_qh);
        cudaGetSymbolAddress((void**)&p_kvh,  g_kvh);
        cudaGetSymbolAddress((void**)&p_ctxh, g_ctxh);
        cudaGetSymbolAddress((void**)&p_qsh,  g_qsh);
        cudaGetSymbolAddress((void**)&p_aoh,  g_aoh);
        cudaGetSymbolAddress((void**)&p_wq,   g_wq);
        cudaGetSymbolAddress((void**)&p_wkv,  g_wkv);
        cudaGetSymbolAddress((void**)&p_wo,   g_wo);
        cudaFuncSetAttribute(mma_gemm_kernel,
                             cudaFuncAttributeMaxDynamicSharedMemorySize, GEMM_SMEM);
        inited = true;
    }

    // 1) fused channel layernorms (one launch) + weight conversion (one launch)
    fused_norm_kernel<<<2048, 256>>>(context, ctx_g, ctx_b, p_ctxh,
                                     query_source, qs_g, qs_b, p_qsh, p_qsn);
    wconv_kernel<<<1024, 256>>>(w_q, w_kv, w_out);

    // 2) projections (fp16 HMMA, fp16 out)
    mma_gemm_kernel<<<dim3(32, 8, 8), 128, GEMM_SMEM>>>(p_wkv, p_ctxh, nullptr, p_kvh,
                                                        1024, nullptr, nullptr);
    mma_gemm_kernel<<<dim3(32, 4, 8), 128, GEMM_SMEM>>>(p_wq, p_qsh, nullptr, p_qh,
                                                        512, nullptr, nullptr);

    // 3) inverse L2 norms (one launch for q and k)
    inv_norm_kernel<<<2048, 256>>>();

    // 4) pruning statistics + selection + gather
    khw_kernel<<<4096, 128>>>();
    qprobe_kernel<<<4096, 256>>>();
    score_topk_kernel<<<64, 64>>>();
    gather_kernel<<<1024, 256>>>();

    // 5) MMA attention (emits fp16 [d][p] for out-proj)
    attn_kernel<<<dim3(32, 64), 128>>>();

    // 6) out projection + residual: out = gamma*W_out@ao + qs_norm (fp32)
    mma_gemm_kernel<<<dim3(32, 4, 8), 128, GEMM_SMEM>>>(p_wo, p_aoh, out, nullptr,
                                                        512, gamma, p_qsn);
}

// round 9
// speedup vs baseline: 4.8144x; 1.0002x over previous
#include <cuda_runtime.h>
#include <cuda_fp16.h>
#include <math.h>
#include <stdint.h>

#define BATCH 8
#define DIMC  512
#define HW    4096
#define GH    64     // BATCH*HEADS
#define DH    64

// ---------------- scratch (device globals; allocation-free) ----------------
__device__ __align__(128) float  g_qsn[BATCH * DIMC * HW];     // normalized qs fp32 (residual)
__device__ __align__(128) __half g_qh [BATCH * DIMC * HW];     // q proj fp16
__device__ __align__(128) __half g_kvh[BATCH * 2 * DIMC * HW]; // kv proj fp16
__device__ __align__(128) __half g_ctxh[BATCH * DIMC * HW];    // normalized ctx fp16
__device__ __align__(128) __half g_qsh [BATCH * DIMC * HW];    // normalized qs fp16
__device__ __align__(128) __half g_aoh [BATCH * DIMC * HW];    // attention out fp16
__device__ __align__(128) __half g_wq [512 * 512];
__device__ __align__(128) __half g_wkv[1024 * 512];
__device__ __align__(128) __half g_wo [512 * 512];
__device__ float g_qinv[GH * HW];
__device__ float g_kinv[GH * HW];
__device__ float g_qprobe[GH * DH];
__device__ float g_kh[GH * DH * 64];
__device__ float g_kw[GH * DH * 64];
__device__ int   g_idxh[GH * 8];
__device__ int   g_idxw[GH * 8];
__device__ __half g_kT[GH * 64 * 64];   // [bh][d][j]  (normalized k, transposed)
__device__ __half g_vf[GH * 64 * 64];   // [bh][j][d]

// ================= warp-MMA helpers =================
__device__ __forceinline__ uint32_t smem_u32(const void* p) {
    uint32_t a;
    asm("{ .reg .u64 t; cvta.to.shared.u64 t, %1; cvt.u32.u64 %0, t; }" : "=r"(a) : "l"(p));
    return a;
}
__device__ __forceinline__ void cp16(uint32_t d, const void* s) {
    asm volatile("cp.async.cg.shared.global [%0], [%1], 16;" :: "r"(d), "l"(s));
}
__device__ __forceinline__ void ldsm4(uint32_t* r, uint32_t a) {
    asm volatile("ldmatrix.sync.aligned.m8n8.x4.shared.b16 {%0,%1,%2,%3}, [%4];"
                 : "=r"(r[0]), "=r"(r[1]), "=r"(r[2]), "=r"(r[3]) : "r"(a));
}
__device__ __forceinline__ void ldsm4t(uint32_t* r, uint32_t a) {
    asm volatile("ldmatrix.sync.aligned.m8n8.x4.trans.shared.b16 {%0,%1,%2,%3}, [%4];"
                 : "=r"(r[0]), "=r"(r[1]), "=r"(r[2]), "=r"(r[3]) : "r"(a));
}
__device__ __forceinline__ void mma16816(float* c, const uint32_t* a, const uint32_t* b) {
    asm volatile(
        "mma.sync.aligned.m16n8k16.row.col.f32.f16.f16.f32 "
        "{%0,%1,%2,%3}, {%4,%5,%6,%7}, {%8,%9}, {%0,%1,%2,%3};"
        : "+f"(c[0]), "+f"(c[1]), "+f"(c[2]), "+f"(c[3])
        : "r"(a[0]), "r"(a[1]), "r"(a[2]), "r"(a[3]), "r"(b[0]), "r"(b[1]));
}

// SMEM: A padded to 72 elems/row, B to 136 (conflict-free ldmatrix)
#define A_PAD 72
#define B_PAD 136
#define A_PL  (128 * A_PAD)              // 9216 elems
#define ST_ELEMS (A_PL + 64 * B_PAD)     // 17920 elems = 35840 B/stage
#define GEMM_SMEM (3 * ST_ELEMS * 2)     // 107520 B, 3 stages

// ======== GEMM: Y[b,m,n] = sum_k W[m,k]*X[b,k,n], fp16 in, fp32 acc ========
// 128x128 CTA tile, 4 warps of 64x64, 3-stage cp.async, 2 CTAs/SM.
// If invOut != nullptr: also emits per-column 1/L2-norm over each 64-row
// d-group (rows m0+wm < 512 only), into invOut[(b*8 + group)*HW + n].
__global__ void __launch_bounds__(128, 2)
mma_gemm_kernel(const __half* __restrict__ Wh, const __half* __restrict__ Xh,
                float* __restrict__ Y, __half* __restrict__ Yh, int M,
                const float* __restrict__ gammap, const float* __restrict__ addend,
                float* __restrict__ invOut) {
    extern __shared__ __half sm[];
    uint32_t sbase = smem_u32(sm);
    int tid = threadIdx.x;
    int lane = tid & 31, wid = tid >> 5;
    int b = blockIdx.z;
    int m0 = blockIdx.y * 128, n0 = blockIdx.x * 128;
    const __half* wsrc = Wh + (size_t)m0 * 512;
    const __half* xsrc = Xh + (size_t)b * DIMC * HW + n0;

    auto copy_chunk = [&](int c) {
        uint32_t sb = sbase + (uint32_t)(c % 3) * (ST_ELEMS * 2);
#pragma unroll
        for (int i = 0; i < 8; i++) {           // A: 128m x 64k
            int t = tid + i * 128;
            int m = t >> 3, j = t & 7;
            cp16(sb + (uint32_t)(m * A_PAD + j * 8) * 2,
                 wsrc + (size_t)m * 512 + c * 64 + j * 8);
        }
#pragma unroll
        for (int i = 0; i < 8; i++) {           // B: 64k x 128n
            int t = tid + i * 128;
            int k = t >> 4, j = t & 15;
            cp16(sb + (uint32_t)(A_PL + k * B_PAD + j * 8) * 2,
                 xsrc + (size_t)(c * 64 + k) * HW + j * 8);
        }
        asm volatile("cp.async.commit_group;" ::: "memory");
    };

    float acc[4][8][4] = {};
    int wm = (wid & 1) * 64;     // warp m-offset
    int wn = (wid >> 1) * 64;    // warp n-offset

    copy_chunk(0);
    copy_chunk(1);
    for (int c = 0; c < 8; c++) {
        if (c < 7) {
            asm volatile("cp.async.wait_group 1;" ::: "memory");
        } else {
            asm volatile("cp.async.wait_group 0;" ::: "memory");
        }
        __syncthreads();
        if (c < 6) copy_chunk(c + 2);

        uint32_t sb = sbase + (uint32_t)(c % 3) * (ST_ELEMS * 2);
        uint32_t a_0 = sb + (uint32_t)((wm + (lane & 15)) * A_PAD + (lane >> 4) * 8) * 2;
        uint32_t b_0 = sb + (uint32_t)(A_PL + (lane & 15) * B_PAD + wn + (lane >> 4) * 8) * 2;
#pragma unroll
        for (int kk = 0; kk < 4; kk++) {
            uint32_t ah[4][4], bh[4][4];
#pragma unroll
            for (int mb = 0; mb < 4; mb++)
                ldsm4(ah[mb], a_0 + (uint32_t)(mb * 16 * A_PAD + kk * 16) * 2);
#pragma unroll
            for (int nt2 = 0; nt2 < 4; nt2++)
                ldsm4t(bh[nt2], b_0 + (uint32_t)(kk * 16 * B_PAD + nt2 * 16) * 2);
#pragma unroll
            for (int mb = 0; mb < 4; mb++)
#pragma unroll
                for (int nb = 0; nb < 8; nb++)
                    mma16816(acc[mb][nb], ah[mb], &bh[nb >> 1][(nb & 1) * 2]);
        }
    }

    float ga = gammap ? gammap[0] : 1.0f;
    int g = lane >> 2, tig = lane & 3;
#pragma unroll
    for (int mb = 0; mb < 4; mb++) {
#pragma unroll
        for (int nb = 0; nb < 8; nb++) {
            int m = m0 + wm + mb * 16 + g;
            int n = n0 + wn + nb * 8 + tig * 2;
            size_t off0 = ((size_t)b * M + m) * HW + n;
            size_t off1 = off0 + (size_t)8 * HW;
            float* p = acc[mb][nb];
            if (Yh) {
                *(__half2*)(Yh + off0) = __floats2half2_rn(p[0], p[1]);
                *(__half2*)(Yh + off1) = __floats2half2_rn(p[2], p[3]);
            } else if (addend) {
                size_t a0 = ((size_t)b * 512 + m) * HW + n;
                float2 d0 = *(const float2*)(addend + a0);
                float2 d1 = *(const float2*)(addend + a0 + (size_t)8 * HW);
                *(float2*)(Y + off0) = make_float2(ga * p[0] + d0.x, ga * p[1] + d0.y);
                *(float2*)(Y + off1) = make_float2(ga * p[2] + d1.x, ga * p[3] + d1.y);
            } else {
                *(float2*)(Y + off0) = make_float2(p[0], p[1]);
                *(float2*)(Y + off1) = make_float2(p[2], p[3]);
            }
        }
    }

    // fused inverse-L2-norm over each 64-row d-group (k/q tensors)
    if (invOut && (m0 + wm) < 512) {
        int grp = (m0 + wm) >> 6;                 // 0..7
        float* dst = invOut + ((size_t)b * 8 + grp) * HW + n0 + wn;
        float ss0[8], ss1[8];
#pragma unroll
        for (int nb = 0; nb < 8; nb++) {
            float s0 = 0.f, s1 = 0.f;
#pragma unroll
            for (int mb = 0; mb < 4; mb++) {
                float* p = acc[mb][nb];
                s0 += p[0] * p[0] + p[2] * p[2];   // col 2*tig
                s1 += p[1] * p[1] + p[3] * p[3];   // col 2*tig+1
            }
            ss0[nb] = s0; ss1[nb] = s1;
        }
#pragma unroll
        for (int st = 4; st < 32; st <<= 1) {
#pragma unroll
            for (int nb = 0; nb < 8; nb++) {
                ss0[nb] += __shfl_xor_sync(0xffffffff, ss0[nb], st);
                ss1[nb] += __shfl_xor_sync(0xffffffff, ss1[nb], st);
            }
        }
        if (g == 0) {
#pragma unroll
            for (int nb = 0; nb < 8; nb++) {
                int n = nb * 8 + tig * 2;
                dst[n]     = 1.0f / fmaxf(sqrtf(ss0[nb]), 1e-12f);
                dst[n + 1] = 1.0f / fmaxf(sqrtf(ss1[nb]), 1e-12f);
            }
        }
    }
}

// ---------------- fused channel layernorm (both tensors, one launch) ----------------
__global__ __launch_bounds__(256) void fused_norm_kernel(const float* __restrict__ in0,
                                                         const float* __restrict__ gw0,
                                                         const float* __restrict__ bw0,
                                                         __half* __restrict__ oh0,
                                                         const float* __restrict__ in1,
                                                         const float* __restrict__ gw1,
                                                         const float* __restrict__ bw1,
                                                         __half* __restrict__ oh1,
                                                         float* __restrict__ of1) {
    __shared__ float shs[8][32], shq[8][32];
    __shared__ float smean[32], srstd[32];
    int half2nd = blockIdx.x >> 10;
    const float* in = half2nd ? in1 : in0;
    const float* gw = half2nd ? gw1 : gw0;
    const float* bw = half2nd ? bw1 : bw0;
    __half* oh = half2nd ? oh1 : oh0;
    float* of = half2nd ? of1 : nullptr;
    int tid = threadIdx.x;
    int px = tid & 31, cg = tid >> 5;
    int pos = (blockIdx.x & 1023) * 32 + px;
    int b = pos >> 12, sp = pos & 4095;
    size_t base = (size_t)b * DIMC * HW + sp;
    int c0 = cg * 64;
    float v[64];
    float s = 0.f, q = 0.f;
#pragma unroll 8
    for (int c = 0; c < 64; c++) {
        float x = in[base + (size_t)(c0 + c) * HW];
        v[c] = x; s += x; q += x * x;
    }
    shs[cg][px] = s; shq[cg][px] = q;
    __syncthreads();
    if (cg == 0) {
        float ts = 0.f, tq = 0.f;
#pragma unroll
        for (int g = 0; g < 8; g++) { ts += shs[g][px]; tq += shq[g][px]; }
        float mean = ts * (1.0f / 512.0f);
        float var = tq * (1.0f / 512.0f) - mean * mean;
        smean[px] = mean;
        srstd[px] = rsqrtf(var + 1e-5f);
    }
    __syncthreads();
    float m = smean[px], r = srstd[px];
#pragma unroll 8
    for (int c = 0; c < 64; c++) {
        float y = (v[c] - m) * r * gw[c0 + c] + bw[c0 + c];
        size_t idx = base + (size_t)(c0 + c) * HW;
        oh[idx] = __float2half_rn(y);
        if (of) of[idx] = y;
    }
}

// ---------------- all weights fp32 -> fp16, one launch ----------------
__global__ __launch_bounds__(256) void wconv_kernel(const float* __restrict__ wq,
                                                    const float* __restrict__ wkv,
                                                    const float* __restrict__ wo) {
    int i4 = (blockIdx.x * 256 + threadIdx.x) * 4;     // over 1,048,576 elems
    const float* src;
    __half* dst;
    int off;
    if (i4 < 262144)       { src = wq;  dst = g_wq;  off = i4; }
    else if (i4 < 786432)  { src = wkv; dst = g_wkv; off = i4 - 262144; }
    else                   { src = wo;  dst = g_wo;  off = i4 - 786432; }
    float4 x = *(const float4*)(src + off);
    *(__half2*)(dst + off)     = __floats2half2_rn(x.x, x.y);
    *(__half2*)(dst + off + 2) = __floats2half2_rn(x.z, x.w);
}

// ---------------- merged stats: khw (blocks 0..4095) + qprobe (4096..8191) ----------------
__global__ __launch_bounds__(256) void stats_kernel() {
    __shared__ float pl[4096];
    int tid = threadIdx.x;
    if (blockIdx.x < 4096) {
        // k abs-sums over height & width, normalized
        int bh = blockIdx.x >> 6, c = blockIdx.x & 63;
        size_t base = (size_t)(bh >> 3) * (2 * DIMC * HW) + (size_t)(bh & 7) * (64 * HW)
                    + (size_t)c * HW;
        const float* ki = g_kinv + bh * HW;
        for (int i = tid; i < 2048; i += 256) {
            __half2 h = *(const __half2*)(g_kvh + base + 2 * i);
            float2 kv2 = __half22float2(h);
            float2 ki2 = *(const float2*)(ki + 2 * i);
            pl[2 * i]     = fabsf(kv2.x) * ki2.x;
            pl[2 * i + 1] = fabsf(kv2.y) * ki2.y;
        }
        __syncthreads();
        if (tid < 64) {
            int h = tid;
            float s = 0.f;
#pragma unroll 8
            for (int w = 0; w < 64; w++) s += pl[h * 64 + ((w + h) & 63)];
            g_kh[bh * 4096 + c * 64 + h] = s;
        } else if (tid < 128) {
            int w = tid - 64;
            float s = 0.f;
#pragma unroll 8
            for (int h = 0; h < 64; h++) s += pl[h * 64 + w];
            g_kw[bh * 4096 + c * 64 + w] = s;
        }
    } else {
        // q abs-sum over spatial, normalized
        int bid = blockIdx.x - 4096;     // bh*64 + c
        int g = bid >> 6;
        const __half2* p2 = (const __half2*)(g_qh + (size_t)bid * HW);
        const float2* iv2 = (const float2*)(g_qinv + (size_t)g * HW);
        float s = 0.f;
        for (int i = tid; i < 2048; i += 256) {
            float2 v = __half22float2(p2[i]);
            float2 iv = iv2[i];
            s += fabsf(v.x) * iv.x + fabsf(v.y) * iv.y;
        }
        pl[tid] = s;
        __syncthreads();
        for (int st = 128; st > 0; st >>= 1) {
            if (tid < st) pl[tid] += pl[tid + st];
            __syncthreads();
        }
        if (tid == 0) g_qprobe[bid] = pl[0];
    }
}

// ---------------- scores + top-8 selection ----------------
__global__ __launch_bounds__(64) void score_topk_kernel() {
    int bh = blockIdx.x;
    int h = threadIdx.x;
    __shared__ float sr[64], sc[64];
    float a = 0.f, bb = 0.f;
    for (int c = 0; c < 64; c++) {
        float qp = g_qprobe[bh * 64 + c];
        a  += qp * g_kh[bh * 4096 + c * 64 + h];
        bb += qp * g_kw[bh * 4096 + c * 64 + h];
    }
    sr[h] = a; sc[h] = bb;
    __syncthreads();
    if (h == 0) {
        for (int i = 0; i < 8; i++) {
            float best = -INFINITY; int bi = 0;
            for (int j = 0; j < 64; j++) if (sr[j] > best) { best = sr[j]; bi = j; }
            g_idxh[bh * 8 + i] = bi;
            sr[bi] = -INFINITY;
        }
    } else if (h == 1) {
        for (int i = 0; i < 8; i++) {
            float best = -INFINITY; int bi = 0;
            for (int j = 0; j < 64; j++) if (sc[j] > best) { best = sc[j]; bi = j; }
            g_idxw[bh * 8 + i] = bi;
            sc[bi] = -INFINITY;
        }
    }
}

// ---------------- gather pruned k/v -> fp16 tiles for MMA attention ----------------
__global__ __launch_bounds__(256) void gather_kernel() {
    int idx = blockIdx.x * 256 + threadIdx.x;   // 262144
    int bh = idx >> 12, r = (idx >> 6) & 63, cc = idx & 63;
    size_t base = (size_t)(bh >> 3) * (2 * DIMC * HW) + (size_t)(bh & 7) * (64 * HW);
    {   // kT: row d=r, col j=cc (normalized)
        int hh = g_idxh[bh * 8 + (cc >> 3)];
        int ww = g_idxw[bh * 8 + (cc & 7)];
        int p = hh * 64 + ww;
        float k = __half2float(g_kvh[base + (size_t)r * HW + p]) * g_kinv[bh * HW + p];
        g_kT[idx] = __float2half_rn(k);
    }
    {   // vf: row j=r, col d=cc (plain copy)
        int hh = g_idxh[bh * 8 + (r >> 3)];
        int ww = g_idxw[bh * 8 + (r & 7)];
        int p = hh * 64 + ww;
        g_vf[idx] = g_kvh[base + (size_t)DIMC * HW + (size_t)cc * HW + p];
    }
}

// ---------------- MMA attention: per (bh, 128-query tile) ----------------
__global__ __launch_bounds__(128) void attn_kernel() {
    __shared__ __half sQ[128 * A_PAD];   // [p][d]; reused for O staging [q][d]
    __shared__ __half sK[64 * A_PAD];    // [d][j]
    __shared__ __half sV[64 * A_PAD];    // [j][d]
    int tid = threadIdx.x, lane = tid & 31, w = tid >> 5;
    int p0 = blockIdx.x * 128, bh = blockIdx.y;
    uint32_t sQa = smem_u32(sQ), sKa = smem_u32(sK), sVa = smem_u32(sV);

    const __half* kt = g_kT + bh * 4096;
    const __half* vf = g_vf + bh * 4096;
#pragma unroll
    for (int i = 0; i < 4; i++) {
        int t = tid + i * 128;
        int r = t >> 3, j = t & 7;
        cp16(sKa + (uint32_t)(r * A_PAD + j * 8) * 2, kt + r * 64 + j * 8);
        cp16(sVa + (uint32_t)(r * A_PAD + j * 8) * 2, vf + r * 64 + j * 8);
    }
    asm volatile("cp.async.commit_group;" ::: "memory");

    // Q: fp16 * qinv -> fp16 smem [p][d]
    const __half* qp = g_qh + (size_t)bh * 64 * HW + p0;
    const float* qi = g_qinv + bh * HW + p0;
#pragma unroll
    for (int i = 0; i < 32; i++) {
        int t = tid + i * 128;          // 4096 half2 units
        int d2 = t >> 7, p = t & 127;
        float iv = qi[p];
        __half2 h = __floats2half2_rn(__half2float(qp[(size_t)(2 * d2) * HW + p]) * iv,
                                      __half2float(qp[(size_t)(2 * d2 + 1) * HW + p]) * iv);
        *(__half2*)(sQ + p * A_PAD + 2 * d2) = h;
    }
    asm volatile("cp.async.wait_group 0;" ::: "memory");
    __syncthreads();

    // S = Q*K^T
    float sacc[2][8][4] = {};
#pragma unroll
    for (int kk = 0; kk < 4; kk++) {
        uint32_t a[2][4], bk[4][4];
#pragma unroll
        for (int mb = 0; mb < 2; mb++)
            ldsm4(a[mb], sQa + (uint32_t)((w * 32 + mb * 16 + (lane & 15)) * A_PAD
                                          + kk * 16 + (lane >> 4) * 8) * 2);
#pragma unroll
        for (int nt2 = 0; nt2 < 4; nt2++)
            ldsm4t(bk[nt2], sKa + (uint32_t)((kk * 16 + (lane & 15)) * A_PAD
                                             + nt2 * 16 + (lane >> 4) * 8) * 2);
#pragma unroll
        for (int mb = 0; mb < 2; mb++)
#pragma unroll
            for (int nt = 0; nt < 8; nt++)
                mma16816(sacc[mb][nt], a[mb], &bk[nt >> 1][(nt & 1) * 2]);
    }

    // softmax per row
    float is0[2], is1[2];
#pragma unroll
    for (int mb = 0; mb < 2; mb++) {
        float mx0 = -INFINITY, mx1 = -INFINITY;
#pragma unroll
        for (int nt = 0; nt < 8; nt++) {
            mx0 = fmaxf(mx0, fmaxf(sacc[mb][nt][0], sacc[mb][nt][1]));
            mx1 = fmaxf(mx1, fmaxf(sacc[mb][nt][2], sacc[mb][nt][3]));
        }
        mx0 = fmaxf(mx0, __shfl_xor_sync(0xffffffff, mx0, 1));
        mx0 = fmaxf(mx0, __shfl_xor_sync(0xffffffff, mx0, 2));
        mx1 = fmaxf(mx1, __shfl_xor_sync(0xffffffff, mx1, 1));
        mx1 = fmaxf(mx1, __shfl_xor_sync(0xffffffff, mx1, 2));
        float s0 = 0.f, s1 = 0.f;
#pragma unroll
        for (int nt = 0; nt < 8; nt++) {
            sacc[mb][nt][0] = expf(sacc[mb][nt][0] - mx0);
            sacc[mb][nt][1] = expf(sacc[mb][nt][1] - mx0);
            sacc[mb][nt][2] = expf(sacc[mb][nt][2] - mx1);
            sacc[mb][nt][3] = expf(sacc[mb][nt][3] - mx1);
            s0 += sacc[mb][nt][0] + sacc[mb][nt][1];
            s1 += sacc[mb][nt][2] + sacc[mb][nt][3];
        }
        s0 += __shfl_xor_sync(0xffffffff, s0, 1);
        s0 += __shfl_xor_sync(0xffffffff, s0, 2);
        s1 += __shfl_xor_sync(0xffffffff, s1, 1);
        s1 += __shfl_xor_sync(0xffffffff, s1, 2);
        is0[mb] = 1.0f / s0;
        is1[mb] = 1.0f / s1;
    }

    // P a-frags from acc frags
    uint32_t pa[2][4][4];
#pragma unroll
    for (int mb = 0; mb < 2; mb++)
#pragma unroll
        for (int u = 0; u < 4; u++) {
            __half2 h0 = __floats2half2_rn(sacc[mb][2*u][0],   sacc[mb][2*u][1]);
            __half2 h1 = __floats2half2_rn(sacc[mb][2*u][2],   sacc[mb][2*u][3]);
            __half2 h2 = __floats2half2_rn(sacc[mb][2*u+1][0], sacc[mb][2*u+1][1]);
            __half2 h3 = __floats2half2_rn(sacc[mb][2*u+1][2], sacc[mb][2*u+1][3]);
            pa[mb][u][0] = *(uint32_t*)&h0;
            pa[mb][u][1] = *(uint32_t*)&h1;
            pa[mb][u][2] = *(uint32_t*)&h2;
            pa[mb][u][3] = *(uint32_t*)&h3;
        }

    // O = P*V
    float oacc[2][8][4] = {};
#pragma unroll
    for (int u = 0; u < 4; u++) {
        uint32_t bv[4][4];
#pragma unroll
        for (int nt2 = 0; nt2 < 4; nt2++)
            ldsm4t(bv[nt2], sVa + (uint32_t)((u * 16 + (lane & 15)) * A_PAD
                                             + nt2 * 16 + (lane >> 4) * 8) * 2);
#pragma unroll
        for (int mb = 0; mb < 2; mb++)
#pragma unroll
            for (int nt = 0; nt < 8; nt++)
                mma16816(oacc[mb][nt], pa[mb][u], &bv[nt >> 1][(nt & 1) * 2]);
    }

    __syncthreads();
#pragma unroll
    for (int mb = 0; mb < 2; mb++) {
        int q = w * 32 + mb * 16 + (lane >> 2);
#pragma unroll
        for (int nt = 0; nt < 8; nt++) {
            int d = nt * 8 + (lane & 3) * 2;
            __half2 h0 = __floats2half2_rn(oacc[mb][nt][0] * is0[mb],
                                           oacc[mb][nt][1] * is0[mb]);
            __half2 h1 = __floats2half2_rn(oacc[mb][nt][2] * is1[mb],
                                           oacc[mb][nt][3] * is1[mb]);
            *(__half2*)(sQ + q * A_PAD + d) = h0;
            *(__half2*)(sQ + (q + 8) * A_PAD + d) = h1;
        }
    }
    __syncthreads();

    size_t ob = ((size_t)(bh >> 3) * 512 + (size_t)(bh & 7) * 64) * HW + p0;
    for (int i = tid; i < 4096; i += 128) {
        int d = i >> 6, jj = i & 63;
        __half2 h = __halves2half2(sQ[(jj * 2) * A_PAD + d],
                                   sQ[(jj * 2 + 1) * A_PAD + d]);
        *(__half2*)(g_aoh + ob + (size_t)d * HW + jj * 2) = h;
    }
}

// ---------------- launch ----------------
extern "C" void kernel_launch(void* const* d_in, const int* in_sizes, int n_in,
                              void* d_out, int out_size) {
    (void)in_sizes; (void)n_in; (void)out_size;
    const float* context      = (const float*)d_in[0];
    const float* query_source = (const float*)d_in[1];
    const float* ctx_g = (const float*)d_in[2];
    const float* ctx_b = (const float*)d_in[3];
    const float* qs_g  = (const float*)d_in[4];
    const float* qs_b  = (const float*)d_in[5];
    const float* w_q   = (const float*)d_in[6];
    const float* w_kv  = (const float*)d_in[7];
    const float* w_out = (const float*)d_in[8];
    const float* gamma = (const float*)d_in[9];
    float* out = (float*)d_out;

    static bool inited = false;
    static float *p_qsn, *p_qinv, *p_kinv;
    static __half *p_qh, *p_kvh, *p_ctxh, *p_qsh, *p_aoh, *p_wq, *p_wkv, *p_wo;
    if (!inited) {
        cudaGetSymbolAddress((void**)&p_qsn,  g_qsn);
        cudaGetSymbolAddress((void**)&p_qinv, g_qinv);
        cudaGetSymbolAddress((void**)&p_kinv, g_kinv);
        cudaGetSymbolAddress((void**)&p_qh,   g_qh);
        cudaGetSymbolAddress((void**)&p_kvh,  g_kvh);
        cudaGetSymbolAddress((void**)&p_ctxh, g_ctxh);
        cudaGetSymbolAddress((void**)&p_qsh,  g_qsh);
        cudaGetSymbolAddress((void**)&p_aoh,  g_aoh);
        cudaGetSymbolAddress((void**)&p_wq,   g_wq);
        cudaGetSymbolAddress((void**)&p_wkv,  g_wkv);
        cudaGetSymbolAddress((void**)&p_wo,   g_wo);
        cudaFuncSetAttribute(mma_gemm_kernel,
                             cudaFuncAttributeMaxDynamicSharedMemorySize, GEMM_SMEM);
        inited = true;
    }

    // 1) fused channel layernorms + weight conversion
    fused_norm_kernel<<<2048, 256>>>(context, ctx_g, ctx_b, p_ctxh,
                                     query_source, qs_g, qs_b, p_qsh, p_qsn);
    wconv_kernel<<<1024, 256>>>(w_q, w_kv, w_out);

    // 2) projections (fp16 HMMA, fp16 out, fused inverse-L2 epilogue)
    mma_gemm_kernel<<<dim3(32, 8, 8), 128, GEMM_SMEM>>>(p_wkv, p_ctxh, nullptr, p_kvh,
                                                        1024, nullptr, nullptr, p_kinv);
    mma_gemm_kernel<<<dim3(32, 4, 8), 128, GEMM_SMEM>>>(p_wq, p_qsh, nullptr, p_qh,
                                                        512, nullptr, nullptr, p_qinv);

    // 3) pruning statistics (merged khw + qprobe) + selection + gather
    stats_kernel<<<8192, 256>>>();
    score_topk_kernel<<<64, 64>>>();
    gather_kernel<<<1024, 256>>>();

    // 4) MMA attention (emits fp16 [d][p] for out-proj)
    attn_kernel<<<dim3(32, 64), 128>>>();

    // 5) out projection + residual: out = gamma*W_out@ao + qs_norm (fp32)
    mma_gemm_kernel<<<dim3(32, 4, 8), 128, GEMM_SMEM>>>(p_wo, p_aoh, out, nullptr,
                                                        512, gamma, p_qsn, nullptr);
}

// round 10
// speedup vs baseline: 4.9705x; 1.0324x over previous
#include <cuda_runtime.h>
#include <cuda_fp16.h>
#include <math.h>
#include <stdint.h>

#define BATCH 8
#define DIMC  512
#define HW    4096
#define GH    64     // BATCH*HEADS
#define DH    64

// ---------------- scratch (device globals; allocation-free) ----------------
__device__ __align__(128) float  g_qsn[BATCH * DIMC * HW];     // normalized qs fp32 (residual)
__device__ __align__(128) __half g_qh [BATCH * DIMC * HW];     // q proj fp16
__device__ __align__(128) __half g_kvh[BATCH * 2 * DIMC * HW]; // kv proj fp16
__device__ __align__(128) __half g_ctxh[BATCH * DIMC * HW];    // normalized ctx fp16
__device__ __align__(128) __half g_qsh [BATCH * DIMC * HW];    // normalized qs fp16
__device__ __align__(128) __half g_aoh [BATCH * DIMC * HW];    // attention out fp16
__device__ __align__(128) __half g_wq [512 * 512];
__device__ __align__(128) __half g_wkv[1024 * 512];
__device__ __align__(128) __half g_wo [512 * 512];
__device__ float g_qinv[GH * HW];
__device__ float g_kinv[GH * HW];
__device__ float g_qprobe[GH * DH];
__device__ float g_kh[GH * DH * 64];
__device__ float g_kw[GH * DH * 64];
__device__ int   g_idxh[GH * 8];
__device__ int   g_idxw[GH * 8];
__device__ __half g_kT[GH * 64 * 64];   // [bh][d][j]  (normalized k, transposed)
__device__ __half g_vf[GH * 64 * 64];   // [bh][j][d]

// ================= warp-MMA helpers =================
__device__ __forceinline__ uint32_t smem_u32(const void* p) {
    uint32_t a;
    asm("{ .reg .u64 t; cvta.to.shared.u64 t, %1; cvt.u32.u64 %0, t; }" : "=r"(a) : "l"(p));
    return a;
}
__device__ __forceinline__ void cp16(uint32_t d, const void* s) {
    asm volatile("cp.async.cg.shared.global [%0], [%1], 16;" :: "r"(d), "l"(s));
}
__device__ __forceinline__ void ldsm4(uint32_t* r, uint32_t a) {
    asm volatile("ldmatrix.sync.aligned.m8n8.x4.shared.b16 {%0,%1,%2,%3}, [%4];"
                 : "=r"(r[0]), "=r"(r[1]), "=r"(r[2]), "=r"(r[3]) : "r"(a));
}
__device__ __forceinline__ void ldsm4t(uint32_t* r, uint32_t a) {
    asm volatile("ldmatrix.sync.aligned.m8n8.x4.trans.shared.b16 {%0,%1,%2,%3}, [%4];"
                 : "=r"(r[0]), "=r"(r[1]), "=r"(r[2]), "=r"(r[3]) : "r"(a));
}
__device__ __forceinline__ void mma16816(float* c, const uint32_t* a, const uint32_t* b) {
    asm volatile(
        "mma.sync.aligned.m16n8k16.row.col.f32.f16.f16.f32 "
        "{%0,%1,%2,%3}, {%4,%5,%6,%7}, {%8,%9}, {%0,%1,%2,%3};"
        : "+f"(c[0]), "+f"(c[1]), "+f"(c[2]), "+f"(c[3])
        : "r"(a[0]), "r"(a[1]), "r"(a[2]), "r"(a[3]), "r"(b[0]), "r"(b[1]));
}

// SMEM: A padded to 72 elems/row, B to 136 (conflict-free ldmatrix)
#define A_PAD 72
#define B_PAD 136
#define A_PL  (128 * A_PAD)              // 9216 elems
#define ST_ELEMS (A_PL + 64 * B_PAD)     // 17920 elems = 35840 B/stage
#define GEMM_SMEM (3 * ST_ELEMS * 2)     // 107520 B, 3 stages

// ======== GEMM: Y[b,m,n] = sum_k W[m,k]*X[b,k,n], fp16 in, fp32 acc ========
// 128x128 CTA tile, 8 warps of 32x64, 3-stage cp.async, 2 CTAs/SM (<=128 regs).
__global__ void __launch_bounds__(256, 2)
mma_gemm_kernel(const __half* __restrict__ Wh, const __half* __restrict__ Xh,
                float* __restrict__ Y, __half* __restrict__ Yh, int M,
                const float* __restrict__ gammap, const float* __restrict__ addend) {
    extern __shared__ __half sm[];
    uint32_t sbase = smem_u32(sm);
    int tid = threadIdx.x;
    int lane = tid & 31, wid = tid >> 5;
    int b = blockIdx.z;
    int m0 = blockIdx.y * 128, n0 = blockIdx.x * 128;
    const __half* wsrc = Wh + (size_t)m0 * 512;
    const __half* xsrc = Xh + (size_t)b * DIMC * HW + n0;

    auto copy_chunk = [&](int c) {
        uint32_t sb = sbase + (uint32_t)(c % 3) * (ST_ELEMS * 2);
#pragma unroll
        for (int i = 0; i < 4; i++) {           // A: 128m x 64k
            int t = tid + i * 256;
            int m = t >> 3, j = t & 7;
            cp16(sb + (uint32_t)(m * A_PAD + j * 8) * 2,
                 wsrc + (size_t)m * 512 + c * 64 + j * 8);
        }
#pragma unroll
        for (int i = 0; i < 4; i++) {           // B: 64k x 128n
            int t = tid + i * 256;
            int k = t >> 4, j = t & 15;
            cp16(sb + (uint32_t)(A_PL + k * B_PAD + j * 8) * 2,
                 xsrc + (size_t)(c * 64 + k) * HW + j * 8);
        }
        asm volatile("cp.async.commit_group;" ::: "memory");
    };

    float acc[2][8][4] = {};
    int wm = (wid & 3) * 32;     // warp m-offset (4 m-warps)
    int wn = (wid >> 2) * 64;    // warp n-offset (2 n-warps)

    copy_chunk(0);
    copy_chunk(1);
    for (int c = 0; c < 8; c++) {
        if (c < 7) {
            asm volatile("cp.async.wait_group 1;" ::: "memory");
        } else {
            asm volatile("cp.async.wait_group 0;" ::: "memory");
        }
        __syncthreads();        // chunk c visible; all warps done reading stage (c-1)%3
        if (c < 6) copy_chunk(c + 2);

        uint32_t sb = sbase + (uint32_t)(c % 3) * (ST_ELEMS * 2);
        uint32_t a_0 = sb + (uint32_t)((wm + (lane & 15)) * A_PAD + (lane >> 4) * 8) * 2;
        uint32_t b_0 = sb + (uint32_t)(A_PL + (lane & 15) * B_PAD + wn + (lane >> 4) * 8) * 2;
#pragma unroll
        for (int kk = 0; kk < 4; kk++) {
            uint32_t ah[2][4], bh[4][4];
#pragma unroll
            for (int mb = 0; mb < 2; mb++)
                ldsm4(ah[mb], a_0 + (uint32_t)(mb * 16 * A_PAD + kk * 16) * 2);
#pragma unroll
            for (int nt2 = 0; nt2 < 4; nt2++)
                ldsm4t(bh[nt2], b_0 + (uint32_t)(kk * 16 * B_PAD + nt2 * 16) * 2);
#pragma unroll
            for (int mb = 0; mb < 2; mb++)
#pragma unroll
                for (int nb = 0; nb < 8; nb++)
                    mma16816(acc[mb][nb], ah[mb], &bh[nb >> 1][(nb & 1) * 2]);
        }
    }

    float ga = gammap ? gammap[0] : 1.0f;
    int g = lane >> 2, tig = lane & 3;
#pragma unroll
    for (int mb = 0; mb < 2; mb++) {
#pragma unroll
        for (int nb = 0; nb < 8; nb++) {
            int m = m0 + wm + mb * 16 + g;
            int n = n0 + wn + nb * 8 + tig * 2;
            size_t off0 = ((size_t)b * M + m) * HW + n;
            size_t off1 = off0 + (size_t)8 * HW;
            float* p = acc[mb][nb];
            if (Yh) {
                *(__half2*)(Yh + off0) = __floats2half2_rn(p[0], p[1]);
                *(__half2*)(Yh + off1) = __floats2half2_rn(p[2], p[3]);
            } else if (addend) {
                size_t a0 = ((size_t)b * 512 + m) * HW + n;
                float2 d0 = *(const float2*)(addend + a0);
                float2 d1 = *(const float2*)(addend + a0 + (size_t)8 * HW);
                *(float2*)(Y + off0) = make_float2(ga * p[0] + d0.x, ga * p[1] + d0.y);
                *(float2*)(Y + off1) = make_float2(ga * p[2] + d1.x, ga * p[3] + d1.y);
            } else {
                *(float2*)(Y + off0) = make_float2(p[0], p[1]);
                *(float2*)(Y + off1) = make_float2(p[2], p[3]);
            }
        }
    }
}

// ---------------- fused channel layernorm (both tensors, one launch) ----------------
__global__ __launch_bounds__(256) void fused_norm_kernel(const float* __restrict__ in0,
                                                         const float* __restrict__ gw0,
                                                         const float* __restrict__ bw0,
                                                         __half* __restrict__ oh0,
                                                         const float* __restrict__ in1,
                                                         const float* __restrict__ gw1,
                                                         const float* __restrict__ bw1,
                                                         __half* __restrict__ oh1,
                                                         float* __restrict__ of1) {
    __shared__ float shs[8][32], shq[8][32];
    __shared__ float smean[32], srstd[32];
    int half2nd = blockIdx.x >> 10;
    const float* in = half2nd ? in1 : in0;
    const float* gw = half2nd ? gw1 : gw0;
    const float* bw = half2nd ? bw1 : bw0;
    __half* oh = half2nd ? oh1 : oh0;
    float* of = half2nd ? of1 : nullptr;
    int tid = threadIdx.x;
    int px = tid & 31, cg = tid >> 5;
    int pos = (blockIdx.x & 1023) * 32 + px;
    int b = pos >> 12, sp = pos & 4095;
    size_t base = (size_t)b * DIMC * HW + sp;
    int c0 = cg * 64;
    float v[64];
    float s = 0.f, q = 0.f;
#pragma unroll 8
    for (int c = 0; c < 64; c++) {
        float x = in[base + (size_t)(c0 + c) * HW];
        v[c] = x; s += x; q += x * x;
    }
    shs[cg][px] = s; shq[cg][px] = q;
    __syncthreads();
    if (cg == 0) {
        float ts = 0.f, tq = 0.f;
#pragma unroll
        for (int g = 0; g < 8; g++) { ts += shs[g][px]; tq += shq[g][px]; }
        float mean = ts * (1.0f / 512.0f);
        float var = tq * (1.0f / 512.0f) - mean * mean;
        smean[px] = mean;
        srstd[px] = rsqrtf(var + 1e-5f);
    }
    __syncthreads();
    float m = smean[px], r = srstd[px];
#pragma unroll 8
    for (int c = 0; c < 64; c++) {
        float y = (v[c] - m) * r * gw[c0 + c] + bw[c0 + c];
        size_t idx = base + (size_t)(c0 + c) * HW;
        oh[idx] = __float2half_rn(y);
        if (of) of[idx] = y;
    }
}

// ---------------- all weights fp32 -> fp16, one launch ----------------
__global__ __launch_bounds__(256) void wconv_kernel(const float* __restrict__ wq,
                                                    const float* __restrict__ wkv,
                                                    const float* __restrict__ wo) {
    int i4 = (blockIdx.x * 256 + threadIdx.x) * 4;     // over 1,048,576 elems
    const float* src;
    __half* dst;
    int off;
    if (i4 < 262144)       { src = wq;  dst = g_wq;  off = i4; }
    else if (i4 < 786432)  { src = wkv; dst = g_wkv; off = i4 - 262144; }
    else                   { src = wo;  dst = g_wo;  off = i4 - 786432; }
    float4 x = *(const float4*)(src + off);
    *(__half2*)(dst + off)     = __floats2half2_rn(x.x, x.y);
    *(__half2*)(dst + off + 2) = __floats2half2_rn(x.z, x.w);
}

// ---------------- inverse L2 norms for q and k, one launch ----------------
__global__ __launch_bounds__(256) void inv_norm_kernel() {
    int gidx = blockIdx.x * 256 + threadIdx.x;    // 2*GH*HW
    int qk = gidx >> 18;                          // 0: q, 1: k
    int idx = gidx & 262143;
    int g = idx >> 12, p = idx & 4095;
    const __half* t;
    size_t base;
    if (qk == 0) {
        base = (size_t)(g >> 3) * (DIMC * HW) + (size_t)(g & 7) * (64 * HW) + p;
        t = g_qh;
    } else {
        base = (size_t)(g >> 3) * (2 * DIMC * HW) + (size_t)(g & 7) * (64 * HW) + p;
        t = g_kvh;
    }
    float ss = 0.f;
#pragma unroll 8
    for (int d = 0; d < 64; d++) {
        float x = __half2float(t[base + (size_t)d * HW]);
        ss += x * x;
    }
    float r = 1.0f / fmaxf(sqrtf(ss), 1e-12f);
    if (qk == 0) g_qinv[idx] = r; else g_kinv[idx] = r;
}

// ---------------- merged stats: khw (blocks 0..4095) + qprobe (4096..8191) ----------------
__global__ __launch_bounds__(256) void stats_kernel() {
    __shared__ float pl[4096];
    int tid = threadIdx.x;
    if (blockIdx.x < 4096) {
        int bh = blockIdx.x >> 6, c = blockIdx.x & 63;
        size_t base = (size_t)(bh >> 3) * (2 * DIMC * HW) + (size_t)(bh & 7) * (64 * HW)
                    + (size_t)c * HW;
        const float* ki = g_kinv + bh * HW;
        for (int i = tid; i < 2048; i += 256) {
            __half2 h = *(const __half2*)(g_kvh + base + 2 * i);
            float2 kv2 = __half22float2(h);
            float2 ki2 = *(const float2*)(ki + 2 * i);
            pl[2 * i]     = fabsf(kv2.x) * ki2.x;
            pl[2 * i + 1] = fabsf(kv2.y) * ki2.y;
        }
        __syncthreads();
        if (tid < 64) {
            int h = tid;
            float s = 0.f;
#pragma unroll 8
            for (int w = 0; w < 64; w++) s += pl[h * 64 + ((w + h) & 63)];
            g_kh[bh * 4096 + c * 64 + h] = s;
        } else if (tid < 128) {
            int w = tid - 64;
            float s = 0.f;
#pragma unroll 8
            for (int h = 0; h < 64; h++) s += pl[h * 64 + w];
            g_kw[bh * 4096 + c * 64 + w] = s;
        }
    } else {
        int bid = blockIdx.x - 4096;     // bh*64 + c
        int g = bid >> 6;
        const __half2* p2 = (const __half2*)(g_qh + (size_t)bid * HW);
        const float2* iv2 = (const float2*)(g_qinv + (size_t)g * HW);
        float s = 0.f;
        for (int i = tid; i < 2048; i += 256) {
            float2 v = __half22float2(p2[i]);
            float2 iv = iv2[i];
            s += fabsf(v.x) * iv.x + fabsf(v.y) * iv.y;
        }
        pl[tid] = s;
        __syncthreads();
        for (int st = 128; st > 0; st >>= 1) {
            if (tid < st) pl[tid] += pl[tid + st];
            __syncthreads();
        }
        if (tid == 0) g_qprobe[bid] = pl[0];
    }
}

// ---------------- scores + top-8 selection ----------------
__global__ __launch_bounds__(64) void score_topk_kernel() {
    int bh = blockIdx.x;
    int h = threadIdx.x;
    __shared__ float sr[64], sc[64];
    float a = 0.f, bb = 0.f;
    for (int c = 0; c < 64; c++) {
        float qp = g_qprobe[bh * 64 + c];
        a  += qp * g_kh[bh * 4096 + c * 64 + h];
        bb += qp * g_kw[bh * 4096 + c * 64 + h];
    }
    sr[h] = a; sc[h] = bb;
    __syncthreads();
    if (h == 0) {
        for (int i = 0; i < 8; i++) {
            float best = -INFINITY; int bi = 0;
            for (int j = 0; j < 64; j++) if (sr[j] > best) { best = sr[j]; bi = j; }
            g_idxh[bh * 8 + i] = bi;
            sr[bi] = -INFINITY;
        }
    } else if (h == 1) {
        for (int i = 0; i < 8; i++) {
            float best = -INFINITY; int bi = 0;
            for (int j = 0; j < 64; j++) if (sc[j] > best) { best = sc[j]; bi = j; }
            g_idxw[bh * 8 + i] = bi;
            sc[bi] = -INFINITY;
        }
    }
}

// ---------------- gather pruned k/v -> fp16 tiles for MMA attention ----------------
__global__ __launch_bounds__(256) void gather_kernel() {
    int idx = blockIdx.x * 256 + threadIdx.x;   // 262144
    int bh = idx >> 12, r = (idx >> 6) & 63, cc = idx & 63;
    size_t base = (size_t)(bh >> 3) * (2 * DIMC * HW) + (size_t)(bh & 7) * (64 * HW);
    {   // kT: row d=r, col j=cc (normalized)
        int hh = g_idxh[bh * 8 + (cc >> 3)];
        int ww = g_idxw[bh * 8 + (cc & 7)];
        int p = hh * 64 + ww;
        float k = __half2float(g_kvh[base + (size_t)r * HW + p]) * g_kinv[bh * HW + p];
        g_kT[idx] = __float2half_rn(k);
    }
    {   // vf: row j=r, col d=cc (plain copy)
        int hh = g_idxh[bh * 8 + (r >> 3)];
        int ww = g_idxw[bh * 8 + (r & 7)];
        int p = hh * 64 + ww;
        g_vf[idx] = g_kvh[base + (size_t)DIMC * HW + (size_t)cc * HW + p];
    }
}

// ---------------- MMA attention: per (bh, 128-query tile) ----------------
__global__ __launch_bounds__(128) void attn_kernel() {
    __shared__ __half sQ[128 * A_PAD];   // [p][d]; reused for O staging [q][d]
    __shared__ __half sK[64 * A_PAD];    // [d][j]
    __shared__ __half sV[64 * A_PAD];    // [j][d]
    int tid = threadIdx.x, lane = tid & 31, w = tid >> 5;
    int p0 = blockIdx.x * 128, bh = blockIdx.y;
    uint32_t sQa = smem_u32(sQ), sKa = smem_u32(sK), sVa = smem_u32(sV);

    const __half* kt = g_kT + bh * 4096;
    const __half* vf = g_vf + bh * 4096;
#pragma unroll
    for (int i = 0; i < 4; i++) {
        int t = tid + i * 128;
        int r = t >> 3, j = t & 7;
        cp16(sKa + (uint32_t)(r * A_PAD + j * 8) * 2, kt + r * 64 + j * 8);
        cp16(sVa + (uint32_t)(r * A_PAD + j * 8) * 2, vf + r * 64 + j * 8);
    }
    asm volatile("cp.async.commit_group;" ::: "memory");

    // Q: fp16 * qinv -> fp16 smem [p][d]
    const __half* qp = g_qh + (size_t)bh * 64 * HW + p0;
    const float* qi = g_qinv + bh * HW + p0;
#pragma unroll
    for (int i = 0; i < 32; i++) {
        int t = tid + i * 128;          // 4096 half2 units
        int d2 = t >> 7, p = t & 127;
        float iv = qi[p];
        __half2 h = __floats2half2_rn(__half2float(qp[(size_t)(2 * d2) * HW + p]) * iv,
                                      __half2float(qp[(size_t)(2 * d2 + 1) * HW + p]) * iv);
        *(__half2*)(sQ + p * A_PAD + 2 * d2) = h;
    }
    asm volatile("cp.async.wait_group 0;" ::: "memory");
    __syncthreads();

    // S = Q*K^T
    float sacc[2][8][4] = {};
#pragma unroll
    for (int kk = 0; kk < 4; kk++) {
        uint32_t a[2][4], bk[4][4];
#pragma unroll
        for (int mb = 0; mb < 2; mb++)
            ldsm4(a[mb], sQa + (uint32_t)((w * 32 + mb * 16 + (lane & 15)) * A_PAD
                                          + kk * 16 + (lane >> 4) * 8) * 2);
#pragma unroll
        for (int nt2 = 0; nt2 < 4; nt2++)
            ldsm4t(bk[nt2], sKa + (uint32_t)((kk * 16 + (lane & 15)) * A_PAD
                                             + nt2 * 16 + (lane >> 4) * 8) * 2);
#pragma unroll
        for (int mb = 0; mb < 2; mb++)
#pragma unroll
            for (int nt = 0; nt < 8; nt++)
                mma16816(sacc[mb][nt], a[mb], &bk[nt >> 1][(nt & 1) * 2]);
    }

    // softmax per row
    float is0[2], is1[2];
#pragma unroll
    for (int mb = 0; mb < 2; mb++) {
        float mx0 = -INFINITY, mx1 = -INFINITY;
#pragma unroll
        for (int nt = 0; nt < 8; nt++) {
            mx0 = fmaxf(mx0, fmaxf(sacc[mb][nt][0], sacc[mb][nt][1]));
            mx1 = fmaxf(mx1, fmaxf(sacc[mb][nt][2], sacc[mb][nt][3]));
        }
        mx0 = fmaxf(mx0, __shfl_xor_sync(0xffffffff, mx0, 1));
        mx0 = fmaxf(mx0, __shfl_xor_sync(0xffffffff, mx0, 2));
        mx1 = fmaxf(mx1, __shfl_xor_sync(0xffffffff, mx1, 1));
        mx1 = fmaxf(mx1, __shfl_xor_sync(0xffffffff, mx1, 2));
        float s0 = 0.f, s1 = 0.f;
#pragma unroll
        for (int nt = 0; nt < 8; nt++) {
            sacc[mb][nt][0] = expf(sacc[mb][nt][0] - mx0);
            sacc[mb][nt][1] = expf(sacc[mb][nt][1] - mx0);
            sacc[mb][nt][2] = expf(sacc[mb][nt][2] - mx1);
            sacc[mb][nt][3] = expf(sacc[mb][nt][3] - mx1);
            s0 += sacc[mb][nt][0] + sacc[mb][nt][1];
            s1 += sacc[mb][nt][2] + sacc[mb][nt][3];
        }
        s0 += __shfl_xor_sync(0xffffffff, s0, 1);
        s0 += __shfl_xor_sync(0xffffffff, s0, 2);
        s1 += __shfl_xor_sync(0xffffffff, s1, 1);
        s1 += __shfl_xor_sync(0xffffffff, s1, 2);
        is0[mb] = 1.0f / s0;
        is1[mb] = 1.0f / s1;
    }

    // P a-frags from acc frags
    uint32_t pa[2][4][4];
#pragma unroll
    for (int mb = 0; mb < 2; mb++)
#pragma unroll
        for (int u = 0; u < 4; u++) {
            __half2 h0 = __floats2half2_rn(sacc[mb][2*u][0],   sacc[mb][2*u][1]);
            __half2 h1 = __floats2half2_rn(sacc[mb][2*u][2],   sacc[mb][2*u][3]);
            __half2 h2 = __floats2half2_rn(sacc[mb][2*u+1][0], sacc[mb][2*u+1][1]);
            __half2 h3 = __floats2half2_rn(sacc[mb][2*u+1][2], sacc[mb][2*u+1][3]);
            pa[mb][u][0] = *(uint32_t*)&h0;
            pa[mb][u][1] = *(uint32_t*)&h1;
            pa[mb][u][2] = *(uint32_t*)&h2;
            pa[mb][u][3] = *(uint32_t*)&h3;
        }

    // O = P*V
    float oacc[2][8][4] = {};
#pragma unroll
    for (int u = 0; u < 4; u++) {
        uint32_t bv[4][4];
#pragma unroll
        for (int nt2 = 0; nt2 < 4; nt2++)
            ldsm4t(bv[nt2], sVa + (uint32_t)((u * 16 + (lane & 15)) * A_PAD
                                             + nt2 * 16 + (lane >> 4) * 8) * 2);
#pragma unroll
        for (int mb = 0; mb < 2; mb++)
#pragma unroll
            for (int nt = 0; nt < 8; nt++)
                mma16816(oacc[mb][nt], pa[mb][u], &bv[nt >> 1][(nt & 1) * 2]);
    }

    __syncthreads();
#pragma unroll
    for (int mb = 0; mb < 2; mb++) {
        int q = w * 32 + mb * 16 + (lane >> 2);
#pragma unroll
        for (int nt = 0; nt < 8; nt++) {
            int d = nt * 8 + (lane & 3) * 2;
            __half2 h0 = __floats2half2_rn(oacc[mb][nt][0] * is0[mb],
                                           oacc[mb][nt][1] * is0[mb]);
            __half2 h1 = __floats2half2_rn(oacc[mb][nt][2] * is1[mb],
                                           oacc[mb][nt][3] * is1[mb]);
            *(__half2*)(sQ + q * A_PAD + d) = h0;
            *(__half2*)(sQ + (q + 8) * A_PAD + d) = h1;
        }
    }
    __syncthreads();

    size_t ob = ((size_t)(bh >> 3) * 512 + (size_t)(bh & 7) * 64) * HW + p0;
    for (int i = tid; i < 4096; i += 128) {
        int d = i >> 6, jj = i & 63;
        __half2 h = __halves2half2(sQ[(jj * 2) * A_PAD + d],
                                   sQ[(jj * 2 + 1) * A_PAD + d]);
        *(__half2*)(g_aoh + ob + (size_t)d * HW + jj * 2) = h;
    }
}

// ---------------- launch ----------------
extern "C" void kernel_launch(void* const* d_in, const int* in_sizes, int n_in,
                              void* d_out, int out_size) {
    (void)in_sizes; (void)n_in; (void)out_size;
    const float* context      = (const float*)d_in[0];
    const float* query_source = (const float*)d_in[1];
    const float* ctx_g = (const float*)d_in[2];
    const float* ctx_b = (const float*)d_in[3];
    const float* qs_g  = (const float*)d_in[4];
    const float* qs_b  = (const float*)d_in[5];
    const float* w_q   = (const float*)d_in[6];
    const float* w_kv  = (const float*)d_in[7];
    const float* w_out = (const float*)d_in[8];
    const float* gamma = (const float*)d_in[9];
    float* out = (float*)d_out;

    static bool inited = false;
    static float *p_qsn;
    static __half *p_qh, *p_kvh, *p_ctxh, *p_qsh, *p_aoh, *p_wq, *p_wkv, *p_wo;
    if (!inited) {
        cudaGetSymbolAddress((void**)&p_qsn,  g_qsn);
        cudaGetSymbolAddress((void**)&p_qh,   g_qh);
        cudaGetSymbolAddress((void**)&p_kvh,  g_kvh);
        cudaGetSymbolAddress((void**)&p_ctxh, g_ctxh);
        cudaGetSymbolAddress((void**)&p_qsh,  g_qsh);
        cudaGetSymbolAddress((void**)&p_aoh,  g_aoh);
        cudaGetSymbolAddress((void**)&p_wq,   g_wq);
        cudaGetSymbolAddress((void**)&p_wkv,  g_wkv);
        cudaGetSymbolAddress((void**)&p_wo,   g_wo);
        cudaFuncSetAttribute(mma_gemm_kernel,
                             cudaFuncAttributeMaxDynamicSharedMemorySize, GEMM_SMEM);
        inited = true;
    }

    // 1) fused channel layernorms + weight conversion
    fused_norm_kernel<<<2048, 256>>>(context, ctx_g, ctx_b, p_ctxh,
                                     query_source, qs_g, qs_b, p_qsh, p_qsn);
    wconv_kernel<<<1024, 256>>>(w_q, w_kv, w_out);

    // 2) projections (fp16 HMMA, fp16 out), 8-warp CTAs
    mma_gemm_kernel<<<dim3(32, 8, 8), 256, GEMM_SMEM>>>(p_wkv, p_ctxh, nullptr, p_kvh,
                                                        1024, nullptr, nullptr);
    mma_gemm_kernel<<<dim3(32, 4, 8), 256, GEMM_SMEM>>>(p_wq, p_qsh, nullptr, p_qh,
                                                        512, nullptr, nullptr);

    // 3) inverse L2 norms (standalone; GEMM epilogue kept lean)
    inv_norm_kernel<<<2048, 256>>>();

    // 4) pruning statistics (merged khw + qprobe) + selection + gather
    stats_kernel<<<8192, 256>>>();
    score_topk_kernel<<<64, 64>>>();
    gather_kernel<<<1024, 256>>>();

    // 5) MMA attention (emits fp16 [d][p] for out-proj)
    attn_kernel<<<dim3(32, 64), 128>>>();

    // 6) out projection + residual: out = gamma*W_out@ao + qs_norm (fp32)
    mma_gemm_kernel<<<dim3(32, 4, 8), 256, GEMM_SMEM>>>(p_wo, p_aoh, out, nullptr,
                                                        512, gamma, p_qsn);
}

// round 11
// speedup vs baseline: 5.6233x; 1.1313x over previous
#include <cuda_runtime.h>
#include <cuda_fp16.h>
#include <math.h>
#include <stdint.h>

#define BATCH 8
#define DIMC  512
#define HW    4096
#define GH    64     // BATCH*HEADS
#define DH    64

// ---------------- scratch (device globals; allocation-free) ----------------
__device__ __align__(128) __half g_qh [BATCH * DIMC * HW];     // q proj fp16 [b][m][p]
__device__ __align__(128) __half g_kk [BATCH * DIMC * HW];     // k proj fp16 [b][m][p]
__device__ __align__(128) __half g_ctxh[BATCH * DIMC * HW];    // normalized ctx fp16
__device__ __align__(128) __half g_qsh [BATCH * DIMC * HW];    // normalized qs fp16 (also residual)
__device__ __align__(128) __half g_aoh [BATCH * DIMC * HW];    // attention out fp16
__device__ __align__(128) __half g_wq [512 * 512];
__device__ __align__(128) __half g_wkv[1024 * 512];
__device__ __align__(128) __half g_wo [512 * 512];
__device__ float g_qinv[GH * HW];
__device__ float g_kinv[GH * HW];
__device__ float g_qprobe[GH * DH];
__device__ float g_kh[GH * DH * 64];
__device__ float g_kw[GH * DH * 64];
__device__ int   g_idxh[GH * 8];
__device__ int   g_idxw[GH * 8];
__device__ __half g_kT[GH * 64 * 64];   // [bh][d][j]  (normalized k, transposed)
__device__ __half g_vf[GH * 64 * 64];   // [bh][j][d]

// ================= warp-MMA helpers =================
__device__ __forceinline__ uint32_t smem_u32(const void* p) {
    uint32_t a;
    asm("{ .reg .u64 t; cvta.to.shared.u64 t, %1; cvt.u32.u64 %0, t; }" : "=r"(a) : "l"(p));
    return a;
}
__device__ __forceinline__ void cp16(uint32_t d, const void* s) {
    asm volatile("cp.async.cg.shared.global [%0], [%1], 16;" :: "r"(d), "l"(s));
}
__device__ __forceinline__ void ldsm4(uint32_t* r, uint32_t a) {
    asm volatile("ldmatrix.sync.aligned.m8n8.x4.shared.b16 {%0,%1,%2,%3}, [%4];"
                 : "=r"(r[0]), "=r"(r[1]), "=r"(r[2]), "=r"(r[3]) : "r"(a));
}
__device__ __forceinline__ void ldsm4t(uint32_t* r, uint32_t a) {
    asm volatile("ldmatrix.sync.aligned.m8n8.x4.trans.shared.b16 {%0,%1,%2,%3}, [%4];"
                 : "=r"(r[0]), "=r"(r[1]), "=r"(r[2]), "=r"(r[3]) : "r"(a));
}
__device__ __forceinline__ void mma16816(float* c, const uint32_t* a, const uint32_t* b) {
    asm volatile(
        "mma.sync.aligned.m16n8k16.row.col.f32.f16.f16.f32 "
        "{%0,%1,%2,%3}, {%4,%5,%6,%7}, {%8,%9}, {%0,%1,%2,%3};"
        : "+f"(c[0]), "+f"(c[1]), "+f"(c[2]), "+f"(c[3])
        : "r"(a[0]), "r"(a[1]), "r"(a[2]), "r"(a[3]), "r"(b[0]), "r"(b[1]));
}

// SMEM: A padded to 72 elems/row, B to 136 (conflict-free ldmatrix)
#define A_PAD 72
#define B_PAD 136
#define A_PL  (128 * A_PAD)              // 9216 elems
#define ST_ELEMS (A_PL + 64 * B_PAD)     // 17920 elems = 35840 B/stage
#define GEMM_SMEM (3 * ST_ELEMS * 2)     // 107520 B, 3 stages

// ======== merged q+k projection GEMM: z<8 -> k (Wk,Xk), z>=8 -> q (Wq,Xq) ========
// Y[b,m,n] = sum_k W[m,k]*X[b,k,n], M=512, fp16 out.
__global__ void __launch_bounds__(256, 2)
proj_gemm_kernel(const __half* __restrict__ Wk, const __half* __restrict__ Xk,
                 __half* __restrict__ Yk,
                 const __half* __restrict__ Wq, const __half* __restrict__ Xq,
                 __half* __restrict__ Yq) {
    extern __shared__ __half sm[];
    uint32_t sbase = smem_u32(sm);
    int tid = threadIdx.x;
    int lane = tid & 31, wid = tid >> 5;
    int z = blockIdx.z;
    const __half *W, *X;
    __half* Yh;
    int b;
    if (z < 8) { W = Wk; X = Xk; Yh = Yk; b = z; }
    else       { W = Wq; X = Xq; Yh = Yq; b = z - 8; }
    int m0 = blockIdx.y * 128, n0 = blockIdx.x * 128;
    const __half* wsrc = W + (size_t)m0 * 512;
    const __half* xsrc = X + (size_t)b * DIMC * HW + n0;

    auto copy_chunk = [&](int c) {
        uint32_t sb = sbase + (uint32_t)(c % 3) * (ST_ELEMS * 2);
#pragma unroll
        for (int i = 0; i < 4; i++) {           // A: 128m x 64k
            int t = tid + i * 256;
            int m = t >> 3, j = t & 7;
            cp16(sb + (uint32_t)(m * A_PAD + j * 8) * 2,
                 wsrc + (size_t)m * 512 + c * 64 + j * 8);
        }
#pragma unroll
        for (int i = 0; i < 4; i++) {           // B: 64k x 128n
            int t = tid + i * 256;
            int k = t >> 4, j = t & 15;
            cp16(sb + (uint32_t)(A_PL + k * B_PAD + j * 8) * 2,
                 xsrc + (size_t)(c * 64 + k) * HW + j * 8);
        }
        asm volatile("cp.async.commit_group;" ::: "memory");
    };

    float acc[2][8][4] = {};
    int wm = (wid & 3) * 32;
    int wn = (wid >> 2) * 64;

    copy_chunk(0);
    copy_chunk(1);
    for (int c = 0; c < 8; c++) {
        if (c < 7) {
            asm volatile("cp.async.wait_group 1;" ::: "memory");
        } else {
            asm volatile("cp.async.wait_group 0;" ::: "memory");
        }
        __syncthreads();
        if (c < 6) copy_chunk(c + 2);

        uint32_t sb = sbase + (uint32_t)(c % 3) * (ST_ELEMS * 2);
        uint32_t a_0 = sb + (uint32_t)((wm + (lane & 15)) * A_PAD + (lane >> 4) * 8) * 2;
        uint32_t b_0 = sb + (uint32_t)(A_PL + (lane & 15) * B_PAD + wn + (lane >> 4) * 8) * 2;
#pragma unroll
        for (int kk = 0; kk < 4; kk++) {
            uint32_t ah[2][4], bh[4][4];
#pragma unroll
            for (int mb = 0; mb < 2; mb++)
                ldsm4(ah[mb], a_0 + (uint32_t)(mb * 16 * A_PAD + kk * 16) * 2);
#pragma unroll
            for (int nt2 = 0; nt2 < 4; nt2++)
                ldsm4t(bh[nt2], b_0 + (uint32_t)(kk * 16 * B_PAD + nt2 * 16) * 2);
#pragma unroll
            for (int mb = 0; mb < 2; mb++)
#pragma unroll
                for (int nb = 0; nb < 8; nb++)
                    mma16816(acc[mb][nb], ah[mb], &bh[nb >> 1][(nb & 1) * 2]);
        }
    }

    int g = lane >> 2, tig = lane & 3;
#pragma unroll
    for (int mb = 0; mb < 2; mb++) {
#pragma unroll
        for (int nb = 0; nb < 8; nb++) {
            int m = m0 + wm + mb * 16 + g;
            int n = n0 + wn + nb * 8 + tig * 2;
            size_t off0 = ((size_t)b * 512 + m) * HW + n;
            size_t off1 = off0 + (size_t)8 * HW;
            float* p = acc[mb][nb];
            *(__half2*)(Yh + off0) = __floats2half2_rn(p[0], p[1]);
            *(__half2*)(Yh + off1) = __floats2half2_rn(p[2], p[3]);
        }
    }
}

// ======== out-proj GEMM: Y = gamma*(W@X) + addend(fp16), fp32 out, M=512 ========
__global__ void __launch_bounds__(256, 2)
out_gemm_kernel(const __half* __restrict__ W, const __half* __restrict__ X,
                float* __restrict__ Y, const float* __restrict__ gammap,
                const __half* __restrict__ addend) {
    extern __shared__ __half sm[];
    uint32_t sbase = smem_u32(sm);
    int tid = threadIdx.x;
    int lane = tid & 31, wid = tid >> 5;
    int b = blockIdx.z;
    int m0 = blockIdx.y * 128, n0 = blockIdx.x * 128;
    const __half* wsrc = W + (size_t)m0 * 512;
    const __half* xsrc = X + (size_t)b * DIMC * HW + n0;

    auto copy_chunk = [&](int c) {
        uint32_t sb = sbase + (uint32_t)(c % 3) * (ST_ELEMS * 2);
#pragma unroll
        for (int i = 0; i < 4; i++) {
            int t = tid + i * 256;
            int m = t >> 3, j = t & 7;
            cp16(sb + (uint32_t)(m * A_PAD + j * 8) * 2,
                 wsrc + (size_t)m * 512 + c * 64 + j * 8);
        }
#pragma unroll
        for (int i = 0; i < 4; i++) {
            int t = tid + i * 256;
            int k = t >> 4, j = t & 15;
            cp16(sb + (uint32_t)(A_PL + k * B_PAD + j * 8) * 2,
                 xsrc + (size_t)(c * 64 + k) * HW + j * 8);
        }
        asm volatile("cp.async.commit_group;" ::: "memory");
    };

    float acc[2][8][4] = {};
    int wm = (wid & 3) * 32;
    int wn = (wid >> 2) * 64;

    copy_chunk(0);
    copy_chunk(1);
    for (int c = 0; c < 8; c++) {
        if (c < 7) {
            asm volatile("cp.async.wait_group 1;" ::: "memory");
        } else {
            asm volatile("cp.async.wait_group 0;" ::: "memory");
        }
        __syncthreads();
        if (c < 6) copy_chunk(c + 2);

        uint32_t sb = sbase + (uint32_t)(c % 3) * (ST_ELEMS * 2);
        uint32_t a_0 = sb + (uint32_t)((wm + (lane & 15)) * A_PAD + (lane >> 4) * 8) * 2;
        uint32_t b_0 = sb + (uint32_t)(A_PL + (lane & 15) * B_PAD + wn + (lane >> 4) * 8) * 2;
#pragma unroll
        for (int kk = 0; kk < 4; kk++) {
            uint32_t ah[2][4], bh[4][4];
#pragma unroll
            for (int mb = 0; mb < 2; mb++)
                ldsm4(ah[mb], a_0 + (uint32_t)(mb * 16 * A_PAD + kk * 16) * 2);
#pragma unroll
            for (int nt2 = 0; nt2 < 4; nt2++)
                ldsm4t(bh[nt2], b_0 + (uint32_t)(kk * 16 * B_PAD + nt2 * 16) * 2);
#pragma unroll
            for (int mb = 0; mb < 2; mb++)
#pragma unroll
                for (int nb = 0; nb < 8; nb++)
                    mma16816(acc[mb][nb], ah[mb], &bh[nb >> 1][(nb & 1) * 2]);
        }
    }

    float ga = gammap[0];
    int g = lane >> 2, tig = lane & 3;
#pragma unroll
    for (int mb = 0; mb < 2; mb++) {
#pragma unroll
        for (int nb = 0; nb < 8; nb++) {
            int m = m0 + wm + mb * 16 + g;
            int n = n0 + wn + nb * 8 + tig * 2;
            size_t off0 = ((size_t)b * 512 + m) * HW + n;
            size_t off1 = off0 + (size_t)8 * HW;
            float* p = acc[mb][nb];
            float2 d0 = __half22float2(*(const __half2*)(addend + off0));
            float2 d1 = __half22float2(*(const __half2*)(addend + off1));
            *(float2*)(Y + off0) = make_float2(ga * p[0] + d0.x, ga * p[1] + d0.y);
            *(float2*)(Y + off1) = make_float2(ga * p[2] + d1.x, ga * p[3] + d1.y);
        }
    }
}

// ======== v-gather GEMM: per bh, V[j][d] = sum_c wv[d,c]*ctx[c,p_j], 64x64x512 ========
#define VG_APAD 520
#define VG_BOFF (64 * VG_APAD)                    // 33280 elems
#define VG_SMEM ((VG_BOFF + 512 * 72) * 2)        // 140288 B
__global__ void __launch_bounds__(128) vgather_kernel() {
    extern __shared__ __half sm[];
    __shared__ int sidx[16];
    uint32_t sbase = smem_u32(sm);
    int tid = threadIdx.x, lane = tid & 31, w = tid >> 5;
    int bh = blockIdx.x;

    if (tid < 8) sidx[tid] = g_idxh[bh * 8 + tid];
    else if (tid < 16) sidx[tid] = g_idxw[bh * 8 + tid - 8];

    // A: wv rows for this head: [64 d][512 c], padded rows of 520
    const __half* wv = g_wkv + (size_t)(512 + (bh & 7) * 64) * 512;
#pragma unroll
    for (int i = 0; i < 32; i++) {
        int t = tid + i * 128;          // 4096 cp16 ops
        int row = t >> 6, j8 = t & 63;
        cp16(sbase + (uint32_t)(row * VG_APAD + j8 * 8) * 2, wv + row * 512 + j8 * 8);
    }
    asm volatile("cp.async.commit_group;" ::: "memory");
    __syncthreads();                    // sidx visible

    // B: gathered ctx [512 c][64 j], padded rows of 72
    const __half* ctx = g_ctxh + (size_t)(bh >> 3) * DIMC * HW;
    int pj = sidx[(tid & 63) >> 3] * 64 + sidx[8 + (tid & 7)];   // position for j = tid&63
#pragma unroll 8
    for (int i = 0; i < 256; i++) {
        int t = tid + i * 128;
        int k = t >> 6, j = t & 63;     // j pattern repeats with tid&63
        sm[VG_BOFF + k * 72 + j] = ctx[(size_t)k * HW + pj];
    }
    asm volatile("cp.async.wait_group 0;" ::: "memory");
    __syncthreads();

    // compute: warp w -> m rows d = w*16 .. +16, n = 64 j
    float acc[8][4] = {};
    uint32_t a_0 = sbase + (uint32_t)((w * 16 + (lane & 15)) * VG_APAD + (lane >> 4) * 8) * 2;
    uint32_t b_0 = sbase + (uint32_t)(VG_BOFF + (lane & 15) * 72 + (lane >> 4) * 8) * 2;
#pragma unroll 4
    for (int kc = 0; kc < 32; kc++) {   // 32 k16 steps
        uint32_t af[4], bf[4][4];
        ldsm4(af, a_0 + (uint32_t)(kc * 16) * 2);
#pragma unroll
        for (int nt2 = 0; nt2 < 4; nt2++)
            ldsm4t(bf[nt2], b_0 + (uint32_t)(kc * 16 * 72 + nt2 * 16) * 2);
#pragma unroll
        for (int nb = 0; nb < 8; nb++)
            mma16816(acc[nb], af, &bf[nb >> 1][(nb & 1) * 2]);
    }

    // epilogue: C[d][j] -> vf[bh][j][d]
    __half* dst = g_vf + bh * 4096;
    int g = lane >> 2, tig = lane & 3;
    int d0 = w * 16 + g;
#pragma unroll
    for (int nb = 0; nb < 8; nb++) {
        int j0 = nb * 8 + tig * 2;
        float* p = acc[nb];
        dst[j0 * 64 + d0]           = __float2half_rn(p[0]);
        dst[(j0 + 1) * 64 + d0]     = __float2half_rn(p[1]);
        dst[j0 * 64 + d0 + 8]       = __float2half_rn(p[2]);
        dst[(j0 + 1) * 64 + d0 + 8] = __float2half_rn(p[3]);
    }
}

// ---------------- fused channel layernorm (both tensors, one launch) ----------------
__global__ __launch_bounds__(256) void fused_norm_kernel(const float* __restrict__ in0,
                                                         const float* __restrict__ gw0,
                                                         const float* __restrict__ bw0,
                                                         __half* __restrict__ oh0,
                                                         const float* __restrict__ in1,
                                                         const float* __restrict__ gw1,
                                                         const float* __restrict__ bw1,
                                                         __half* __restrict__ oh1) {
    __shared__ float shs[8][32], shq[8][32];
    __shared__ float smean[32], srstd[32];
    int half2nd = blockIdx.x >> 10;
    const float* in = half2nd ? in1 : in0;
    const float* gw = half2nd ? gw1 : gw0;
    const float* bw = half2nd ? bw1 : bw0;
    __half* oh = half2nd ? oh1 : oh0;
    int tid = threadIdx.x;
    int px = tid & 31, cg = tid >> 5;
    int pos = (blockIdx.x & 1023) * 32 + px;
    int b = pos >> 12, sp = pos & 4095;
    size_t base = (size_t)b * DIMC * HW + sp;
    int c0 = cg * 64;
    float v[64];
    float s = 0.f, q = 0.f;
#pragma unroll 8
    for (int c = 0; c < 64; c++) {
        float x = in[base + (size_t)(c0 + c) * HW];
        v[c] = x; s += x; q += x * x;
    }
    shs[cg][px] = s; shq[cg][px] = q;
    __syncthreads();
    if (cg == 0) {
        float ts = 0.f, tq = 0.f;
#pragma unroll
        for (int g = 0; g < 8; g++) { ts += shs[g][px]; tq += shq[g][px]; }
        float mean = ts * (1.0f / 512.0f);
        float var = tq * (1.0f / 512.0f) - mean * mean;
        smean[px] = mean;
        srstd[px] = rsqrtf(var + 1e-5f);
    }
    __syncthreads();
    float m = smean[px], r = srstd[px];
#pragma unroll 8
    for (int c = 0; c < 64; c++) {
        float y = (v[c] - m) * r * gw[c0 + c] + bw[c0 + c];
        oh[base + (size_t)(c0 + c) * HW] = __float2half_rn(y);
    }
}

// ---------------- all weights fp32 -> fp16, one launch ----------------
__global__ __launch_bounds__(256) void wconv_kernel(const float* __restrict__ wq,
                                                    const float* __restrict__ wkv,
                                                    const float* __restrict__ wo) {
    int i4 = (blockIdx.x * 256 + threadIdx.x) * 4;
    const float* src;
    __half* dst;
    int off;
    if (i4 < 262144)       { src = wq;  dst = g_wq;  off = i4; }
    else if (i4 < 786432)  { src = wkv; dst = g_wkv; off = i4 - 262144; }
    else                   { src = wo;  dst = g_wo;  off = i4 - 786432; }
    float4 x = *(const float4*)(src + off);
    *(__half2*)(dst + off)     = __floats2half2_rn(x.x, x.y);
    *(__half2*)(dst + off + 2) = __floats2half2_rn(x.z, x.w);
}

// ---------------- inverse L2 norms for q and k, one launch ----------------
__global__ __launch_bounds__(256) void inv_norm_kernel() {
    int gidx = blockIdx.x * 256 + threadIdx.x;    // 2*GH*HW
    int qk = gidx >> 18;                          // 0: q, 1: k
    int idx = gidx & 262143;
    const __half* t = qk ? g_kk : g_qh;
    size_t base = (size_t)(idx >> 12) * (64 * HW) + (idx & 4095);
    float ss = 0.f;
#pragma unroll 8
    for (int d = 0; d < 64; d++) {
        float x = __half2float(t[base + (size_t)d * HW]);
        ss += x * x;
    }
    float r = 1.0f / fmaxf(sqrtf(ss), 1e-12f);
    if (qk == 0) g_qinv[idx] = r; else g_kinv[idx] = r;
}

// ---------------- merged stats: khw (blocks 0..4095) + qprobe (4096..8191) ----------------
__global__ __launch_bounds__(256) void stats_kernel() {
    __shared__ float pl[4096];
    int tid = threadIdx.x;
    if (blockIdx.x < 4096) {
        int bh = blockIdx.x >> 6, c = blockIdx.x & 63;
        size_t base = ((size_t)bh * 64 + c) * HW;
        const float* ki = g_kinv + bh * HW;
        for (int i = tid; i < 2048; i += 256) {
            __half2 h = *(const __half2*)(g_kk + base + 2 * i);
            float2 kv2 = __half22float2(h);
            float2 ki2 = *(const float2*)(ki + 2 * i);
            pl[2 * i]     = fabsf(kv2.x) * ki2.x;
            pl[2 * i + 1] = fabsf(kv2.y) * ki2.y;
        }
        __syncthreads();
        if (tid < 64) {
            int h = tid;
            float s = 0.f;
#pragma unroll 8
            for (int w = 0; w < 64; w++) s += pl[h * 64 + ((w + h) & 63)];
            g_kh[bh * 4096 + c * 64 + h] = s;
        } else if (tid < 128) {
            int w = tid - 64;
            float s = 0.f;
#pragma unroll 8
            for (int h = 0; h < 64; h++) s += pl[h * 64 + w];
            g_kw[bh * 4096 + c * 64 + w] = s;
        }
    } else {
        int bid = blockIdx.x - 4096;     // bh*64 + c
        int g = bid >> 6;
        const __half2* p2 = (const __half2*)(g_qh + (size_t)bid * HW);
        const float2* iv2 = (const float2*)(g_qinv + (size_t)g * HW);
        float s = 0.f;
        for (int i = tid; i < 2048; i += 256) {
            float2 v = __half22float2(p2[i]);
            float2 iv = iv2[i];
            s += fabsf(v.x) * iv.x + fabsf(v.y) * iv.y;
        }
        pl[tid] = s;
        __syncthreads();
        for (int st = 128; st > 0; st >>= 1) {
            if (tid < st) pl[tid] += pl[tid + st];
            __syncthreads();
        }
        if (tid == 0) g_qprobe[bid] = pl[0];
    }
}

// ---------------- scores + top-8 selection ----------------
__global__ __launch_bounds__(64) void score_topk_kernel() {
    int bh = blockIdx.x;
    int h = threadIdx.x;
    __shared__ float sr[64], sc[64];
    float a = 0.f, bb = 0.f;
    for (int c = 0; c < 64; c++) {
        float qp = g_qprobe[bh * 64 + c];
        a  += qp * g_kh[bh * 4096 + c * 64 + h];
        bb += qp * g_kw[bh * 4096 + c * 64 + h];
    }
    sr[h] = a; sc[h] = bb;
    __syncthreads();
    if (h == 0) {
        for (int i = 0; i < 8; i++) {
            float best = -INFINITY; int bi = 0;
            for (int j = 0; j < 64; j++) if (sr[j] > best) { best = sr[j]; bi = j; }
            g_idxh[bh * 8 + i] = bi;
            sr[bi] = -INFINITY;
        }
    } else if (h == 1) {
        for (int i = 0; i < 8; i++) {
            float best = -INFINITY; int bi = 0;
            for (int j = 0; j < 64; j++) if (sc[j] > best) { best = sc[j]; bi = j; }
            g_idxw[bh * 8 + i] = bi;
            sc[bi] = -INFINITY;
        }
    }
}

// ---------------- gather pruned k -> kT fp16 tile ----------------
__global__ __launch_bounds__(256) void gather_kernel() {
    int idx = blockIdx.x * 256 + threadIdx.x;   // 262144
    int bh = idx >> 12, r = (idx >> 6) & 63, cc = idx & 63;
    int hh = g_idxh[bh * 8 + (cc >> 3)];
    int ww = g_idxw[bh * 8 + (cc & 7)];
    int p = hh * 64 + ww;
    float k = __half2float(g_kk[((size_t)bh * 64 + r) * HW + p]) * g_kinv[bh * HW + p];
    g_kT[idx] = __float2half_rn(k);
}

// ---------------- MMA attention: per (bh, 128-query tile) ----------------
__global__ __launch_bounds__(128) void attn_kernel() {
    __shared__ __half sQ[128 * A_PAD];   // [p][d]; reused for O staging [q][d]
    __shared__ __half sK[64 * A_PAD];    // [d][j]
    __shared__ __half sV[64 * A_PAD];    // [j][d]
    int tid = threadIdx.x, lane = tid & 31, w = tid >> 5;
    int p0 = blockIdx.x * 128, bh = blockIdx.y;
    uint32_t sQa = smem_u32(sQ), sKa = smem_u32(sK), sVa = smem_u32(sV);

    const __half* kt = g_kT + bh * 4096;
    const __half* vf = g_vf + bh * 4096;
#pragma unroll
    for (int i = 0; i < 4; i++) {
        int t = tid + i * 128;
        int r = t >> 3, j = t & 7;
        cp16(sKa + (uint32_t)(r * A_PAD + j * 8) * 2, kt + r * 64 + j * 8);
        cp16(sVa + (uint32_t)(r * A_PAD + j * 8) * 2, vf + r * 64 + j * 8);
    }
    asm volatile("cp.async.commit_group;" ::: "memory");

    // Q: fp16 * qinv -> fp16 smem [p][d]
    const __half* qp = g_qh + (size_t)bh * 64 * HW + p0;
    const float* qi = g_qinv + bh * HW + p0;
#pragma unroll
    for (int i = 0; i < 32; i++) {
        int t = tid + i * 128;
        int d2 = t >> 7, p = t & 127;
        float iv = qi[p];
        __half2 h = __floats2half2_rn(__half2float(qp[(size_t)(2 * d2) * HW + p]) * iv,
                                      __half2float(qp[(size_t)(2 * d2 + 1) * HW + p]) * iv);
        *(__half2*)(sQ + p * A_PAD + 2 * d2) = h;
    }
    asm volatile("cp.async.wait_group 0;" ::: "memory");
    __syncthreads();

    // S = Q*K^T
    float sacc[2][8][4] = {};
#pragma unroll
    for (int kk = 0; kk < 4; kk++) {
        uint32_t a[2][4], bk[4][4];
#pragma unroll
        for (int mb = 0; mb < 2; mb++)
            ldsm4(a[mb], sQa + (uint32_t)((w * 32 + mb * 16 + (lane & 15)) * A_PAD
                                          + kk * 16 + (lane >> 4) * 8) * 2);
#pragma unroll
        for (int nt2 = 0; nt2 < 4; nt2++)
            ldsm4t(bk[nt2], sKa + (uint32_t)((kk * 16 + (lane & 15)) * A_PAD
                                             + nt2 * 16 + (lane >> 4) * 8) * 2);
#pragma unroll
        for (int mb = 0; mb < 2; mb++)
#pragma unroll
            for (int nt = 0; nt < 8; nt++)
                mma16816(sacc[mb][nt], a[mb], &bk[nt >> 1][(nt & 1) * 2]);
    }

    // softmax per row
    float is0[2], is1[2];
#pragma unroll
    for (int mb = 0; mb < 2; mb++) {
        float mx0 = -INFINITY, mx1 = -INFINITY;
#pragma unroll
        for (int nt = 0; nt < 8; nt++) {
            mx0 = fmaxf(mx0, fmaxf(sacc[mb][nt][0], sacc[mb][nt][1]));
            mx1 = fmaxf(mx1, fmaxf(sacc[mb][nt][2], sacc[mb][nt][3]));
        }
        mx0 = fmaxf(mx0, __shfl_xor_sync(0xffffffff, mx0, 1));
        mx0 = fmaxf(mx0, __shfl_xor_sync(0xffffffff, mx0, 2));
        mx1 = fmaxf(mx1, __shfl_xor_sync(0xffffffff, mx1, 1));
        mx1 = fmaxf(mx1, __shfl_xor_sync(0xffffffff, mx1, 2));
        float s0 = 0.f, s1 = 0.f;
#pragma unroll
        for (int nt = 0; nt < 8; nt++) {
            sacc[mb][nt][0] = expf(sacc[mb][nt][0] - mx0);
            sacc[mb][nt][1] = expf(sacc[mb][nt][1] - mx0);
            sacc[mb][nt][2] = expf(sacc[mb][nt][2] - mx1);
            sacc[mb][nt][3] = expf(sacc[mb][nt][3] - mx1);
            s0 += sacc[mb][nt][0] + sacc[mb][nt][1];
            s1 += sacc[mb][nt][2] + sacc[mb][nt][3];
        }
        s0 += __shfl_xor_sync(0xffffffff, s0, 1);
        s0 += __shfl_xor_sync(0xffffffff, s0, 2);
        s1 += __shfl_xor_sync(0xffffffff, s1, 1);
        s1 += __shfl_xor_sync(0xffffffff, s1, 2);
        is0[mb] = 1.0f / s0;
        is1[mb] = 1.0f / s1;
    }

    // P a-frags from acc frags
    uint32_t pa[2][4][4];
#pragma unroll
    for (int mb = 0; mb < 2; mb++)
#pragma unroll
        for (int u = 0; u < 4; u++) {
            __half2 h0 = __floats2half2_rn(sacc[mb][2*u][0],   sacc[mb][2*u][1]);
            __half2 h1 = __floats2half2_rn(sacc[mb][2*u][2],   sacc[mb][2*u][3]);
            __half2 h2 = __floats2half2_rn(sacc[mb][2*u+1][0], sacc[mb][2*u+1][1]);
            __half2 h3 = __floats2half2_rn(sacc[mb][2*u+1][2], sacc[mb][2*u+1][3]);
            pa[mb][u][0] = *(uint32_t*)&h0;
            pa[mb][u][1] = *(uint32_t*)&h1;
            pa[mb][u][2] = *(uint32_t*)&h2;
            pa[mb][u][3] = *(uint32_t*)&h3;
        }

    // O = P*V
    float oacc[2][8][4] = {};
#pragma unroll
    for (int u = 0; u < 4; u++) {
        uint32_t bv[4][4];
#pragma unroll
        for (int nt2 = 0; nt2 < 4; nt2++)
            ldsm4t(bv[nt2], sVa + (uint32_t)((u * 16 + (lane & 15)) * A_PAD
                                             + nt2 * 16 + (lane >> 4) * 8) * 2);
#pragma unroll
        for (int mb = 0; mb < 2; mb++)
#pragma unroll
            for (int nt = 0; nt < 8; nt++)
                mma16816(oacc[mb][nt], pa[mb][u], &bv[nt >> 1][(nt & 1) * 2]);
    }

    __syncthreads();
#pragma unroll
    for (int mb = 0; mb < 2; mb++) {
        int q = w * 32 + mb * 16 + (lane >> 2);
#pragma unroll
        for (int nt = 0; nt < 8; nt++) {
            int d = nt * 8 + (lane & 3) * 2;
            __half2 h0 = __floats2half2_rn(oacc[mb][nt][0] * is0[mb],
                                           oacc[mb][nt][1] * is0[mb]);
            __half2 h1 = __floats2half2_rn(oacc[mb][nt][2] * is1[mb],
                                           oacc[mb][nt][3] * is1[mb]);
            *(__half2*)(sQ + q * A_PAD + d) = h0;
            *(__half2*)(sQ + (q + 8) * A_PAD + d) = h1;
        }
    }
    __syncthreads();

    size_t ob = ((size_t)(bh >> 3) * 512 + (size_t)(bh & 7) * 64) * HW + p0;
    for (int i = tid; i < 4096; i += 128) {
        int d = i >> 6, jj = i & 63;
        __half2 h = __halves2half2(sQ[(jj * 2) * A_PAD + d],
                                   sQ[(jj * 2 + 1) * A_PAD + d]);
        *(__half2*)(g_aoh + ob + (size_t)d * HW + jj * 2) = h;
    }
}

// ---------------- launch ----------------
extern "C" void kernel_launch(void* const* d_in, const int* in_sizes, int n_in,
                              void* d_out, int out_size) {
    (void)in_sizes; (void)n_in; (void)out_size;
    const float* context      = (const float*)d_in[0];
    const float* query_source = (const float*)d_in[1];
    const float* ctx_g = (const float*)d_in[2];
    const float* ctx_b = (const float*)d_in[3];
    const float* qs_g  = (const float*)d_in[4];
    const float* qs_b  = (const float*)d_in[5];
    const float* w_q   = (const float*)d_in[6];
    const float* w_kv  = (const float*)d_in[7];
    const float* w_out = (const float*)d_in[8];
    const float* gamma = (const float*)d_in[9];
    float* out = (float*)d_out;

    static bool inited = false;
    static __half *p_qh, *p_kk, *p_ctxh, *p_qsh, *p_aoh, *p_wq, *p_wkv, *p_wo;
    if (!inited) {
        cudaGetSymbolAddress((void**)&p_qh,   g_qh);
        cudaGetSymbolAddress((void**)&p_kk,   g_kk);
        cudaGetSymbolAddress((void**)&p_ctxh, g_ctxh);
        cudaGetSymbolAddress((void**)&p_qsh,  g_qsh);
        cudaGetSymbolAddress((void**)&p_aoh,  g_aoh);
        cudaGetSymbolAddress((void**)&p_wq,   g_wq);
        cudaGetSymbolAddress((void**)&p_wkv,  g_wkv);
        cudaGetSymbolAddress((void**)&p_wo,   g_wo);
        cudaFuncSetAttribute(proj_gemm_kernel,
                             cudaFuncAttributeMaxDynamicSharedMemorySize, GEMM_SMEM);
        cudaFuncSetAttribute(out_gemm_kernel,
                             cudaFuncAttributeMaxDynamicSharedMemorySize, GEMM_SMEM);
        cudaFuncSetAttribute(vgather_kernel,
                             cudaFuncAttributeMaxDynamicSharedMemorySize, VG_SMEM);
        inited = true;
    }

    // 1) fused channel layernorms + weight conversion
    fused_norm_kernel<<<2048, 256>>>(context, ctx_g, ctx_b, p_ctxh,
                                     query_source, qs_g, qs_b, p_qsh);
    wconv_kernel<<<1024, 256>>>(w_q, w_kv, w_out);

    // 2) merged k + q projections (k uses w_kv rows 0..511)
    proj_gemm_kernel<<<dim3(32, 4, 16), 256, GEMM_SMEM>>>(p_wkv, p_ctxh, p_kk,
                                                          p_wq, p_qsh, p_qh);

    // 3) inverse L2 norms
    inv_norm_kernel<<<2048, 256>>>();

    // 4) pruning statistics + selection
    stats_kernel<<<8192, 256>>>();
    score_topk_kernel<<<64, 64>>>();

    // 5) gather k^T; compute V only at gathered positions
    gather_kernel<<<1024, 256>>>();
    vgather_kernel<<<64, 128, VG_SMEM>>>();

    // 6) MMA attention (emits fp16 [d][p])
    attn_kernel<<<dim3(32, 64), 128>>>();

    // 7) out projection + fp16 residual: out = gamma*W_out@ao + qs_norm
    out_gemm_kernel<<<dim3(32, 4, 8), 256, GEMM_SMEM>>>(p_wo, p_aoh, out, gamma, p_qsh);
}